// round 1
// baseline (speedup 1.0000x reference)
#include <cuda_runtime.h>
#include <math.h>

// ---------------- problem constants ----------------
#define HW   64
#define NF   64
#define BB   32
#define TT   12
#define GATES 256           // 4*NF
#define STATE_ELEMS (BB*NF*HW*HW)   // 8,388,608 floats
#define Y_ELEMS (BB*TT*HW*HW)       // 1,572,864 floats

// ---------------- static device scratch (no allocs allowed) ----------------
__device__ float g_hA[STATE_ELEMS];
__device__ float g_hB[STATE_ELEMS];
__device__ float g_c [STATE_ELEMS];
__device__ float g_ev[STATE_ELEMS];
__device__ float g_Wenc_t[65  * GATES * 9];
__device__ float g_Wdec_t[128 * GATES * 9];

// ---------------- small helpers ----------------
__global__ void zero_buf(float* __restrict__ p, int n) {
    for (int i = blockIdx.x * blockDim.x + threadIdx.x; i < n;
         i += gridDim.x * blockDim.x)
        p[i] = 0.f;
}

// copy src -> d1 and d2 (encoder vector kept for decoder input AND written to output)
__global__ void copy2(const float* __restrict__ src, float* __restrict__ d1,
                      float* __restrict__ d2, int n) {
    for (int i = blockIdx.x * blockDim.x + threadIdx.x; i < n;
         i += gridDim.x * blockDim.x) {
        float v = src[i];
        d1[i] = v;
        d2[i] = v;
    }
}

// W[oc][cin][9] -> Wt[cin][oc][9]
__global__ void transpose_w(const float* __restrict__ W, float* __restrict__ Wt,
                            int CIN) {
    int total = GATES * CIN * 9;
    for (int i = blockIdx.x * blockDim.x + threadIdx.x; i < total;
         i += gridDim.x * blockDim.x) {
        int k    = i % 9;
        int rest = i / 9;
        int cin  = rest % CIN;
        int oc   = rest / CIN;
        Wt[((size_t)cin * GATES + oc) * 9 + k] = W[i];
    }
}

__device__ __forceinline__ float sigmoidf_(float x) {
    return 1.f / (1.f + __expf(-x));
}

// ---------------- fused ConvLSTM step ----------------
// Input = concat(xin [CA ch], h_in [NF ch]); weights pre-transposed [CA+NF][256][9].
// Block: 256 threads, 8x8 pixel tile, all 256 gate-channels.
// Thread owns 2 nf-channels x 4 gates x 8 pixels (one tile row) = 64 accumulators.
template <int CA>
__global__ __launch_bounds__(256, 2)
void convlstm_step(const float* __restrict__ xin, int xin_bstride,
                   const float* __restrict__ h_in,
                   float* __restrict__ h_out,
                   float* __restrict__ c,
                   const float* __restrict__ Wt,      // [(CA+NF)*256*9]
                   const float* __restrict__ bias) {  // [256]
    __shared__ float s_in[10][12];          // 8x8 tile + halo, padded
    __shared__ float s_w[GATES * 9];        // weights for current input channel

    const int tid = threadIdx.x;
    const int bx  = blockIdx.x & 7;
    const int by  = (blockIdx.x >> 3) & 7;
    const int b   = blockIdx.x >> 6;
    const int g   = tid >> 3;               // 0..31  -> nf-channel pair
    const int p   = tid & 7;                // row within tile
    const int n0  = g * 2;

    // acc[l][j], l = n*4 + gate  (n in 0..1, gate: 0=i,1=f,2=o,3=g)
    float acc[8][8];
#pragma unroll
    for (int l = 0; l < 8; l++) {
        int ch   = ((l & 3) << 6) + n0 + (l >> 2);
        float bv = bias[ch];
#pragma unroll
        for (int j = 0; j < 8; j++) acc[l][j] = bv;
    }

    const int y0 = by * 8, x0 = bx * 8;

    for (int cin = 0; cin < CA + NF; ++cin) {
        const float* src;
        if (cin < CA)
            src = xin + (size_t)b * xin_bstride + (size_t)cin * (HW * HW);
        else
            src = h_in + ((size_t)b * NF + (cin - CA)) * (HW * HW);

        __syncthreads();
        // stage weights for this input channel: 2304 floats, coalesced
#pragma unroll
        for (int i = 0; i < 9; i++)
            s_w[tid + i * 256] = Wt[(size_t)cin * (GATES * 9) + tid + i * 256];
        // stage input halo tile 10x10
        if (tid < 100) {
            int r  = tid / 10, cc = tid % 10;
            int gy = y0 - 1 + r, gx = x0 - 1 + cc;
            float v = 0.f;
            if ((unsigned)gy < HW && (unsigned)gx < HW) v = src[gy * HW + gx];
            s_in[r][cc] = v;
        }
        __syncthreads();

#pragma unroll
        for (int dy = 0; dy < 3; ++dy) {
            float row[10];
#pragma unroll
            for (int jj = 0; jj < 10; jj++) row[jj] = s_in[p + dy][jj];
#pragma unroll
            for (int l = 0; l < 8; l++) {
                int ch = ((l & 3) << 6) + n0 + (l >> 2);
                const float* wp = &s_w[ch * 9 + dy * 3];
                float w0 = wp[0], w1 = wp[1], w2 = wp[2];
#pragma unroll
                for (int j = 0; j < 8; j++)
                    acc[l][j] += w0 * row[j] + w1 * row[j + 1] + w2 * row[j + 2];
            }
        }
    }

    // ---- LSTM pointwise epilogue ----
#pragma unroll
    for (int n = 0; n < 2; n++) {
        int chn = n0 + n;
        size_t base = (((size_t)b * NF + chn) * HW + (y0 + p)) * HW + x0;
#pragma unroll
        for (int j = 0; j < 8; j++) {
            float iv = sigmoidf_(acc[n * 4 + 0][j]);
            float fv = sigmoidf_(acc[n * 4 + 1][j]);
            float ov = sigmoidf_(acc[n * 4 + 2][j]);
            float gv = tanhf(acc[n * 4 + 3][j]);
            float cold = c[base + j];
            float cn   = fv * cold + iv * gv;
            c[base + j]     = cn;
            h_out[base + j] = ov * tanhf(cn);
        }
    }
}

// ---------------- fused 3D-CNN head (kernel (1,3,3)) per decoder step ----------------
// y[b][t][y][x] = b_cnn + sum_n sum_{ky,kx} Wc[n][ky][kx] * h[b][n][y+ky-1][x+kx-1]
__global__ __launch_bounds__(256)
void cnn_head(const float* __restrict__ h, const float* __restrict__ Wc,
              const float* __restrict__ bc, float* __restrict__ out, int t) {
    __shared__ float s_w[NF * 9];
    __shared__ float s_t[18][20];

    const int tid = threadIdx.x;
    const int tx  = blockIdx.x & 3;
    const int ty  = (blockIdx.x >> 2) & 3;
    const int b   = blockIdx.x >> 4;
    const int px  = tid & 15;
    const int py  = tid >> 4;

    for (int i = tid; i < NF * 9; i += 256) s_w[i] = Wc[i];

    float acc = 0.f;
    const int gy0 = ty * 16 - 1, gx0 = tx * 16 - 1;
    for (int n = 0; n < NF; n++) {
        __syncthreads();
        const float* src = h + ((size_t)b * NF + n) * (HW * HW);
        for (int i = tid; i < 18 * 18; i += 256) {
            int r = i / 18, cc = i % 18;
            int gy = gy0 + r, gx = gx0 + cc;
            float v = 0.f;
            if ((unsigned)gy < HW && (unsigned)gx < HW) v = src[gy * HW + gx];
            s_t[r][cc] = v;
        }
        __syncthreads();
#pragma unroll
        for (int ky = 0; ky < 3; ky++)
#pragma unroll
            for (int kx = 0; kx < 3; kx++)
                acc += s_w[n * 9 + ky * 3 + kx] * s_t[py + ky][px + kx];
    }
    int yy = ty * 16 + py, xx = tx * 16 + px;
    out[((size_t)b * TT + t) * (HW * HW) + yy * HW + xx] = acc + bc[0];
}

// ---------------- launch ----------------
extern "C" void kernel_launch(void* const* d_in, const int* in_sizes, int n_in,
                              void* d_out, int out_size) {
    const float* x     = (const float*)d_in[0];
    // d_in[1] = future_step (always 12)
    const float* W_enc = (const float*)d_in[2];
    const float* b_enc = (const float*)d_in[3];
    const float* W_dec = (const float*)d_in[4];
    const float* b_dec = (const float*)d_in[5];
    const float* W_cnn = (const float*)d_in[6];
    const float* b_cnn = (const float*)d_in[7];
    float* out = (float*)d_out;

    float *hA, *hB, *c, *ev, *wet, *wdt;
    cudaGetSymbolAddress((void**)&hA,  g_hA);
    cudaGetSymbolAddress((void**)&hB,  g_hB);
    cudaGetSymbolAddress((void**)&c,   g_c);
    cudaGetSymbolAddress((void**)&ev,  g_ev);
    cudaGetSymbolAddress((void**)&wet, g_Wenc_t);
    cudaGetSymbolAddress((void**)&wdt, g_Wdec_t);

    zero_buf<<<2048, 256>>>(hA, STATE_ELEMS);
    zero_buf<<<2048, 256>>>(c,  STATE_ELEMS);
    transpose_w<<<256, 256>>>(W_enc, wet, 65);
    transpose_w<<<256, 256>>>(W_dec, wdt, 128);

    // ---- encoder: 12 steps, x_t has 1 channel ----
    float* cur = hA;
    float* oth = hB;
    for (int t = 0; t < TT; t++) {
        convlstm_step<1><<<2048, 256>>>(x + (size_t)t * HW * HW, TT * HW * HW,
                                        cur, oth, c, wet, b_enc);
        float* tmp = cur; cur = oth; oth = tmp;
    }

    // encoder vector -> keep for decoder input, and write to output tail
    copy2<<<2048, 256>>>(cur, ev, out + Y_ELEMS, STATE_ELEMS);

    // decoder state restarts at zero
    zero_buf<<<2048, 256>>>(cur, STATE_ELEMS);
    zero_buf<<<2048, 256>>>(c,   STATE_ELEMS);

    // ---- decoder: 12 steps; input is ev then previous h ----
    for (int t = 0; t < TT; t++) {
        const float* xin = (t == 0) ? ev : cur;
        convlstm_step<64><<<2048, 256>>>(xin, NF * HW * HW, cur, oth, c, wdt,
                                         b_dec);
        cnn_head<<<512, 256>>>(oth, W_cnn, b_cnn, out, t);
        float* tmp = cur; cur = oth; oth = tmp;
    }
}

// round 2
// speedup vs baseline: 1.6388x; 1.6388x over previous
#include <cuda_runtime.h>
#include <math.h>

// ---------------- problem constants ----------------
#define HW   64
#define NF   64
#define BB   32
#define TT   12
#define GATES 256           // 4*NF
#define STATE_ELEMS (BB*NF*HW*HW)   // 8,388,608 floats
#define Y_ELEMS (BB*TT*HW*HW)       // 1,572,864 floats

typedef unsigned long long u64;

// ---------------- static device scratch (no allocs allowed) ----------------
__device__ float g_hA[STATE_ELEMS];
__device__ float g_hB[STATE_ELEMS];
__device__ float g_c [STATE_ELEMS];
__device__ float g_ev[STATE_ELEMS];
__device__ float g_Wenc_t[65  * GATES * 9];
__device__ float g_Wdec_t[128 * GATES * 9];

// ---------------- packed f32x2 helpers ----------------
__device__ __forceinline__ u64 pk(float lo, float hi) {
    u64 r; asm("mov.b64 %0, {%1, %2};" : "=l"(r) : "f"(lo), "f"(hi)); return r;
}
__device__ __forceinline__ void unpk(float& lo, float& hi, u64 v) {
    asm("mov.b64 {%0, %1}, %2;" : "=f"(lo), "=f"(hi) : "l"(v));
}
__device__ __forceinline__ void ffma2(u64& d, u64 a, u64 b) {
    asm("fma.rn.f32x2 %0, %1, %2, %0;" : "+l"(d) : "l"(a), "l"(b));
}

// ---------------- small helpers ----------------
__global__ void zero_buf(float* __restrict__ p, int n) {
    for (int i = blockIdx.x * blockDim.x + threadIdx.x; i < n;
         i += gridDim.x * blockDim.x)
        p[i] = 0.f;
}

__global__ void copy2(const float* __restrict__ src, float* __restrict__ d1,
                      float* __restrict__ d2, int n) {
    for (int i = blockIdx.x * blockDim.x + threadIdx.x; i < n;
         i += gridDim.x * blockDim.x) {
        float v = src[i];
        d1[i] = v;
        d2[i] = v;
    }
}

// W[oc][cin][9] -> Wt[cin][oc][9]
__global__ void transpose_w(const float* __restrict__ W, float* __restrict__ Wt,
                            int CIN) {
    int total = GATES * CIN * 9;
    for (int i = blockIdx.x * blockDim.x + threadIdx.x; i < total;
         i += gridDim.x * blockDim.x) {
        int k    = i % 9;
        int rest = i / 9;
        int cin  = rest % CIN;
        int oc   = rest / CIN;
        Wt[((size_t)cin * GATES + oc) * 9 + k] = W[i];
    }
}

__device__ __forceinline__ float sigmoidf_(float x) {
    return 1.f / (1.f + __expf(-x));
}
__device__ __forceinline__ float tanhf_(float x) {
    float e = __expf(2.f * x);
    return (e - 1.f) * __frcp_rn(e + 1.f);
}

// ---------------- fused ConvLSTM step (packed f32x2) ----------------
// Input = concat(xin [CA ch], h_in [NF ch]); weights pre-transposed [CA+NF][256][9].
// Runtime ncin bounds the channel loop (skip all-zero h at t=0).
// Block: 256 threads, 8x8 pixel tile, all 256 gate-channels.
// Thread owns 2 nf-channels x 4 gates x 4 pixel-pairs = 32 packed accumulators.
template <int CA>
__global__ __launch_bounds__(256, 2)
void convlstm_step(const float* __restrict__ xin, int xin_bstride,
                   const float* __restrict__ h_in,
                   float* __restrict__ h_out,
                   float* __restrict__ c,
                   const float* __restrict__ Wt,      // [(CA+NF)*256*9]
                   const float* __restrict__ bias,    // [256]
                   int ncin) {
    __shared__ __align__(16) float  s_in[10][12];     // 8x8 tile + halo, padded
    __shared__ __align__(16) float2 s_w2[GATES * 9];  // (w,w) duplicated pairs

    const int tid = threadIdx.x;
    const int bx  = blockIdx.x & 7;
    const int by  = (blockIdx.x >> 3) & 7;
    const int b   = blockIdx.x >> 6;
    const int g   = tid >> 3;               // 0..31  -> nf-channel pair
    const int p   = tid & 7;                // row within tile
    const int n0  = g * 2;

    // acc2[l][m]: l = n*4 + gate (n 0..1, gate i/f/o/g), m = pixel pair 0..3
    u64 acc2[8][4];
#pragma unroll
    for (int l = 0; l < 8; l++) {
        int ch   = ((l & 3) << 6) + n0 + (l >> 2);
        float bv = bias[ch];
        u64 bp = pk(bv, bv);
#pragma unroll
        for (int m = 0; m < 4; m++) acc2[l][m] = bp;
    }

    const int y0 = by * 8, x0 = bx * 8;

    for (int cin = 0; cin < ncin; ++cin) {
        const float* src;
        if (cin < CA)
            src = xin + (size_t)b * xin_bstride + (size_t)cin * (HW * HW);
        else
            src = h_in + ((size_t)b * NF + (cin - CA)) * (HW * HW);

        __syncthreads();
        // stage weights duplicated: 2304 float2, coalesced
#pragma unroll
        for (int i = 0; i < 9; i++) {
            float w = Wt[(size_t)cin * (GATES * 9) + tid + i * 256];
            s_w2[tid + i * 256] = make_float2(w, w);
        }
        // stage input halo tile 10x10
        if (tid < 100) {
            int r  = tid / 10, cc = tid % 10;
            int gy = y0 - 1 + r, gx = x0 - 1 + cc;
            float v = 0.f;
            if ((unsigned)gy < HW && (unsigned)gx < HW) v = src[gy * HW + gx];
            s_in[r][cc] = v;
        }
        __syncthreads();

#pragma unroll
        for (int dy = 0; dy < 3; ++dy) {
            float row[10];
#pragma unroll
            for (int jj = 0; jj < 10; jj++) row[jj] = s_in[p + dy][jj];
            // shifted packed views of the row
            u64 A[5], Bv[4];
#pragma unroll
            for (int m = 0; m < 5; m++) A[m]  = pk(row[2 * m], row[2 * m + 1]);
#pragma unroll
            for (int m = 0; m < 4; m++) Bv[m] = pk(row[2 * m + 1], row[2 * m + 2]);

#pragma unroll
            for (int l = 0; l < 8; l++) {
                int ch = ((l & 3) << 6) + n0 + (l >> 2);
                const u64* wp = reinterpret_cast<const u64*>(&s_w2[ch * 9 + dy * 3]);
                u64 w0 = wp[0], w1 = wp[1], w2 = wp[2];
#pragma unroll
                for (int m = 0; m < 4; m++) {
                    ffma2(acc2[l][m], A[m],     w0);
                    ffma2(acc2[l][m], Bv[m],    w1);
                    ffma2(acc2[l][m], A[m + 1], w2);
                }
            }
        }
    }

    // ---- LSTM pointwise epilogue ----
#pragma unroll
    for (int n = 0; n < 2; n++) {
        int chn = n0 + n;
        size_t base = (((size_t)b * NF + chn) * HW + (y0 + p)) * HW + x0;
        float2* cp = reinterpret_cast<float2*>(&c[base]);
        float2* hp = reinterpret_cast<float2*>(&h_out[base]);
#pragma unroll
        for (int m = 0; m < 4; m++) {
            float i0, i1, f0, f1, o0, o1, g0, g1;
            unpk(i0, i1, acc2[n * 4 + 0][m]);
            unpk(f0, f1, acc2[n * 4 + 1][m]);
            unpk(o0, o1, acc2[n * 4 + 2][m]);
            unpk(g0, g1, acc2[n * 4 + 3][m]);
            float2 cold = cp[m];
            float cn0 = sigmoidf_(f0) * cold.x + sigmoidf_(i0) * tanhf_(g0);
            float cn1 = sigmoidf_(f1) * cold.y + sigmoidf_(i1) * tanhf_(g1);
            cp[m] = make_float2(cn0, cn1);
            hp[m] = make_float2(sigmoidf_(o0) * tanhf_(cn0),
                                sigmoidf_(o1) * tanhf_(cn1));
        }
    }
}

// ---------------- fused 3D-CNN head (kernel (1,3,3)) per decoder step ----------------
__global__ __launch_bounds__(256)
void cnn_head(const float* __restrict__ h, const float* __restrict__ Wc,
              const float* __restrict__ bc, float* __restrict__ out, int t) {
    __shared__ float s_w[NF * 9];
    __shared__ float s_t[18][20];

    const int tid = threadIdx.x;
    const int tx  = blockIdx.x & 3;
    const int ty  = (blockIdx.x >> 2) & 3;
    const int b   = blockIdx.x >> 4;
    const int px  = tid & 15;
    const int py  = tid >> 4;

    for (int i = tid; i < NF * 9; i += 256) s_w[i] = Wc[i];

    float acc = 0.f;
    const int gy0 = ty * 16 - 1, gx0 = tx * 16 - 1;
    for (int n = 0; n < NF; n++) {
        __syncthreads();
        const float* src = h + ((size_t)b * NF + n) * (HW * HW);
        for (int i = tid; i < 18 * 18; i += 256) {
            int r = i / 18, cc = i % 18;
            int gy = gy0 + r, gx = gx0 + cc;
            float v = 0.f;
            if ((unsigned)gy < HW && (unsigned)gx < HW) v = src[gy * HW + gx];
            s_t[r][cc] = v;
        }
        __syncthreads();
#pragma unroll
        for (int ky = 0; ky < 3; ky++)
#pragma unroll
            for (int kx = 0; kx < 3; kx++)
                acc += s_w[n * 9 + ky * 3 + kx] * s_t[py + ky][px + kx];
    }
    int yy = ty * 16 + py, xx = tx * 16 + px;
    out[((size_t)b * TT + t) * (HW * HW) + yy * HW + xx] = acc + bc[0];
}

// ---------------- launch ----------------
extern "C" void kernel_launch(void* const* d_in, const int* in_sizes, int n_in,
                              void* d_out, int out_size) {
    const float* x     = (const float*)d_in[0];
    // d_in[1] = future_step (always 12)
    const float* W_enc = (const float*)d_in[2];
    const float* b_enc = (const float*)d_in[3];
    const float* W_dec = (const float*)d_in[4];
    const float* b_dec = (const float*)d_in[5];
    const float* W_cnn = (const float*)d_in[6];
    const float* b_cnn = (const float*)d_in[7];
    float* out = (float*)d_out;

    float *hA, *hB, *c, *ev, *wet, *wdt;
    cudaGetSymbolAddress((void**)&hA,  g_hA);
    cudaGetSymbolAddress((void**)&hB,  g_hB);
    cudaGetSymbolAddress((void**)&c,   g_c);
    cudaGetSymbolAddress((void**)&ev,  g_ev);
    cudaGetSymbolAddress((void**)&wet, g_Wenc_t);
    cudaGetSymbolAddress((void**)&wdt, g_Wdec_t);

    zero_buf<<<2048, 256>>>(c, STATE_ELEMS);
    transpose_w<<<256, 256>>>(W_enc, wet, 65);
    transpose_w<<<256, 256>>>(W_dec, wdt, 128);

    // ---- encoder: 12 steps, x_t has 1 channel; t=0 skips zero h ----
    float* cur = hA;
    float* oth = hB;
    for (int t = 0; t < TT; t++) {
        int ncin = (t == 0) ? 1 : 65;
        convlstm_step<1><<<2048, 256>>>(x + (size_t)t * HW * HW, TT * HW * HW,
                                        cur, oth, c, wet, b_enc, ncin);
        float* tmp = cur; cur = oth; oth = tmp;
    }

    // encoder vector -> keep for decoder input, and write to output tail
    copy2<<<2048, 256>>>(cur, ev, out + Y_ELEMS, STATE_ELEMS);

    // decoder state restarts at zero (c only; t=0 never reads h_in)
    zero_buf<<<2048, 256>>>(c, STATE_ELEMS);

    // ---- decoder: 12 steps; input is ev then previous h; t=0 skips zero h ----
    for (int t = 0; t < TT; t++) {
        const float* xin = (t == 0) ? ev : cur;
        int ncin = (t == 0) ? 64 : 128;
        convlstm_step<64><<<2048, 256>>>(xin, NF * HW * HW, cur, oth, c, wdt,
                                         b_dec, ncin);
        cnn_head<<<512, 256>>>(oth, W_cnn, b_cnn, out, t);
        float* tmp = cur; cur = oth; oth = tmp;
    }
}

// round 4
// speedup vs baseline: 2.2046x; 1.3452x over previous
#include <cuda_runtime.h>
#include <math.h>

// ---------------- problem constants ----------------
#define HW   64
#define NF   64
#define BB   32
#define TT   12
#define GATES 256           // 4*NF
#define STATE_ELEMS (BB*NF*HW*HW)   // 8,388,608 floats
#define Y_ELEMS (BB*TT*HW*HW)       // 1,572,864 floats

typedef unsigned long long u64;

// ---------------- static device scratch (no allocs allowed) ----------------
__device__ float g_hA[STATE_ELEMS];
__device__ float g_hB[STATE_ELEMS];
__device__ float g_c [STATE_ELEMS];
__device__ float g_ev[STATE_ELEMS];
__device__ __align__(16) float g_Wenc_t[65  * GATES * 9];
__device__ __align__(16) float g_Wdec_t[128 * GATES * 9];

// ---------------- packed f32x2 helpers ----------------
__device__ __forceinline__ u64 pk(float lo, float hi) {
    u64 r; asm("mov.b64 %0, {%1, %2};" : "=l"(r) : "f"(lo), "f"(hi)); return r;
}
__device__ __forceinline__ void unpk(float& lo, float& hi, u64 v) {
    asm("mov.b64 {%0, %1}, %2;" : "=f"(lo), "=f"(hi) : "l"(v));
}
__device__ __forceinline__ void ffma2(u64& d, u64 a, u64 b) {
    asm("fma.rn.f32x2 %0, %1, %2, %0;" : "+l"(d) : "l"(a), "l"(b));
}

// ---------------- cp.async helpers ----------------
__device__ __forceinline__ void cp16(void* sdst, const void* gsrc) {
    unsigned s = (unsigned)__cvta_generic_to_shared(sdst);
    asm volatile("cp.async.cg.shared.global [%0], [%1], 16;" :: "r"(s), "l"(gsrc));
}
__device__ __forceinline__ void cp_commit() {
    asm volatile("cp.async.commit_group;");
}

// ---------------- small helpers ----------------
__global__ void zero_buf(float* __restrict__ p, int n) {
    for (int i = blockIdx.x * blockDim.x + threadIdx.x; i < n;
         i += gridDim.x * blockDim.x)
        p[i] = 0.f;
}

__global__ void copy2(const float* __restrict__ src, float* __restrict__ d1,
                      float* __restrict__ d2, int n) {
    for (int i = blockIdx.x * blockDim.x + threadIdx.x; i < n;
         i += gridDim.x * blockDim.x) {
        float v = src[i];
        d1[i] = v;
        d2[i] = v;
    }
}

// W[oc][cin][9] -> Wt[cin][tap][oc]   (oc fastest, so och pairs are adjacent)
__global__ void transpose_w(const float* __restrict__ W, float* __restrict__ Wt,
                            int CIN) {
    int total = CIN * 9 * GATES;
    for (int i = blockIdx.x * blockDim.x + threadIdx.x; i < total;
         i += gridDim.x * blockDim.x) {
        int oc   = i % GATES;
        int rest = i / GATES;
        int k    = rest % 9;
        int cin  = rest / 9;
        Wt[i] = W[((size_t)oc * CIN + cin) * 9 + k];
    }
}

__device__ __forceinline__ float sigmoidf_(float x) {
    return 1.f / (1.f + __expf(-x));
}
__device__ __forceinline__ float tanhf_(float x) {
    float e = __expf(2.f * x);
    return (e - 1.f) * __frcp_rn(e + 1.f);
}

// ---------------- fused ConvLSTM step (channel-packed f32x2, cp.async pipelined) ----
// Input = concat(xin [CA ch], h_in [NF ch]); weights pre-transposed [cin][9][256].
// Block: 256 threads, 8x8 pixel tile. Thread (g = tid>>3, p = tid&7) owns
// output-channel pair (2g, 2g+1) for all 4 gates at pixels (y0+py, x0+p), py=0..7.
// acc[gate][py] : packed (ch 2g, ch 2g+1).
template <int CA>
__global__ __launch_bounds__(256, 2)
void convlstm_step(const float* __restrict__ xin, int xin_bstride,
                   const float* __restrict__ h_in,
                   float* __restrict__ h_out,
                   float* __restrict__ c,
                   const float* __restrict__ Wt,      // [(CA+NF)*9*256]
                   const float* __restrict__ bias,    // [256]
                   int ncin) {
    __shared__ __align__(16) float  s_w[2][9 * GATES];      // 18.4 KB
    __shared__ __align__(16) float2 s_it[2][10][11];        // transposed dup halo [x][y]

    const int tid = threadIdx.x;
    const int bx  = blockIdx.x & 7;
    const int by  = (blockIdx.x >> 3) & 7;
    const int b   = blockIdx.x >> 6;
    const int g   = tid >> 3;               // 0..31 -> output-channel pair
    const int p   = tid & 7;                // x within tile
    const int n0  = g * 2;

    const int y0 = by * 8, x0 = bx * 8;

    // accumulators: 4 gates x 8 rows, each packed over channel pair
    u64 acc[4][8];
#pragma unroll
    for (int gi = 0; gi < 4; gi++) {
        float2 bv = *reinterpret_cast<const float2*>(&bias[gi * 64 + n0]);
        u64 bp = pk(bv.x, bv.y);
#pragma unroll
        for (int py = 0; py < 8; py++) acc[gi][py] = bp;
    }

    // ---- loader-thread setup (100 threads stage the 10x10 halo) ----
    const bool is_loader = tid < 100;
    const int lr = tid / 10, lc = tid % 10;          // halo row/col
    const int gy = y0 - 1 + lr, gx = x0 - 1 + lc;
    const bool inb = ((unsigned)gy < HW) & ((unsigned)gx < HW);
    const int goff = gy * HW + gx;

    // ---- prologue: stage cin=0, prefetch input for cin=1 ----
    float vnext = 0.f;
    {
        float v0 = 0.f;
        if (is_loader && inb) {
            const float* s0 = (0 < CA)
                ? xin + (size_t)b * xin_bstride
                : h_in + ((size_t)b * NF + (0 - CA)) * (HW * HW);
            v0 = s0[goff];
        }
        if (is_loader) s_it[0][lc][lr] = make_float2(v0, v0);
        const float* wsrc = Wt;
        float* wdst = s_w[0];
        for (int i = tid; i < 576; i += 256)
            cp16(wdst + i * 4, wsrc + i * 4);
        cp_commit();
        if (1 < ncin && is_loader && inb) {
            const float* s1 = (1 < CA)
                ? xin + (size_t)b * xin_bstride + (size_t)1 * (HW * HW)
                : h_in + ((size_t)b * NF + (1 - CA)) * (HW * HW);
            vnext = s1[goff];
        }
    }

    // ---- main channel loop, 2-stage pipeline ----
    for (int cin = 0; cin < ncin; ++cin) {
        const int buf = cin & 1, nb = buf ^ 1;

        if (cin + 1 < ncin) {
            const float* wsrc = Wt + (size_t)(cin + 1) * (9 * GATES);
            float* wdst = s_w[nb];
            for (int i = tid; i < 576; i += 256)
                cp16(wdst + i * 4, wsrc + i * 4);
            cp_commit();
            if (is_loader) s_it[nb][lc][lr] = make_float2(vnext, vnext);
        }
        if (cin + 2 < ncin && is_loader && inb) {
            int c2 = cin + 2;
            const float* s2 = (c2 < CA)
                ? xin + (size_t)b * xin_bstride + (size_t)c2 * (HW * HW)
                : h_in + ((size_t)b * NF + (c2 - CA)) * (HW * HW);
            vnext = s2[goff];
        } else {
            vnext = 0.f;
        }

        if (cin + 1 < ncin) asm volatile("cp.async.wait_group 1;");
        else                asm volatile("cp.async.wait_group 0;");
        __syncthreads();

        // ---- compute: 288 FFMA2 + 66 LDS.64 ----
        const float* wb = s_w[buf];
#pragma unroll
        for (int kx = 0; kx < 3; kx++) {
            u64 dup[10];
#pragma unroll
            for (int r = 0; r < 10; r++)
                dup[r] = *reinterpret_cast<const u64*>(&s_it[buf][p + kx][r]);
#pragma unroll
            for (int dy = 0; dy < 3; dy++) {
#pragma unroll
                for (int gi = 0; gi < 4; gi++) {
                    u64 w2 = *reinterpret_cast<const u64*>(
                        &wb[(dy * 3 + kx) * GATES + gi * 64 + n0]);
#pragma unroll
                    for (int py = 0; py < 8; py++)
                        ffma2(acc[gi][py], dup[py + dy], w2);
                }
            }
        }
        __syncthreads();
    }

    // ---- LSTM pointwise epilogue ----
    // pixel (y0+py, x0+p); channels n0, n0+1
    const size_t ch0 = ((size_t)b * NF + n0) * (HW * HW);
    const size_t ch1 = ch0 + (HW * HW);
#pragma unroll
    for (int py = 0; py < 8; py++) {
        size_t off = (size_t)(y0 + py) * HW + (x0 + p);
        float i0, i1, f0, f1, o0, o1, g0, g1;
        unpk(i0, i1, acc[0][py]);
        unpk(f0, f1, acc[1][py]);
        unpk(o0, o1, acc[2][py]);
        unpk(g0, g1, acc[3][py]);
        float c0 = c[ch0 + off], c1 = c[ch1 + off];
        float cn0 = sigmoidf_(f0) * c0 + sigmoidf_(i0) * tanhf_(g0);
        float cn1 = sigmoidf_(f1) * c1 + sigmoidf_(i1) * tanhf_(g1);
        c[ch0 + off] = cn0;
        c[ch1 + off] = cn1;
        h_out[ch0 + off] = sigmoidf_(o0) * tanhf_(cn0);
        h_out[ch1 + off] = sigmoidf_(o1) * tanhf_(cn1);
    }
}

// ---------------- fused 3D-CNN head (kernel (1,3,3)) per decoder step ----------------
__global__ __launch_bounds__(256)
void cnn_head(const float* __restrict__ h, const float* __restrict__ Wc,
              const float* __restrict__ bc, float* __restrict__ out, int t) {
    __shared__ float s_w[NF * 9];
    __shared__ float s_t[18][20];

    const int tid = threadIdx.x;
    const int tx  = blockIdx.x & 3;
    const int ty  = (blockIdx.x >> 2) & 3;
    const int b   = blockIdx.x >> 4;
    const int px  = tid & 15;
    const int py  = tid >> 4;

    for (int i = tid; i < NF * 9; i += 256) s_w[i] = Wc[i];

    float acc = 0.f;
    const int gy0 = ty * 16 - 1, gx0 = tx * 16 - 1;
    for (int n = 0; n < NF; n++) {
        __syncthreads();
        const float* src = h + ((size_t)b * NF + n) * (HW * HW);
        for (int i = tid; i < 18 * 18; i += 256) {
            int r = i / 18, cc = i % 18;
            int gy = gy0 + r, gx = gx0 + cc;
            float v = 0.f;
            if ((unsigned)gy < HW && (unsigned)gx < HW) v = src[gy * HW + gx];
            s_t[r][cc] = v;
        }
        __syncthreads();
#pragma unroll
        for (int ky = 0; ky < 3; ky++)
#pragma unroll
            for (int kx = 0; kx < 3; kx++)
                acc += s_w[n * 9 + ky * 3 + kx] * s_t[py + ky][px + kx];
    }
    int yy = ty * 16 + py, xx = tx * 16 + px;
    out[((size_t)b * TT + t) * (HW * HW) + yy * HW + xx] = acc + bc[0];
}

// ---------------- launch ----------------
extern "C" void kernel_launch(void* const* d_in, const int* in_sizes, int n_in,
                              void* d_out, int out_size) {
    const float* x     = (const float*)d_in[0];
    // d_in[1] = future_step (always 12)
    const float* W_enc = (const float*)d_in[2];
    const float* b_enc = (const float*)d_in[3];
    const float* W_dec = (const float*)d_in[4];
    const float* b_dec = (const float*)d_in[5];
    const float* W_cnn = (const float*)d_in[6];
    const float* b_cnn = (const float*)d_in[7];
    float* out = (float*)d_out;

    float *hA, *hB, *c, *ev, *wet, *wdt;
    cudaGetSymbolAddress((void**)&hA,  g_hA);
    cudaGetSymbolAddress((void**)&hB,  g_hB);
    cudaGetSymbolAddress((void**)&c,   g_c);
    cudaGetSymbolAddress((void**)&ev,  g_ev);
    cudaGetSymbolAddress((void**)&wet, g_Wenc_t);
    cudaGetSymbolAddress((void**)&wdt, g_Wdec_t);

    zero_buf<<<2048, 256>>>(c, STATE_ELEMS);
    transpose_w<<<256, 256>>>(W_enc, wet, 65);
    transpose_w<<<256, 256>>>(W_dec, wdt, 128);

    // ---- encoder: 12 steps, x_t has 1 channel; t=0 skips zero h ----
    float* cur = hA;
    float* oth = hB;
    for (int t = 0; t < TT; t++) {
        int ncin = (t == 0) ? 1 : 65;
        convlstm_step<1><<<2048, 256>>>(x + (size_t)t * HW * HW, TT * HW * HW,
                                        cur, oth, c, wet, b_enc, ncin);
        float* tmp = cur; cur = oth; oth = tmp;
    }

    // encoder vector -> keep for decoder input, and write to output tail
    copy2<<<2048, 256>>>(cur, ev, out + Y_ELEMS, STATE_ELEMS);

    // decoder state restarts at zero (c only; t=0 never reads h_in)
    zero_buf<<<2048, 256>>>(c, STATE_ELEMS);

    // ---- decoder: 12 steps; input is ev then previous h; t=0 skips zero h ----
    for (int t = 0; t < TT; t++) {
        const float* xin = (t == 0) ? ev : cur;
        int ncin = (t == 0) ? 64 : 128;
        convlstm_step<64><<<2048, 256>>>(xin, NF * HW * HW, cur, oth, c, wdt,
                                         b_dec, ncin);
        cnn_head<<<512, 256>>>(oth, W_cnn, b_cnn, out, t);
        float* tmp = cur; cur = oth; oth = tmp;
    }
}

// round 5
// speedup vs baseline: 2.2327x; 1.0127x over previous
#include <cuda_runtime.h>
#include <math.h>

// ---------------- problem constants ----------------
#define HW   64
#define NF   64
#define BB   32
#define TT   12
#define GATES 256           // 4*NF
#define STATE_ELEMS (BB*NF*HW*HW)   // 8,388,608 floats
#define Y_ELEMS (BB*TT*HW*HW)       // 1,572,864 floats

typedef unsigned long long u64;

// ---------------- static device scratch (no allocs allowed) ----------------
__device__ float g_hA[STATE_ELEMS];
__device__ float g_hB[STATE_ELEMS];
__device__ float g_c [STATE_ELEMS];
__device__ float g_ev[STATE_ELEMS];
__device__ __align__(16) float g_Wenc_t[65  * GATES * 9];
__device__ __align__(16) float g_Wdec_t[128 * GATES * 9];

// ---------------- packed f32x2 helpers ----------------
__device__ __forceinline__ u64 pk(float lo, float hi) {
    u64 r; asm("mov.b64 %0, {%1, %2};" : "=l"(r) : "f"(lo), "f"(hi)); return r;
}
__device__ __forceinline__ void unpk(float& lo, float& hi, u64 v) {
    asm("mov.b64 {%0, %1}, %2;" : "=f"(lo), "=f"(hi) : "l"(v));
}
__device__ __forceinline__ void ffma2(u64& d, u64 a, u64 b) {
    asm("fma.rn.f32x2 %0, %1, %2, %0;" : "+l"(d) : "l"(a), "l"(b));
}

// ---------------- cp.async helpers ----------------
__device__ __forceinline__ void cp16(void* sdst, const void* gsrc) {
    unsigned s = (unsigned)__cvta_generic_to_shared(sdst);
    asm volatile("cp.async.cg.shared.global [%0], [%1], 16;" :: "r"(s), "l"(gsrc));
}
__device__ __forceinline__ void cp_commit() {
    asm volatile("cp.async.commit_group;");
}

// ---------------- small helpers ----------------
__global__ void zero_buf(float* __restrict__ p, int n) {
    for (int i = blockIdx.x * blockDim.x + threadIdx.x; i < n;
         i += gridDim.x * blockDim.x)
        p[i] = 0.f;
}

__global__ void copy2(const float* __restrict__ src, float* __restrict__ d1,
                      float* __restrict__ d2, int n) {
    for (int i = blockIdx.x * blockDim.x + threadIdx.x; i < n;
         i += gridDim.x * blockDim.x) {
        float v = src[i];
        d1[i] = v;
        d2[i] = v;
    }
}

// W[oc][cin][9] -> Wt[cin][tap][oc]   (oc fastest, so och pairs are adjacent)
__global__ void transpose_w(const float* __restrict__ W, float* __restrict__ Wt,
                            int CIN) {
    int total = CIN * 9 * GATES;
    for (int i = blockIdx.x * blockDim.x + threadIdx.x; i < total;
         i += gridDim.x * blockDim.x) {
        int oc   = i % GATES;
        int rest = i / GATES;
        int k    = rest % 9;
        int cin  = rest / 9;
        Wt[i] = W[((size_t)oc * CIN + cin) * 9 + k];
    }
}

__device__ __forceinline__ float sigmoidf_(float x) {
    return 1.f / (1.f + __expf(-x));
}
__device__ __forceinline__ float tanhf_(float x) {
    float e = __expf(2.f * x);
    return (e - 1.f) * __frcp_rn(e + 1.f);
}

// ---------------- fused ConvLSTM step ----------------
// Channel-packed f32x2, cp.async pipelined, 4 input channels per stage.
// Input = concat(xin [CA ch], h_in [NF ch]); weights pre-transposed [cin][9][256].
// Block: 256 threads, 8x8 pixel tile. Thread (g = tid>>3, p = tid&7) owns
// output-channel pair (2g, 2g+1) for all 4 gates at pixels (y0+py, x0+p).
template <int CA>
__global__ __launch_bounds__(256, 2)
void convlstm_step(const float* __restrict__ xin, int xin_bstride,
                   const float* __restrict__ h_in,
                   float* __restrict__ h_out,
                   float* __restrict__ c,
                   const float* __restrict__ Wt,      // [(CA+NF)*9*256]
                   const float* __restrict__ bias,    // [256]
                   int ncin) {
    __shared__ __align__(16) float  s_w[2][4 * 9 * GATES];   // 73.7 KB
    __shared__ __align__(16) float2 s_it[2][4][10][11];      // dup halo [x][y], 7 KB

    const int tid = threadIdx.x;
    const int bx  = blockIdx.x & 7;
    const int by  = (blockIdx.x >> 3) & 7;
    const int b   = blockIdx.x >> 6;
    const int g   = tid >> 3;               // 0..31 -> output-channel pair
    const int p   = tid & 7;                // x within tile
    const int n0  = g * 2;

    const int y0 = by * 8, x0 = bx * 8;

    // accumulators: 4 gates x 8 rows, packed over channel pair
    u64 acc[4][8];
#pragma unroll
    for (int gi = 0; gi < 4; gi++) {
        float2 bv = *reinterpret_cast<const float2*>(&bias[gi * 64 + n0]);
        u64 bp = pk(bv.x, bv.y);
#pragma unroll
        for (int py = 0; py < 8; py++) acc[gi][py] = bp;
    }

    // ---- loader-thread setup (100 threads stage the 10x10 halo) ----
    const bool is_loader = tid < 100;
    const int lr = tid / 10, lc = tid % 10;          // halo row/col
    const int gy = y0 - 1 + lr, gx = x0 - 1 + lc;
    const bool inb = ((unsigned)gy < HW) & ((unsigned)gx < HW);
    const int goff = gy * HW + gx;

    auto chan_ptr = [&](int ch) -> const float* {
        return (ch < CA)
            ? xin + (size_t)b * xin_bstride + (size_t)ch * (HW * HW)
            : h_in + ((size_t)b * NF + (ch - CA)) * (HW * HW);
    };
    auto stage_w = [&](float* wdst, int ch) {
        const float* wsrc = Wt + (size_t)ch * (9 * GATES);
        for (int i = tid; i < 576; i += 256)
            cp16(wdst + i * 4, wsrc + i * 4);
    };

    // ---- prologue: stage quad 0, prefetch inputs for quad 1 ----
    float vn[4];
    {
#pragma unroll
        for (int s = 0; s < 4; s++) {
            float v = 0.f;
            if (s < ncin && is_loader && inb) v = chan_ptr(s)[goff];
            if (is_loader) s_it[0][s][lc][lr] = make_float2(v, v);
        }
#pragma unroll
        for (int s = 0; s < 4; s++)
            stage_w(s_w[0] + s * (9 * GATES), min(s, ncin - 1));
        cp_commit();
#pragma unroll
        for (int s = 0; s < 4; s++) {
            vn[s] = 0.f;
            if (4 + s < ncin && is_loader && inb) vn[s] = chan_ptr(4 + s)[goff];
        }
    }

    // ---- main loop over channel quads, 2-stage pipeline ----
    const int nq = (ncin + 3) >> 2;
    for (int qi = 0; qi < nq; qi++) {
        const int buf = qi & 1, nb = buf ^ 1;
        const int base = qi * 4;

        if (qi + 1 < nq) {
#pragma unroll
            for (int s = 0; s < 4; s++)
                stage_w(s_w[nb] + s * (9 * GATES), min(base + 4 + s, ncin - 1));
            cp_commit();
            if (is_loader) {
#pragma unroll
                for (int s = 0; s < 4; s++)
                    s_it[nb][s][lc][lr] = make_float2(vn[s], vn[s]);
            }
        }
        // refill register prefetch for quad qi+2
#pragma unroll
        for (int s = 0; s < 4; s++) {
            vn[s] = 0.f;
            if (base + 8 + s < ncin && is_loader && inb)
                vn[s] = chan_ptr(base + 8 + s)[goff];
        }

        if (qi + 1 < nq) asm volatile("cp.async.wait_group 1;");
        else             asm volatile("cp.async.wait_group 0;");
        __syncthreads();

        // ---- compute up to 4 channels ----
#pragma unroll
        for (int s = 0; s < 4; s++) {
            if (base + s >= ncin) break;
            const float* wb = s_w[buf] + s * (9 * GATES);
#pragma unroll
            for (int kx = 0; kx < 3; kx++) {
                u64 dup_[10];
#pragma unroll
                for (int r = 0; r < 10; r++)
                    dup_[r] = *reinterpret_cast<const u64*>(&s_it[buf][s][p + kx][r]);
#pragma unroll
                for (int dy = 0; dy < 3; dy++) {
#pragma unroll
                    for (int gi = 0; gi < 4; gi++) {
                        u64 w2 = *reinterpret_cast<const u64*>(
                            &wb[(dy * 3 + kx) * GATES + gi * 64 + n0]);
#pragma unroll
                        for (int py = 0; py < 8; py++)
                            ffma2(acc[gi][py], dup_[py + dy], w2);
                    }
                }
            }
        }
        __syncthreads();
    }

    // ---- LSTM pointwise epilogue ----
    const size_t ch0 = ((size_t)b * NF + n0) * (HW * HW);
    const size_t ch1 = ch0 + (HW * HW);
#pragma unroll
    for (int py = 0; py < 8; py++) {
        size_t off = (size_t)(y0 + py) * HW + (x0 + p);
        float i0, i1, f0, f1, o0, o1, g0, g1;
        unpk(i0, i1, acc[0][py]);
        unpk(f0, f1, acc[1][py]);
        unpk(o0, o1, acc[2][py]);
        unpk(g0, g1, acc[3][py]);
        float c0 = c[ch0 + off], c1 = c[ch1 + off];
        float cn0 = sigmoidf_(f0) * c0 + sigmoidf_(i0) * tanhf_(g0);
        float cn1 = sigmoidf_(f1) * c1 + sigmoidf_(i1) * tanhf_(g1);
        c[ch0 + off] = cn0;
        c[ch1 + off] = cn1;
        h_out[ch0 + off] = sigmoidf_(o0) * tanhf_(cn0);
        h_out[ch1 + off] = sigmoidf_(o1) * tanhf_(cn1);
    }
}

// ---------------- fused 3D-CNN head (kernel (1,3,3)) per decoder step ----------------
__global__ __launch_bounds__(256)
void cnn_head(const float* __restrict__ h, const float* __restrict__ Wc,
              const float* __restrict__ bc, float* __restrict__ out, int t) {
    __shared__ float s_w[NF * 9];
    __shared__ float s_t[18][20];

    const int tid = threadIdx.x;
    const int tx  = blockIdx.x & 3;
    const int ty  = (blockIdx.x >> 2) & 3;
    const int b   = blockIdx.x >> 4;
    const int px  = tid & 15;
    const int py  = tid >> 4;

    for (int i = tid; i < NF * 9; i += 256) s_w[i] = Wc[i];

    float acc = 0.f;
    const int gy0 = ty * 16 - 1, gx0 = tx * 16 - 1;
    for (int n = 0; n < NF; n++) {
        __syncthreads();
        const float* src = h + ((size_t)b * NF + n) * (HW * HW);
        for (int i = tid; i < 18 * 18; i += 256) {
            int r = i / 18, cc = i % 18;
            int gy = gy0 + r, gx = gx0 + cc;
            float v = 0.f;
            if ((unsigned)gy < HW && (unsigned)gx < HW) v = src[gy * HW + gx];
            s_t[r][cc] = v;
        }
        __syncthreads();
#pragma unroll
        for (int ky = 0; ky < 3; ky++)
#pragma unroll
            for (int kx = 0; kx < 3; kx++)
                acc += s_w[n * 9 + ky * 3 + kx] * s_t[py + ky][px + kx];
    }
    int yy = ty * 16 + py, xx = tx * 16 + px;
    out[((size_t)b * TT + t) * (HW * HW) + yy * HW + xx] = acc + bc[0];
}

// ---------------- launch ----------------
extern "C" void kernel_launch(void* const* d_in, const int* in_sizes, int n_in,
                              void* d_out, int out_size) {
    const float* x     = (const float*)d_in[0];
    // d_in[1] = future_step (always 12)
    const float* W_enc = (const float*)d_in[2];
    const float* b_enc = (const float*)d_in[3];
    const float* W_dec = (const float*)d_in[4];
    const float* b_dec = (const float*)d_in[5];
    const float* W_cnn = (const float*)d_in[6];
    const float* b_cnn = (const float*)d_in[7];
    float* out = (float*)d_out;

    float *hA, *hB, *c, *ev, *wet, *wdt;
    cudaGetSymbolAddress((void**)&hA,  g_hA);
    cudaGetSymbolAddress((void**)&hB,  g_hB);
    cudaGetSymbolAddress((void**)&c,   g_c);
    cudaGetSymbolAddress((void**)&ev,  g_ev);
    cudaGetSymbolAddress((void**)&wet, g_Wenc_t);
    cudaGetSymbolAddress((void**)&wdt, g_Wdec_t);

    zero_buf<<<2048, 256>>>(c, STATE_ELEMS);
    transpose_w<<<256, 256>>>(W_enc, wet, 65);
    transpose_w<<<256, 256>>>(W_dec, wdt, 128);

    // ---- encoder: 12 steps, x_t has 1 channel; t=0 skips zero h ----
    float* cur = hA;
    float* oth = hB;
    for (int t = 0; t < TT; t++) {
        int ncin = (t == 0) ? 1 : 65;
        convlstm_step<1><<<2048, 256>>>(x + (size_t)t * HW * HW, TT * HW * HW,
                                        cur, oth, c, wet, b_enc, ncin);
        float* tmp = cur; cur = oth; oth = tmp;
    }

    // encoder vector -> keep for decoder input, and write to output tail
    copy2<<<2048, 256>>>(cur, ev, out + Y_ELEMS, STATE_ELEMS);

    // decoder state restarts at zero (c only; t=0 never reads h_in)
    zero_buf<<<2048, 256>>>(c, STATE_ELEMS);

    // ---- decoder: 12 steps; input is ev then previous h; t=0 skips zero h ----
    for (int t = 0; t < TT; t++) {
        const float* xin = (t == 0) ? ev : cur;
        int ncin = (t == 0) ? 64 : 128;
        convlstm_step<64><<<2048, 256>>>(xin, NF * HW * HW, cur, oth, c, wdt,
                                         b_dec, ncin);
        cnn_head<<<512, 256>>>(oth, W_cnn, b_cnn, out, t);
        float* tmp = cur; cur = oth; oth = tmp;
    }
}

// round 6
// speedup vs baseline: 2.2331x; 1.0002x over previous
#include <cuda_runtime.h>
#include <math.h>

// ---------------- problem constants ----------------
#define HW   64
#define NF   64
#define BB   32
#define TT   12
#define GATES 256           // 4*NF
#define STATE_ELEMS (BB*NF*HW*HW)   // 8,388,608 floats
#define Y_ELEMS (BB*TT*HW*HW)       // 1,572,864 floats

typedef unsigned long long u64;

// ---------------- static device scratch (no allocs allowed) ----------------
__device__ float g_hA[STATE_ELEMS];
__device__ float g_hB[STATE_ELEMS];
__device__ float g_c [STATE_ELEMS];
__device__ float g_ev[STATE_ELEMS];
__device__ __align__(16) float g_Wenc_t[65  * GATES * 9];
__device__ __align__(16) float g_Wdec_t[128 * GATES * 9];

// ---------------- packed f32x2 helpers ----------------
__device__ __forceinline__ u64 pk(float lo, float hi) {
    u64 r; asm("mov.b64 %0, {%1, %2};" : "=l"(r) : "f"(lo), "f"(hi)); return r;
}
__device__ __forceinline__ void unpk(float& lo, float& hi, u64 v) {
    asm("mov.b64 {%0, %1}, %2;" : "=f"(lo), "=f"(hi) : "l"(v));
}
__device__ __forceinline__ void ffma2(u64& d, u64 a, u64 b) {
    asm("fma.rn.f32x2 %0, %1, %2, %0;" : "+l"(d) : "l"(a), "l"(b));
}

// ---------------- cp.async helpers ----------------
__device__ __forceinline__ void cp16(void* sdst, const void* gsrc) {
    unsigned s = (unsigned)__cvta_generic_to_shared(sdst);
    asm volatile("cp.async.cg.shared.global [%0], [%1], 16;" :: "r"(s), "l"(gsrc));
}
__device__ __forceinline__ void cp_commit() {
    asm volatile("cp.async.commit_group;");
}

// ---------------- small helpers ----------------
__global__ void zero_buf(float* __restrict__ p, int n) {
    for (int i = blockIdx.x * blockDim.x + threadIdx.x; i < n;
         i += gridDim.x * blockDim.x)
        p[i] = 0.f;
}

__global__ void copy2(const float* __restrict__ src, float* __restrict__ d1,
                      float* __restrict__ d2, int n) {
    for (int i = blockIdx.x * blockDim.x + threadIdx.x; i < n;
         i += gridDim.x * blockDim.x) {
        float v = src[i];
        d1[i] = v;
        d2[i] = v;
    }
}

// W[oc][cin][9] -> Wt[cin][tap][oc]   (oc fastest, so och pairs are adjacent)
__global__ void transpose_w(const float* __restrict__ W, float* __restrict__ Wt,
                            int CIN) {
    int total = CIN * 9 * GATES;
    for (int i = blockIdx.x * blockDim.x + threadIdx.x; i < total;
         i += gridDim.x * blockDim.x) {
        int oc   = i % GATES;
        int rest = i / GATES;
        int k    = rest % 9;
        int cin  = rest / 9;
        Wt[i] = W[((size_t)oc * CIN + cin) * 9 + k];
    }
}

__device__ __forceinline__ float sigmoidf_(float x) {
    return 1.f / (1.f + __expf(-x));
}
__device__ __forceinline__ float tanhf_(float x) {
    float e = __expf(2.f * x);
    return (e - 1.f) * __frcp_rn(e + 1.f);
}

// ---------------- fused ConvLSTM step ----------------
// Channel-packed f32x2, cp.async pipelined, 4 input channels per stage.
// Input = concat(xin [CA ch], h_in [NF ch]); weights pre-transposed [cin][9][256].
// Block: 256 threads, 8x8 pixel tile. Thread (g = tid>>3, p = tid&7) owns
// output-channel pair (2g, 2g+1) for all 4 gates at pixels (y0+py, x0+p).
template <int CA>
__global__ __launch_bounds__(256, 2)
void convlstm_step(const float* __restrict__ xin, int xin_bstride,
                   const float* __restrict__ h_in,
                   float* __restrict__ h_out,
                   float* __restrict__ c,
                   const float* __restrict__ Wt,      // [(CA+NF)*9*256]
                   const float* __restrict__ bias,    // [256]
                   int ncin) {
    __shared__ __align__(16) float  s_w[2][4 * 9 * GATES];   // 73.7 KB
    __shared__ __align__(16) float2 s_it[2][4][10][11];      // dup halo [x][y], 7 KB

    const int tid = threadIdx.x;
    const int bx  = blockIdx.x & 7;
    const int by  = (blockIdx.x >> 3) & 7;
    const int b   = blockIdx.x >> 6;
    const int g   = tid >> 3;               // 0..31 -> output-channel pair
    const int p   = tid & 7;                // x within tile
    const int n0  = g * 2;

    const int y0 = by * 8, x0 = bx * 8;

    // accumulators: 4 gates x 8 rows, packed over channel pair
    u64 acc[4][8];
#pragma unroll
    for (int gi = 0; gi < 4; gi++) {
        float2 bv = *reinterpret_cast<const float2*>(&bias[gi * 64 + n0]);
        u64 bp = pk(bv.x, bv.y);
#pragma unroll
        for (int py = 0; py < 8; py++) acc[gi][py] = bp;
    }

    // ---- loader-thread setup (100 threads stage the 10x10 halo) ----
    const bool is_loader = tid < 100;
    const int lr = tid / 10, lc = tid % 10;          // halo row/col
    const int gy = y0 - 1 + lr, gx = x0 - 1 + lc;
    const bool inb = ((unsigned)gy < HW) & ((unsigned)gx < HW);
    const int goff = gy * HW + gx;

    auto chan_ptr = [&](int ch) -> const float* {
        return (ch < CA)
            ? xin + (size_t)b * xin_bstride + (size_t)ch * (HW * HW)
            : h_in + ((size_t)b * NF + (ch - CA)) * (HW * HW);
    };
    auto stage_w = [&](float* wdst, int ch) {
        const float* wsrc = Wt + (size_t)ch * (9 * GATES);
        for (int i = tid; i < 576; i += 256)
            cp16(wdst + i * 4, wsrc + i * 4);
    };

    // ---- prologue: stage quad 0, prefetch inputs for quad 1 ----
    float vn[4];
    {
#pragma unroll
        for (int s = 0; s < 4; s++) {
            float v = 0.f;
            if (s < ncin && is_loader && inb) v = chan_ptr(s)[goff];
            if (is_loader) s_it[0][s][lc][lr] = make_float2(v, v);
        }
#pragma unroll
        for (int s = 0; s < 4; s++)
            stage_w(s_w[0] + s * (9 * GATES), min(s, ncin - 1));
        cp_commit();
#pragma unroll
        for (int s = 0; s < 4; s++) {
            vn[s] = 0.f;
            if (4 + s < ncin && is_loader && inb) vn[s] = chan_ptr(4 + s)[goff];
        }
    }

    // ---- main loop over channel quads, 2-stage pipeline ----
    const int nq = (ncin + 3) >> 2;
    for (int qi = 0; qi < nq; qi++) {
        const int buf = qi & 1, nb = buf ^ 1;
        const int base = qi * 4;

        if (qi + 1 < nq) {
#pragma unroll
            for (int s = 0; s < 4; s++)
                stage_w(s_w[nb] + s * (9 * GATES), min(base + 4 + s, ncin - 1));
            cp_commit();
            if (is_loader) {
#pragma unroll
                for (int s = 0; s < 4; s++)
                    s_it[nb][s][lc][lr] = make_float2(vn[s], vn[s]);
            }
        }
        // refill register prefetch for quad qi+2
#pragma unroll
        for (int s = 0; s < 4; s++) {
            vn[s] = 0.f;
            if (base + 8 + s < ncin && is_loader && inb)
                vn[s] = chan_ptr(base + 8 + s)[goff];
        }

        if (qi + 1 < nq) asm volatile("cp.async.wait_group 1;");
        else             asm volatile("cp.async.wait_group 0;");
        __syncthreads();

        // ---- compute up to 4 channels ----
#pragma unroll
        for (int s = 0; s < 4; s++) {
            if (base + s >= ncin) break;
            const float* wb = s_w[buf] + s * (9 * GATES);
#pragma unroll
            for (int kx = 0; kx < 3; kx++) {
                u64 dup_[10];
#pragma unroll
                for (int r = 0; r < 10; r++)
                    dup_[r] = *reinterpret_cast<const u64*>(&s_it[buf][s][p + kx][r]);
#pragma unroll
                for (int dy = 0; dy < 3; dy++) {
#pragma unroll
                    for (int gi = 0; gi < 4; gi++) {
                        u64 w2 = *reinterpret_cast<const u64*>(
                            &wb[(dy * 3 + kx) * GATES + gi * 64 + n0]);
#pragma unroll
                        for (int py = 0; py < 8; py++)
                            ffma2(acc[gi][py], dup_[py + dy], w2);
                    }
                }
            }
        }
        __syncthreads();
    }

    // ---- LSTM pointwise epilogue ----
    const size_t ch0 = ((size_t)b * NF + n0) * (HW * HW);
    const size_t ch1 = ch0 + (HW * HW);
#pragma unroll
    for (int py = 0; py < 8; py++) {
        size_t off = (size_t)(y0 + py) * HW + (x0 + p);
        float i0, i1, f0, f1, o0, o1, g0, g1;
        unpk(i0, i1, acc[0][py]);
        unpk(f0, f1, acc[1][py]);
        unpk(o0, o1, acc[2][py]);
        unpk(g0, g1, acc[3][py]);
        float c0 = c[ch0 + off], c1 = c[ch1 + off];
        float cn0 = sigmoidf_(f0) * c0 + sigmoidf_(i0) * tanhf_(g0);
        float cn1 = sigmoidf_(f1) * c1 + sigmoidf_(i1) * tanhf_(g1);
        c[ch0 + off] = cn0;
        c[ch1 + off] = cn1;
        h_out[ch0 + off] = sigmoidf_(o0) * tanhf_(cn0);
        h_out[ch1 + off] = sigmoidf_(o1) * tanhf_(cn1);
    }
}

// ---------------- fused 3D-CNN head (kernel (1,3,3)) per decoder step ----------------
__global__ __launch_bounds__(256)
void cnn_head(const float* __restrict__ h, const float* __restrict__ Wc,
              const float* __restrict__ bc, float* __restrict__ out, int t) {
    __shared__ float s_w[NF * 9];
    __shared__ float s_t[18][20];

    const int tid = threadIdx.x;
    const int tx  = blockIdx.x & 3;
    const int ty  = (blockIdx.x >> 2) & 3;
    const int b   = blockIdx.x >> 4;
    const int px  = tid & 15;
    const int py  = tid >> 4;

    for (int i = tid; i < NF * 9; i += 256) s_w[i] = Wc[i];

    float acc = 0.f;
    const int gy0 = ty * 16 - 1, gx0 = tx * 16 - 1;
    for (int n = 0; n < NF; n++) {
        __syncthreads();
        const float* src = h + ((size_t)b * NF + n) * (HW * HW);
        for (int i = tid; i < 18 * 18; i += 256) {
            int r = i / 18, cc = i % 18;
            int gy = gy0 + r, gx = gx0 + cc;
            float v = 0.f;
            if ((unsigned)gy < HW && (unsigned)gx < HW) v = src[gy * HW + gx];
            s_t[r][cc] = v;
        }
        __syncthreads();
#pragma unroll
        for (int ky = 0; ky < 3; ky++)
#pragma unroll
            for (int kx = 0; kx < 3; kx++)
                acc += s_w[n * 9 + ky * 3 + kx] * s_t[py + ky][px + kx];
    }
    int yy = ty * 16 + py, xx = tx * 16 + px;
    out[((size_t)b * TT + t) * (HW * HW) + yy * HW + xx] = acc + bc[0];
}

// ---------------- launch ----------------
extern "C" void kernel_launch(void* const* d_in, const int* in_sizes, int n_in,
                              void* d_out, int out_size) {
    const float* x     = (const float*)d_in[0];
    // d_in[1] = future_step (always 12)
    const float* W_enc = (const float*)d_in[2];
    const float* b_enc = (const float*)d_in[3];
    const float* W_dec = (const float*)d_in[4];
    const float* b_dec = (const float*)d_in[5];
    const float* W_cnn = (const float*)d_in[6];
    const float* b_cnn = (const float*)d_in[7];
    float* out = (float*)d_out;

    float *hA, *hB, *c, *ev, *wet, *wdt;
    cudaGetSymbolAddress((void**)&hA,  g_hA);
    cudaGetSymbolAddress((void**)&hB,  g_hB);
    cudaGetSymbolAddress((void**)&c,   g_c);
    cudaGetSymbolAddress((void**)&ev,  g_ev);
    cudaGetSymbolAddress((void**)&wet, g_Wenc_t);
    cudaGetSymbolAddress((void**)&wdt, g_Wdec_t);

    zero_buf<<<2048, 256>>>(c, STATE_ELEMS);
    transpose_w<<<256, 256>>>(W_enc, wet, 65);
    transpose_w<<<256, 256>>>(W_dec, wdt, 128);

    // ---- encoder: 12 steps, x_t has 1 channel; t=0 skips zero h ----
    float* cur = hA;
    float* oth = hB;
    for (int t = 0; t < TT; t++) {
        int ncin = (t == 0) ? 1 : 65;
        convlstm_step<1><<<2048, 256>>>(x + (size_t)t * HW * HW, TT * HW * HW,
                                        cur, oth, c, wet, b_enc, ncin);
        float* tmp = cur; cur = oth; oth = tmp;
    }

    // encoder vector -> keep for decoder input, and write to output tail
    copy2<<<2048, 256>>>(cur, ev, out + Y_ELEMS, STATE_ELEMS);

    // decoder state restarts at zero (c only; t=0 never reads h_in)
    zero_buf<<<2048, 256>>>(c, STATE_ELEMS);

    // ---- decoder: 12 steps; input is ev then previous h; t=0 skips zero h ----
    for (int t = 0; t < TT; t++) {
        const float* xin = (t == 0) ? ev : cur;
        int ncin = (t == 0) ? 64 : 128;
        convlstm_step<64><<<2048, 256>>>(xin, NF * HW * HW, cur, oth, c, wdt,
                                         b_dec, ncin);
        cnn_head<<<512, 256>>>(oth, W_cnn, b_cnn, out, t);
        float* tmp = cur; cur = oth; oth = tmp;
    }
}

// round 8
// speedup vs baseline: 3.3439x; 1.4974x over previous
#include <cuda_runtime.h>
#include <cuda_bf16.h>
#include <math.h>
#include <stdint.h>

// ---------------- constants ----------------
#define HW 64
#define NF 64
#define BB 32
#define TT 12
#define PHW 66
#define PPX (PHW*PHW)                 // 4356
#define STATE_ELEMS (BB*NF*HW*HW)     // 8,388,608
#define Y_ELEMS (BB*TT*HW*HW)         // 1,572,864

// ---------------- smem layout (bytes) ----------------
#define O_INH 0                       // input slab hi: 198 px * 144B
#define O_INL 28512                   // input slab lo
#define O_WB0 57024                   // weight buf 0: 256 oc * 144B
#define O_WB1 93888                   // weight buf 1
#define O_XS  130752                  // x rows: 198 fp32
#define O_WX  131552                  // Wx: 2304 fp32
#define SMEM_BYTES 140800
// epilogue overlays gates fp32 [4][64px][64ch] = 65536B at offset 0

// ---------------- device globals ----------------
__device__ float g_c[STATE_ELEMS];
__device__ __align__(16) __nv_bfloat16 g_nhA_hi[BB*PPX*NF];
__device__ __align__(16) __nv_bfloat16 g_nhA_lo[BB*PPX*NF];
__device__ __align__(16) __nv_bfloat16 g_nhB_hi[BB*PPX*NF];
__device__ __align__(16) __nv_bfloat16 g_nhB_lo[BB*PPX*NF];
__device__ __align__(16) __nv_bfloat16 g_WhE[9*2*256*64];  // [tap][hi/lo][oc][ch]
__device__ __align__(16) __nv_bfloat16 g_WdX[9*2*256*64];
__device__ __align__(16) __nv_bfloat16 g_WdS[9*2*256*64];
__device__ float g_Wxf[256*9];

// ---------------- PTX helpers ----------------
__device__ __forceinline__ uint32_t smem_u32(const void* p) {
    uint32_t a;
    asm("{ .reg .u64 t; cvta.to.shared.u64 t, %1; cvt.u32.u64 %0, t; }" : "=r"(a) : "l"(p));
    return a;
}
__device__ __forceinline__ void cp16_s(uint32_t sdst, const void* g) {
    asm volatile("cp.async.cg.shared.global [%0], [%1], 16;" :: "r"(sdst), "l"(g));
}
__device__ __forceinline__ void ldsm4(uint32_t* r, uint32_t addr) {
    asm volatile("ldmatrix.sync.aligned.m8n8.x4.shared.b16 {%0,%1,%2,%3}, [%4];"
        : "=r"(r[0]), "=r"(r[1]), "=r"(r[2]), "=r"(r[3]) : "r"(addr));
}
__device__ __forceinline__ void ldsm2(uint32_t* r, uint32_t addr) {
    asm volatile("ldmatrix.sync.aligned.m8n8.x2.shared.b16 {%0,%1}, [%2];"
        : "=r"(r[0]), "=r"(r[1]) : "r"(addr));
}
__device__ __forceinline__ void mma16816(float* d, const uint32_t* a, const uint32_t* b) {
    asm volatile("mma.sync.aligned.m16n8k16.row.col.f32.bf16.bf16.f32 "
        "{%0,%1,%2,%3}, {%4,%5,%6,%7}, {%8,%9}, {%0,%1,%2,%3};"
        : "+f"(d[0]), "+f"(d[1]), "+f"(d[2]), "+f"(d[3])
        : "r"(a[0]), "r"(a[1]), "r"(a[2]), "r"(a[3]), "r"(b[0]), "r"(b[1]));
}
__device__ __forceinline__ float sigmoidf_(float x) { return 1.f / (1.f + __expf(-x)); }
__device__ __forceinline__ float tanhf_(float x) {
    float e = __expf(2.f * x);
    return (e - 1.f) * __frcp_rn(e + 1.f);
}

// ---------------- prep kernels ----------------
__global__ void zero_buf(float* __restrict__ p, int n) {
    for (int i = blockIdx.x * blockDim.x + threadIdx.x; i < n; i += gridDim.x * blockDim.x)
        p[i] = 0.f;
}
// W[oc][CIN][9] -> dst[tap][hi/lo][oc][64ch], channels off1.., optional fold +off2
__global__ void prep_wh(const float* __restrict__ W, __nv_bfloat16* __restrict__ dst,
                        int CIN, int off1, int off2) {
    int idx = blockIdx.x * blockDim.x + threadIdx.x;
    if (idx >= 9 * 256 * 64) return;
    int ch = idx & 63, oc = (idx >> 6) & 255, tap = idx >> 14;
    float w = W[((size_t)oc * CIN + off1 + ch) * 9 + tap];
    if (off2 >= 0) w += W[((size_t)oc * CIN + off2 + ch) * 9 + tap];
    __nv_bfloat16 hi = __float2bfloat16(w);
    __nv_bfloat16 lo = __float2bfloat16(w - __bfloat162float(hi));
    dst[(((size_t)tap * 2 + 0) * 256 + oc) * 64 + ch] = hi;
    dst[(((size_t)tap * 2 + 1) * 256 + oc) * 64 + ch] = lo;
}
__global__ void prep_wxf(const float* __restrict__ W, float* __restrict__ dst) {
    int i = blockIdx.x * blockDim.x + threadIdx.x;
    if (i >= 2304) return;
    int oc = i / 9, tap = i % 9;
    dst[i] = W[(size_t)oc * 65 * 9 + tap];   // cin 0 = x channel
}

// ---------------- ConvLSTM step: bf16 mma.sync implicit GEMM ----------------
// grid 2048 = 32 b x 64 y-rows; 256 threads (8 warps: 4 M-warps x 2 N-warps)
__global__ void __launch_bounds__(256, 1)
conv_step(const __nv_bfloat16* __restrict__ hi_in, const __nv_bfloat16* __restrict__ lo_in,
          __nv_bfloat16* __restrict__ hi_out, __nv_bfloat16* __restrict__ lo_out,
          float* __restrict__ c,
          const __nv_bfloat16* __restrict__ Wm,
          const float* __restrict__ x, int t,
          const float* __restrict__ bias, int has_mma, int has_x) {
    extern __shared__ __align__(16) unsigned char smem[];
    const uint32_t sb = smem_u32(smem);
    const int tid = threadIdx.x, wid = tid >> 5, lane = tid & 31;
    const int b = blockIdx.x >> 6, y = blockIdx.x & 63;

    // ---- prologue staging ----
    if (has_x) {
        if (tid < 198) {
            int r = tid / 66, cc = tid % 66;
            int gy = y + r - 1, gx = cc - 1;
            float v = 0.f;
            if ((unsigned)gy < 64u && (unsigned)gx < 64u)
                v = x[((size_t)b * TT + t) * 4096 + gy * 64 + gx];
            ((float*)(smem + O_XS))[tid] = v;
        }
#pragma unroll
        for (int j = 0; j < 9; j++) {
            int idx = tid + j * 256;
            if (idx < 2304) ((float*)(smem + O_WX))[idx] = g_Wxf[idx];
        }
    }

    auto stage_w = [&](uint32_t dstoff, int ci) {
        const char* src = (const char*)(Wm + (size_t)ci * 16384);
#pragma unroll
        for (int j = 0; j < 8; j++) {
            int idx = tid + j * 256;            // 0..2047
            int oc = idx >> 3, seg = idx & 7;
            cp16_s(sb + dstoff + oc * 144 + seg * 16, src + oc * 128 + seg * 16);
        }
    };

    if (has_mma) {
        const char* hbase = (const char*)(hi_in + ((size_t)b * PPX + (size_t)y * PHW) * 64);
        const char* lbase = (const char*)(lo_in + ((size_t)b * PPX + (size_t)y * PHW) * 64);
#pragma unroll
        for (int j = 0; j < 7; j++) {
            int idx = tid + j * 256;
            if (idx < 1584) {
                int p = idx >> 3, seg = idx & 7;
                cp16_s(sb + O_INH + p * 144 + seg * 16, hbase + p * 128 + seg * 16);
                cp16_s(sb + O_INL + p * 144 + seg * 16, lbase + p * 128 + seg * 16);
            }
        }
        stage_w(O_WB0, 0);
        asm volatile("cp.async.commit_group;" ::: "memory");
        stage_w(O_WB1, 1);
        asm volatile("cp.async.commit_group;" ::: "memory");
    }

    // ---- main loop ----
    const int mw = wid & 3;                  // gate block (64 oc)
    const int nw = wid >> 2;                 // px half (32 px)
    const uint32_t a_row = mw * 64 + (lane & 15);
    const uint32_t a_kh = ((lane >> 4) << 3);
    const int bn = lane & 7;
    const int bk = ((lane >> 3) & 1) << 3;

    float acc[4][4][4];
#pragma unroll
    for (int i = 0; i < 4; i++)
#pragma unroll
        for (int j = 0; j < 4; j++)
#pragma unroll
            for (int k = 0; k < 4; k++) acc[i][j][k] = 0.f;

    if (has_mma) {
        for (int ci = 0; ci < 18; ci++) {
            if (ci < 17) asm volatile("cp.async.wait_group 1;" ::: "memory");
            else         asm volatile("cp.async.wait_group 0;" ::: "memory");
            __syncthreads();

            const uint32_t wb = sb + ((ci & 1) ? O_WB1 : O_WB0);
            const int tap = ci >> 1, comp = ci & 1;
            const int dy = tap / 3, dx = tap % 3;
            const int npass = comp ? 1 : 2;
            const uint32_t bpx = (dy * 66 + dx + nw * 32 + bn) * 144;

#pragma unroll
            for (int ks = 0; ks < 4; ks++) {
                const int k0 = ks * 16;
                uint32_t af[4][4];
#pragma unroll
                for (int mf = 0; mf < 4; mf++)
                    ldsm4(af[mf], wb + (a_row + mf * 16) * 144 + (k0 + a_kh) * 2);
                for (int pp = 0; pp < npass; pp++) {
                    const uint32_t slab = sb + (pp ? O_INL : O_INH);
                    uint32_t bf[4][2];
#pragma unroll
                    for (int nf = 0; nf < 4; nf++)
                        ldsm2(bf[nf], slab + bpx + nf * 8 * 144 + (k0 + bk) * 2);
#pragma unroll
                    for (int mf = 0; mf < 4; mf++)
#pragma unroll
                        for (int nf = 0; nf < 4; nf++)
                            mma16816(acc[mf][nf], af[mf], bf[nf]);
                }
            }
            __syncthreads();
            if (ci + 2 < 18) {
                stage_w((ci & 1) ? O_WB1 : O_WB0, ci + 2);
                asm volatile("cp.async.commit_group;" ::: "memory");
            }
        }
    }
    __syncthreads();

    // ---- store gate fragments to smem overlay [gate][px 64][ch 64] fp32 ----
    float* sg = (float*)smem;
    if (has_mma) {
        const int g = lane >> 2, tp = lane & 3;
#pragma unroll
        for (int mf = 0; mf < 4; mf++)
#pragma unroll
            for (int nf = 0; nf < 4; nf++) {
                int ch0 = mf * 16 + g;
                int px0 = nw * 32 + nf * 8 + tp * 2;
                float* p = sg + mw * 4096 + px0 * 64 + ch0;
                p[0]      = acc[mf][nf][0];
                p[64]     = acc[mf][nf][1];
                p[8]      = acc[mf][nf][2];
                p[64 + 8] = acc[mf][nf][3];
            }
    }
    __syncthreads();

    // ---- LSTM pointwise epilogue ----
    const int ch = tid & 63;
    const int pxb = (tid >> 6) * 16;
    const float bi = __ldg(bias + ch);
    const float bf_ = __ldg(bias + 64 + ch);
    const float bo = __ldg(bias + 128 + ch);
    const float bg = __ldg(bias + 192 + ch);

    float wxr[36];
    if (has_x) {
        const float* sWx = (const float*)(smem + O_WX);
#pragma unroll
        for (int g4 = 0; g4 < 4; g4++)
#pragma unroll
            for (int tp = 0; tp < 9; tp++)
                wxr[g4 * 9 + tp] = sWx[(g4 * 64 + ch) * 9 + tp];
    }
    const float* sx = (const float*)(smem + O_XS);

#pragma unroll 4
    for (int k = 0; k < 16; k++) {
        const int px = pxb + k;
        float vi = bi, vf = bf_, vo = bo, vg = bg;
        if (has_mma) {
            vi += sg[px * 64 + ch];
            vf += sg[4096 + px * 64 + ch];
            vo += sg[8192 + px * 64 + ch];
            vg += sg[12288 + px * 64 + ch];
        }
        if (has_x) {
            float xs[9];
#pragma unroll
            for (int tp = 0; tp < 9; tp++)
                xs[tp] = sx[(tp / 3) * 66 + (tp % 3) + px];
            float s0 = 0, s1 = 0, s2 = 0, s3 = 0;
#pragma unroll
            for (int tp = 0; tp < 9; tp++) {
                s0 += wxr[tp] * xs[tp];
                s1 += wxr[9 + tp] * xs[tp];
                s2 += wxr[18 + tp] * xs[tp];
                s3 += wxr[27 + tp] * xs[tp];
            }
            vi += s0; vf += s1; vo += s2; vg += s3;
        }
        const size_t coff = (((size_t)b * 64 + y) * 64 + px) * 64 + ch;
        float cn = sigmoidf_(vf) * c[coff] + sigmoidf_(vi) * tanhf_(vg);
        c[coff] = cn;
        float hv = sigmoidf_(vo) * tanhf_(cn);
        __nv_bfloat16 hhi = __float2bfloat16(hv);
        __nv_bfloat16 hlo = __float2bfloat16(hv - __bfloat162float(hhi));
        const size_t hoff = ((size_t)b * PPX + (size_t)(y + 1) * PHW + (px + 1)) * 64 + ch;
        hi_out[hoff] = hhi;
        lo_out[hoff] = hlo;
    }
}

// ---------------- encoder-vector: padded NHWC hi/lo -> NCHW fp32 ----------------
__global__ void ev_out(const __nv_bfloat16* __restrict__ hi, const __nv_bfloat16* __restrict__ lo,
                       float* __restrict__ outv) {
    __shared__ float s[64][65];
    int b = blockIdx.x >> 6, y = blockIdx.x & 63;
    int tid = threadIdx.x;
#pragma unroll
    for (int i = 0; i < 16; i++) {
        int xx = (tid >> 6) + i * 4, ch = tid & 63;
        size_t off = (((size_t)b * PPX) + (size_t)(y + 1) * PHW + (xx + 1)) * 64 + ch;
        s[xx][ch] = __bfloat162float(hi[off]) + __bfloat162float(lo[off]);
    }
    __syncthreads();
#pragma unroll
    for (int i = 0; i < 16; i++) {
        int xx = tid & 63, ch = (tid >> 6) + i * 4;
        outv[((size_t)b * 64 + ch) * 4096 + y * 64 + xx] = s[xx][ch];
    }
}

// ---------------- 3D CNN head from padded NHWC hi/lo ----------------
__global__ void cnn_head(const __nv_bfloat16* __restrict__ hi, const __nv_bfloat16* __restrict__ lo,
                         const float* __restrict__ Wc, const float* __restrict__ bc,
                         float* __restrict__ out, int t) {
    __shared__ float s_w[9 * 64];
    int b = blockIdx.x >> 4, yg = blockIdx.x & 15, y0 = yg * 4;
    int tid = threadIdx.x;
    for (int i = tid; i < 576; i += 256) {
        int ch = i / 9, tap = i % 9;
        s_w[tap * 64 + ch] = Wc[i];
    }
    __syncthreads();
    int r = tid >> 6, xx = tid & 63, iy = y0 + r;
    float acc = bc[0];
#pragma unroll
    for (int ky = 0; ky < 3; ky++)
#pragma unroll
        for (int kx = 0; kx < 3; kx++) {
            size_t base = (((size_t)b * PPX) + (size_t)(iy + ky) * PHW + (xx + kx)) * 64;
            const float* wrow = s_w + (ky * 3 + kx) * 64;
            float s = 0.f;
            for (int ch = 0; ch < 64; ch++)
                s += wrow[ch] * (__bfloat162float(hi[base + ch]) + __bfloat162float(lo[base + ch]));
            acc += s;
        }
    out[((size_t)b * TT + t) * 4096 + iy * 64 + xx] = acc;
}

// ---------------- launch ----------------
extern "C" void kernel_launch(void* const* d_in, const int* in_sizes, int n_in,
                              void* d_out, int out_size) {
    const float* x     = (const float*)d_in[0];
    const float* W_enc = (const float*)d_in[2];
    const float* b_enc = (const float*)d_in[3];
    const float* W_dec = (const float*)d_in[4];
    const float* b_dec = (const float*)d_in[5];
    const float* W_cnn = (const float*)d_in[6];
    const float* b_cnn = (const float*)d_in[7];
    float* out = (float*)d_out;

    float *c, *wxf;
    __nv_bfloat16 *ahi, *alo, *bhi, *blo, *whe, *wdx, *wds;
    cudaGetSymbolAddress((void**)&c, g_c);
    cudaGetSymbolAddress((void**)&ahi, g_nhA_hi);
    cudaGetSymbolAddress((void**)&alo, g_nhA_lo);
    cudaGetSymbolAddress((void**)&bhi, g_nhB_hi);
    cudaGetSymbolAddress((void**)&blo, g_nhB_lo);
    cudaGetSymbolAddress((void**)&whe, g_WhE);
    cudaGetSymbolAddress((void**)&wdx, g_WdX);
    cudaGetSymbolAddress((void**)&wds, g_WdS);
    cudaGetSymbolAddress((void**)&wxf, g_Wxf);

    cudaFuncSetAttribute(conv_step, cudaFuncAttributeMaxDynamicSharedMemorySize, SMEM_BYTES);

    zero_buf<<<2048, 256>>>(c, STATE_ELEMS);
    zero_buf<<<2048, 256>>>((float*)ahi, BB * PPX * NF / 2);
    zero_buf<<<2048, 256>>>((float*)alo, BB * PPX * NF / 2);
    zero_buf<<<2048, 256>>>((float*)bhi, BB * PPX * NF / 2);
    zero_buf<<<2048, 256>>>((float*)blo, BB * PPX * NF / 2);

    prep_wh<<<576, 256>>>(W_enc, whe, 65, 1, -1);
    prep_wh<<<576, 256>>>(W_dec, wdx, 128, 0, -1);
    prep_wh<<<576, 256>>>(W_dec, wds, 128, 0, 64);
    prep_wxf<<<9, 256>>>(W_enc, wxf);

    __nv_bfloat16 *curhi = ahi, *curlo = alo, *othhi = bhi, *othlo = blo;

    // ---- encoder ----
    for (int t = 0; t < TT; t++) {
        conv_step<<<2048, 256, SMEM_BYTES>>>(curhi, curlo, othhi, othlo, c,
                                             whe, x, t, b_enc, t > 0, 1);
        __nv_bfloat16* tp;
        tp = curhi; curhi = othhi; othhi = tp;
        tp = curlo; curlo = othlo; othlo = tp;
    }

    ev_out<<<BB * 64, 256>>>(curhi, curlo, out + Y_ELEMS);
    zero_buf<<<2048, 256>>>(c, STATE_ELEMS);

    // ---- decoder ----
    for (int t = 0; t < TT; t++) {
        const __nv_bfloat16* W = (t == 0) ? wdx : wds;
        conv_step<<<2048, 256, SMEM_BYTES>>>(curhi, curlo, othhi, othlo, c,
                                             W, x, t, b_dec, 1, 0);
        cnn_head<<<512, 256>>>(othhi, othlo, W_cnn, b_cnn, out, t);
        __nv_bfloat16* tp;
        tp = curhi; curhi = othhi; othhi = tp;
        tp = curlo; curlo = othlo; othlo = tp;
    }
}

// round 9
// speedup vs baseline: 3.9200x; 1.1723x over previous
#include <cuda_runtime.h>
#include <cuda_bf16.h>
#include <math.h>
#include <stdint.h>

// ---------------- constants ----------------
#define HW 64
#define NF 64
#define BB 32
#define TT 12
#define PHW 66
#define PPX (PHW*PHW)                 // 4356
#define STATE_ELEMS (BB*NF*HW*HW)     // 8,388,608
#define Y_ELEMS (BB*TT*HW*HW)         // 1,572,864

// ---------------- smem layout (bytes) ----------------
#define O_INH 0                       // input slab hi: 264 px * 144B (4 rows x 66)
#define O_INL 38016                   // input slab lo
#define O_WB0 76032                   // weight buf 0: 256 oc * 144B
#define O_WB1 112896                  // weight buf 1
#define O_XS  149760                  // x slab: 264 fp32
#define O_WX  150816                  // Wx: 2304 fp32
#define SMEM_BYTES 160064
// epilogue overlays gates fp32 [4][128px][64ch] = 131072B at offset 0

// ---------------- device globals ----------------
__device__ float g_c[STATE_ELEMS];
__device__ __align__(16) __nv_bfloat16 g_nhA_hi[BB*PPX*NF];
__device__ __align__(16) __nv_bfloat16 g_nhA_lo[BB*PPX*NF];
__device__ __align__(16) __nv_bfloat16 g_nhB_hi[BB*PPX*NF];
__device__ __align__(16) __nv_bfloat16 g_nhB_lo[BB*PPX*NF];
__device__ __align__(16) __nv_bfloat16 g_WhE[9*2*256*64];  // [tap][hi/lo][oc][ch]
__device__ __align__(16) __nv_bfloat16 g_WdX[9*2*256*64];
__device__ __align__(16) __nv_bfloat16 g_WdS[9*2*256*64];
__device__ float g_Wxf[256*9];

// ---------------- PTX helpers ----------------
__device__ __forceinline__ uint32_t smem_u32(const void* p) {
    uint32_t a;
    asm("{ .reg .u64 t; cvta.to.shared.u64 t, %1; cvt.u32.u64 %0, t; }" : "=r"(a) : "l"(p));
    return a;
}
__device__ __forceinline__ void cp16_s(uint32_t sdst, const void* g) {
    asm volatile("cp.async.cg.shared.global [%0], [%1], 16;" :: "r"(sdst), "l"(g));
}
__device__ __forceinline__ void ldsm4(uint32_t* r, uint32_t addr) {
    asm volatile("ldmatrix.sync.aligned.m8n8.x4.shared.b16 {%0,%1,%2,%3}, [%4];"
        : "=r"(r[0]), "=r"(r[1]), "=r"(r[2]), "=r"(r[3]) : "r"(addr));
}
__device__ __forceinline__ void ldsm2(uint32_t* r, uint32_t addr) {
    asm volatile("ldmatrix.sync.aligned.m8n8.x2.shared.b16 {%0,%1}, [%2];"
        : "=r"(r[0]), "=r"(r[1]) : "r"(addr));
}
__device__ __forceinline__ void mma16816(float* d, const uint32_t* a, const uint32_t* b) {
    asm volatile("mma.sync.aligned.m16n8k16.row.col.f32.bf16.bf16.f32 "
        "{%0,%1,%2,%3}, {%4,%5,%6,%7}, {%8,%9}, {%0,%1,%2,%3};"
        : "+f"(d[0]), "+f"(d[1]), "+f"(d[2]), "+f"(d[3])
        : "r"(a[0]), "r"(a[1]), "r"(a[2]), "r"(a[3]), "r"(b[0]), "r"(b[1]));
}
__device__ __forceinline__ float sigmoidf_(float x) { return 1.f / (1.f + __expf(-x)); }
__device__ __forceinline__ float tanhf_(float x) {
    float e = __expf(2.f * x);
    return (e - 1.f) * __frcp_rn(e + 1.f);
}

// ---------------- prep kernels ----------------
__global__ void zero_buf(float* __restrict__ p, int n) {
    for (int i = blockIdx.x * blockDim.x + threadIdx.x; i < n; i += gridDim.x * blockDim.x)
        p[i] = 0.f;
}
__global__ void prep_wh(const float* __restrict__ W, __nv_bfloat16* __restrict__ dst,
                        int CIN, int off1, int off2) {
    int idx = blockIdx.x * blockDim.x + threadIdx.x;
    if (idx >= 9 * 256 * 64) return;
    int ch = idx & 63, oc = (idx >> 6) & 255, tap = idx >> 14;
    float w = W[((size_t)oc * CIN + off1 + ch) * 9 + tap];
    if (off2 >= 0) w += W[((size_t)oc * CIN + off2 + ch) * 9 + tap];
    __nv_bfloat16 hi = __float2bfloat16(w);
    __nv_bfloat16 lo = __float2bfloat16(w - __bfloat162float(hi));
    dst[(((size_t)tap * 2 + 0) * 256 + oc) * 64 + ch] = hi;
    dst[(((size_t)tap * 2 + 1) * 256 + oc) * 64 + ch] = lo;
}
__global__ void prep_wxf(const float* __restrict__ W, float* __restrict__ dst) {
    int i = blockIdx.x * blockDim.x + threadIdx.x;
    if (i >= 2304) return;
    int oc = i / 9, tap = i % 9;
    dst[i] = W[(size_t)oc * 65 * 9 + tap];
}

// ---------------- ConvLSTM step: bf16 mma.sync implicit GEMM ----------------
// grid 1024 = 32 b x 32 y-pairs (2 rows); 512 threads (16 warps: 4 M x 4 N)
__global__ void __launch_bounds__(512, 1)
conv_step(const __nv_bfloat16* __restrict__ hi_in, const __nv_bfloat16* __restrict__ lo_in,
          __nv_bfloat16* __restrict__ hi_out, __nv_bfloat16* __restrict__ lo_out,
          float* __restrict__ c,
          const __nv_bfloat16* __restrict__ Wm,
          const float* __restrict__ x, int t,
          const float* __restrict__ bias, int has_mma, int has_x) {
    extern __shared__ __align__(16) unsigned char smem[];
    const uint32_t sb = smem_u32(smem);
    const int tid = threadIdx.x, wid = tid >> 5, lane = tid & 31;
    const int b = blockIdx.x >> 5, yg = blockIdx.x & 31, y0 = yg * 2;

    // ---- prologue staging ----
    if (has_x) {
        if (tid < 264) {
            int r = tid / 66, cc = tid % 66;
            int gy = y0 + r - 1, gx = cc - 1;
            float v = 0.f;
            if ((unsigned)gy < 64u && (unsigned)gx < 64u)
                v = x[((size_t)b * TT + t) * 4096 + gy * 64 + gx];
            ((float*)(smem + O_XS))[tid] = v;
        }
#pragma unroll
        for (int j = 0; j < 5; j++) {
            int idx = tid + j * 512;
            if (idx < 2304) ((float*)(smem + O_WX))[idx] = g_Wxf[idx];
        }
    }

    auto stage_w = [&](uint32_t dstoff, int ci) {
        const char* src = (const char*)(Wm + (size_t)ci * 16384);
#pragma unroll
        for (int j = 0; j < 4; j++) {
            int idx = tid + j * 512;            // 0..2047
            int oc = idx >> 3, seg = idx & 7;
            cp16_s(sb + dstoff + oc * 144 + seg * 16, src + oc * 128 + seg * 16);
        }
    };

    if (has_mma) {
        const char* hbase = (const char*)(hi_in + ((size_t)b * PPX + (size_t)y0 * PHW) * 64);
        const char* lbase = (const char*)(lo_in + ((size_t)b * PPX + (size_t)y0 * PHW) * 64);
#pragma unroll
        for (int j = 0; j < 5; j++) {
            int idx = tid + j * 512;
            if (idx < 2112) {                    // 264 px * 8 segs
                int p = idx >> 3, seg = idx & 7;
                cp16_s(sb + O_INH + p * 144 + seg * 16, hbase + p * 128 + seg * 16);
                cp16_s(sb + O_INL + p * 144 + seg * 16, lbase + p * 128 + seg * 16);
            }
        }
        stage_w(O_WB0, 0);
        asm volatile("cp.async.commit_group;" ::: "memory");
        stage_w(O_WB1, 1);
        asm volatile("cp.async.commit_group;" ::: "memory");
    }

    // ---- fragment geometry ----
    const int mw = wid & 3;                  // gate block (64 oc)
    const int nw = wid >> 2;                 // px quarter (32 px)
    const uint32_t a_row = mw * 64 + (lane & 15);
    const uint32_t a_kh = ((lane >> 4) << 3);
    const int bk = ((lane >> 3) & 1) << 3;
    // per-nf B pixel row/col (lane&7 is the px within the 8-run)
    int prow[4], pcol[4];
#pragma unroll
    for (int nf = 0; nf < 4; nf++) {
        int p = nw * 32 + nf * 8 + (lane & 7);
        prow[nf] = p >> 6;
        pcol[nf] = p & 63;
    }

    float acc[4][4][4];
#pragma unroll
    for (int i = 0; i < 4; i++)
#pragma unroll
        for (int j = 0; j < 4; j++)
#pragma unroll
            for (int k = 0; k < 4; k++) acc[i][j][k] = 0.f;

    if (has_mma) {
        for (int ci = 0; ci < 18; ci++) {
            if (ci < 17) asm volatile("cp.async.wait_group 1;" ::: "memory");
            else         asm volatile("cp.async.wait_group 0;" ::: "memory");
            __syncthreads();

            const uint32_t wb = sb + ((ci & 1) ? O_WB1 : O_WB0);
            const int tap = ci >> 1, comp = ci & 1;
            const int dy = tap / 3, dx = tap % 3;
            const int npass = comp ? 1 : 2;
            uint32_t boff[4];
#pragma unroll
            for (int nf = 0; nf < 4; nf++)
                boff[nf] = (uint32_t)(((prow[nf] + dy) * 66 + pcol[nf] + dx) * 144 + bk * 2);

#pragma unroll
            for (int ks = 0; ks < 4; ks++) {
                const int k0 = ks * 16;
                uint32_t af[4][4];
#pragma unroll
                for (int mf = 0; mf < 4; mf++)
                    ldsm4(af[mf], wb + (a_row + mf * 16) * 144 + (k0 + a_kh) * 2);
                for (int pp = 0; pp < npass; pp++) {
                    const uint32_t slab = sb + (pp ? O_INL : O_INH);
                    uint32_t bf[4][2];
#pragma unroll
                    for (int nf = 0; nf < 4; nf++)
                        ldsm2(bf[nf], slab + boff[nf] + k0 * 2);
#pragma unroll
                    for (int mf = 0; mf < 4; mf++)
#pragma unroll
                        for (int nf = 0; nf < 4; nf++)
                            mma16816(acc[mf][nf], af[mf], bf[nf]);
                }
            }
            __syncthreads();
            if (ci + 2 < 18) {
                stage_w((ci & 1) ? O_WB1 : O_WB0, ci + 2);
                asm volatile("cp.async.commit_group;" ::: "memory");
            }
        }
    }
    __syncthreads();

    // ---- store gate fragments to smem overlay [gate][128px][64ch] fp32 ----
    float* sg = (float*)smem;
    if (has_mma) {
        const int g = lane >> 2, tp = lane & 3;
#pragma unroll
        for (int mf = 0; mf < 4; mf++)
#pragma unroll
            for (int nf = 0; nf < 4; nf++) {
                int ch0 = mf * 16 + g;
                int px0 = nw * 32 + nf * 8 + tp * 2;
                float* p = sg + mw * 8192 + px0 * 64 + ch0;
                p[0]      = acc[mf][nf][0];
                p[64]     = acc[mf][nf][1];
                p[8]      = acc[mf][nf][2];
                p[64 + 8] = acc[mf][nf][3];
            }
    }
    __syncthreads();

    // ---- LSTM pointwise epilogue: 128 px x 64 ch over 512 threads ----
    const int ch = tid & 63;
    const int pxb = (tid >> 6) * 16;        // 8 segments x 16 px
    const float bi = __ldg(bias + ch);
    const float bf_ = __ldg(bias + 64 + ch);
    const float bo = __ldg(bias + 128 + ch);
    const float bg = __ldg(bias + 192 + ch);

    float wxr[36];
    if (has_x) {
        const float* sWx = (const float*)(smem + O_WX);
#pragma unroll
        for (int g4 = 0; g4 < 4; g4++)
#pragma unroll
            for (int tp = 0; tp < 9; tp++)
                wxr[g4 * 9 + tp] = sWx[(g4 * 64 + ch) * 9 + tp];
    }
    const float* sx = (const float*)(smem + O_XS);

#pragma unroll 4
    for (int k = 0; k < 16; k++) {
        const int px = pxb + k;
        const int pr = px >> 6, pc = px & 63;
        float vi = bi, vf = bf_, vo = bo, vg = bg;
        if (has_mma) {
            vi += sg[px * 64 + ch];
            vf += sg[8192 + px * 64 + ch];
            vo += sg[16384 + px * 64 + ch];
            vg += sg[24576 + px * 64 + ch];
        }
        if (has_x) {
            float xs[9];
#pragma unroll
            for (int tp = 0; tp < 9; tp++)
                xs[tp] = sx[(pr + tp / 3) * 66 + (tp % 3) + pc];
            float s0 = 0, s1 = 0, s2 = 0, s3 = 0;
#pragma unroll
            for (int tp = 0; tp < 9; tp++) {
                s0 += wxr[tp] * xs[tp];
                s1 += wxr[9 + tp] * xs[tp];
                s2 += wxr[18 + tp] * xs[tp];
                s3 += wxr[27 + tp] * xs[tp];
            }
            vi += s0; vf += s1; vo += s2; vg += s3;
        }
        const int y = y0 + pr;
        const size_t coff = (((size_t)b * 64 + y) * 64 + pc) * 64 + ch;
        float cn = sigmoidf_(vf) * c[coff] + sigmoidf_(vi) * tanhf_(vg);
        c[coff] = cn;
        float hv = sigmoidf_(vo) * tanhf_(cn);
        __nv_bfloat16 hhi = __float2bfloat16(hv);
        __nv_bfloat16 hlo = __float2bfloat16(hv - __bfloat162float(hhi));
        const size_t hoff = ((size_t)b * PPX + (size_t)(y + 1) * PHW + (pc + 1)) * 64 + ch;
        hi_out[hoff] = hhi;
        lo_out[hoff] = hlo;
    }
}

// ---------------- encoder-vector: padded NHWC hi/lo -> NCHW fp32 ----------------
__global__ void ev_out(const __nv_bfloat16* __restrict__ hi, const __nv_bfloat16* __restrict__ lo,
                       float* __restrict__ outv) {
    __shared__ float s[64][65];
    int b = blockIdx.x >> 6, y = blockIdx.x & 63;
    int tid = threadIdx.x;
#pragma unroll
    for (int i = 0; i < 16; i++) {
        int xx = (tid >> 6) + i * 4, ch = tid & 63;
        size_t off = (((size_t)b * PPX) + (size_t)(y + 1) * PHW + (xx + 1)) * 64 + ch;
        s[xx][ch] = __bfloat162float(hi[off]) + __bfloat162float(lo[off]);
    }
    __syncthreads();
#pragma unroll
    for (int i = 0; i < 16; i++) {
        int xx = tid & 63, ch = (tid >> 6) + i * 4;
        outv[((size_t)b * 64 + ch) * 4096 + y * 64 + xx] = s[xx][ch];
    }
}

// ---------------- 3D CNN head from padded NHWC hi/lo ----------------
__global__ void cnn_head(const __nv_bfloat16* __restrict__ hi, const __nv_bfloat16* __restrict__ lo,
                         const float* __restrict__ Wc, const float* __restrict__ bc,
                         float* __restrict__ out, int t) {
    __shared__ float s_w[9 * 64];
    int b = blockIdx.x >> 4, yg = blockIdx.x & 15, y0 = yg * 4;
    int tid = threadIdx.x;
    for (int i = tid; i < 576; i += 256) {
        int ch = i / 9, tap = i % 9;
        s_w[tap * 64 + ch] = Wc[i];
    }
    __syncthreads();
    int r = tid >> 6, xx = tid & 63, iy = y0 + r;
    float acc = bc[0];
#pragma unroll
    for (int ky = 0; ky < 3; ky++)
#pragma unroll
        for (int kx = 0; kx < 3; kx++) {
            size_t base = (((size_t)b * PPX) + (size_t)(iy + ky) * PHW + (xx + kx)) * 64;
            const float* wrow = s_w + (ky * 3 + kx) * 64;
            float s = 0.f;
            for (int ch = 0; ch < 64; ch++)
                s += wrow[ch] * (__bfloat162float(hi[base + ch]) + __bfloat162float(lo[base + ch]));
            acc += s;
        }
    out[((size_t)b * TT + t) * 4096 + iy * 64 + xx] = acc;
}

// ---------------- launch ----------------
extern "C" void kernel_launch(void* const* d_in, const int* in_sizes, int n_in,
                              void* d_out, int out_size) {
    const float* x     = (const float*)d_in[0];
    const float* W_enc = (const float*)d_in[2];
    const float* b_enc = (const float*)d_in[3];
    const float* W_dec = (const float*)d_in[4];
    const float* b_dec = (const float*)d_in[5];
    const float* W_cnn = (const float*)d_in[6];
    const float* b_cnn = (const float*)d_in[7];
    float* out = (float*)d_out;

    float *c, *wxf;
    __nv_bfloat16 *ahi, *alo, *bhi, *blo, *whe, *wdx, *wds;
    cudaGetSymbolAddress((void**)&c, g_c);
    cudaGetSymbolAddress((void**)&ahi, g_nhA_hi);
    cudaGetSymbolAddress((void**)&alo, g_nhA_lo);
    cudaGetSymbolAddress((void**)&bhi, g_nhB_hi);
    cudaGetSymbolAddress((void**)&blo, g_nhB_lo);
    cudaGetSymbolAddress((void**)&whe, g_WhE);
    cudaGetSymbolAddress((void**)&wdx, g_WdX);
    cudaGetSymbolAddress((void**)&wds, g_WdS);
    cudaGetSymbolAddress((void**)&wxf, g_Wxf);

    cudaFuncSetAttribute(conv_step, cudaFuncAttributeMaxDynamicSharedMemorySize, SMEM_BYTES);

    zero_buf<<<2048, 256>>>(c, STATE_ELEMS);
    zero_buf<<<2048, 256>>>((float*)ahi, BB * PPX * NF / 2);
    zero_buf<<<2048, 256>>>((float*)alo, BB * PPX * NF / 2);
    zero_buf<<<2048, 256>>>((float*)bhi, BB * PPX * NF / 2);
    zero_buf<<<2048, 256>>>((float*)blo, BB * PPX * NF / 2);

    prep_wh<<<576, 256>>>(W_enc, whe, 65, 1, -1);
    prep_wh<<<576, 256>>>(W_dec, wdx, 128, 0, -1);
    prep_wh<<<576, 256>>>(W_dec, wds, 128, 0, 64);
    prep_wxf<<<9, 256>>>(W_enc, wxf);

    __nv_bfloat16 *curhi = ahi, *curlo = alo, *othhi = bhi, *othlo = blo;

    // ---- encoder ----
    for (int t = 0; t < TT; t++) {
        conv_step<<<1024, 512, SMEM_BYTES>>>(curhi, curlo, othhi, othlo, c,
                                             whe, x, t, b_enc, t > 0, 1);
        __nv_bfloat16* tp;
        tp = curhi; curhi = othhi; othhi = tp;
        tp = curlo; curlo = othlo; othlo = tp;
    }

    ev_out<<<BB * 64, 256>>>(curhi, curlo, out + Y_ELEMS);
    zero_buf<<<2048, 256>>>(c, STATE_ELEMS);

    // ---- decoder ----
    for (int t = 0; t < TT; t++) {
        const __nv_bfloat16* W = (t == 0) ? wdx : wds;
        conv_step<<<1024, 512, SMEM_BYTES>>>(curhi, curlo, othhi, othlo, c,
                                             W, x, t, b_dec, 1, 0);
        cnn_head<<<512, 256>>>(othhi, othlo, W_cnn, b_cnn, out, t);
        __nv_bfloat16* tp;
        tp = curhi; curhi = othhi; othhi = tp;
        tp = curlo; curlo = othlo; othlo = tp;
    }
}

// round 11
// speedup vs baseline: 6.2395x; 1.5917x over previous
#include <cuda_runtime.h>
#include <cuda_bf16.h>
#include <math.h>
#include <stdint.h>

// ---------------- constants ----------------
#define HW 64
#define NF 64
#define BB 32
#define TT 12
#define PHW 66
#define PPX (PHW*PHW)                 // 4356
#define STATE_ELEMS (BB*NF*HW*HW)     // 8,388,608
#define Y_ELEMS (BB*TT*HW*HW)         // 1,572,864

// ---------------- smem layout (bytes) ----------------
#define O_INH 0                       // input slab hi: 264 px * 144B (4 rows x 66)
#define O_INL 38016                   // input slab lo
#define O_WB  76032                   // 3 weight bufs: 256 oc * 144B each
#define WBSZ  36864
#define O_XS  186624                  // x slab: 264 fp32
#define O_WX  187680                  // Wx: 2304 fp32
#define O_HW  196896                  // head weights: 576 fp32
#define SMEM_BYTES 199232
// epilogue overlays gates fp32 [4][128px][64ch] = 131072B at offset 0

// ---------------- device globals ----------------
__device__ float g_c[STATE_ELEMS];
__device__ __align__(16) __nv_bfloat16 g_nhA_hi[BB*PPX*NF];
__device__ __align__(16) __nv_bfloat16 g_nhA_lo[BB*PPX*NF];
__device__ __align__(16) __nv_bfloat16 g_nhB_hi[BB*PPX*NF];
__device__ __align__(16) __nv_bfloat16 g_nhB_lo[BB*PPX*NF];
__device__ __align__(16) __nv_bfloat16 g_WhE[9*2*256*64];  // [tap][hi/lo][oc][ch]
__device__ __align__(16) __nv_bfloat16 g_WdX[9*2*256*64];
__device__ __align__(16) __nv_bfloat16 g_WdS[9*2*256*64];
__device__ float g_Wxf[256*9];

// ---------------- PTX helpers ----------------
__device__ __forceinline__ uint32_t smem_u32(const void* p) {
    uint32_t a;
    asm("{ .reg .u64 t; cvta.to.shared.u64 t, %1; cvt.u32.u64 %0, t; }" : "=r"(a) : "l"(p));
    return a;
}
__device__ __forceinline__ void cp16_s(uint32_t sdst, const void* g) {
    asm volatile("cp.async.cg.shared.global [%0], [%1], 16;" :: "r"(sdst), "l"(g));
}
__device__ __forceinline__ void ldsm4(uint32_t* r, uint32_t addr) {
    asm volatile("ldmatrix.sync.aligned.m8n8.x4.shared.b16 {%0,%1,%2,%3}, [%4];"
        : "=r"(r[0]), "=r"(r[1]), "=r"(r[2]), "=r"(r[3]) : "r"(addr));
}
__device__ __forceinline__ void mma16816(float* d, const uint32_t* a, const uint32_t* b) {
    asm volatile("mma.sync.aligned.m16n8k16.row.col.f32.bf16.bf16.f32 "
        "{%0,%1,%2,%3}, {%4,%5,%6,%7}, {%8,%9}, {%0,%1,%2,%3};"
        : "+f"(d[0]), "+f"(d[1]), "+f"(d[2]), "+f"(d[3])
        : "r"(a[0]), "r"(a[1]), "r"(a[2]), "r"(a[3]), "r"(b[0]), "r"(b[1]));
}
__device__ __forceinline__ float sigmoidf_(float x) { return 1.f / (1.f + __expf(-x)); }
__device__ __forceinline__ float tanhf_(float x) {
    float e = __expf(2.f * x);
    return (e - 1.f) * __frcp_rn(e + 1.f);
}

// ---------------- prep kernels ----------------
__global__ void zero_buf(float* __restrict__ p, int n) {
    for (int i = blockIdx.x * blockDim.x + threadIdx.x; i < n; i += gridDim.x * blockDim.x)
        p[i] = 0.f;
}
__global__ void prep_wh(const float* __restrict__ W, __nv_bfloat16* __restrict__ dst,
                        int CIN, int off1, int off2) {
    int idx = blockIdx.x * blockDim.x + threadIdx.x;
    if (idx >= 9 * 256 * 64) return;
    int ch = idx & 63, oc = (idx >> 6) & 255, tap = idx >> 14;
    float w = W[((size_t)oc * CIN + off1 + ch) * 9 + tap];
    if (off2 >= 0) w += W[((size_t)oc * CIN + off2 + ch) * 9 + tap];
    __nv_bfloat16 hi = __float2bfloat16(w);
    __nv_bfloat16 lo = __float2bfloat16(w - __bfloat162float(hi));
    dst[(((size_t)tap * 2 + 0) * 256 + oc) * 64 + ch] = hi;
    dst[(((size_t)tap * 2 + 1) * 256 + oc) * 64 + ch] = lo;
}
__global__ void prep_wxf(const float* __restrict__ W, float* __restrict__ dst) {
    int i = blockIdx.x * blockDim.x + threadIdx.x;
    if (i >= 2304) return;
    int oc = i / 9, tap = i % 9;
    dst[i] = W[(size_t)oc * 65 * 9 + tap];
}

// ---------------- ConvLSTM step: bf16 mma.sync implicit GEMM ----------------
// grid 1024 = 32 b x 32 y-pairs (2 rows); 512 threads (16 warps: 4 M x 4 N)
// do_head: also compute 3D-CNN head output for step tout from the loaded h slab.
__global__ void __launch_bounds__(512, 1)
conv_step(const __nv_bfloat16* __restrict__ hi_in, const __nv_bfloat16* __restrict__ lo_in,
          __nv_bfloat16* __restrict__ hi_out, __nv_bfloat16* __restrict__ lo_out,
          float* __restrict__ c,
          const __nv_bfloat16* __restrict__ Wm,
          const float* __restrict__ x, int t,
          const float* __restrict__ bias, int has_mma, int has_x,
          int do_head, int tout,
          const float* __restrict__ Wc, const float* __restrict__ bc,
          float* __restrict__ yout) {
    extern __shared__ __align__(16) unsigned char smem[];
    const uint32_t sb = smem_u32(smem);
    const int tid = threadIdx.x, wid = tid >> 5, lane = tid & 31;
    const int b = blockIdx.x >> 5, yg = blockIdx.x & 31, y0 = yg * 2;

    // ---- prologue staging ----
    if (has_x) {
        if (tid < 264) {
            int r = tid / 66, cc = tid % 66;
            int gy = y0 + r - 1, gx = cc - 1;
            float v = 0.f;
            if ((unsigned)gy < 64u && (unsigned)gx < 64u)
                v = x[((size_t)b * TT + t) * 4096 + gy * 64 + gx];
            ((float*)(smem + O_XS))[tid] = v;
        }
#pragma unroll
        for (int j = 0; j < 5; j++) {
            int idx = tid + j * 512;
            if (idx < 2304) ((float*)(smem + O_WX))[idx] = g_Wxf[idx];
        }
    }
    if (do_head) {
        // 576 elements over 512 threads: strided loop (R10 bug was `if (tid<576)`)
        for (int i = tid; i < 576; i += 512) {
            int tap = i >> 6, ch = i & 63;
            ((float*)(smem + O_HW))[i] = Wc[ch * 9 + tap];
        }
    }

    auto stage_w = [&](int ci) {
        uint32_t dstoff = O_WB + (uint32_t)(ci % 3) * WBSZ;
        const char* src = (const char*)(Wm + (size_t)ci * 16384);
#pragma unroll
        for (int j = 0; j < 4; j++) {
            int idx = tid + j * 512;            // 0..2047
            int oc = idx >> 3, seg = idx & 7;
            cp16_s(sb + dstoff + oc * 144 + seg * 16, src + oc * 128 + seg * 16);
        }
        asm volatile("cp.async.commit_group;" ::: "memory");
    };

    if (has_mma) {
        const char* hbase = (const char*)(hi_in + ((size_t)b * PPX + (size_t)y0 * PHW) * 64);
        const char* lbase = (const char*)(lo_in + ((size_t)b * PPX + (size_t)y0 * PHW) * 64);
#pragma unroll
        for (int j = 0; j < 5; j++) {
            int idx = tid + j * 512;
            if (idx < 2112) {                    // 264 px * 8 segs
                int p = idx >> 3, seg = idx & 7;
                cp16_s(sb + O_INH + p * 144 + seg * 16, hbase + p * 128 + seg * 16);
                cp16_s(sb + O_INL + p * 144 + seg * 16, lbase + p * 128 + seg * 16);
            }
        }
        // group0 = slabs + chunk0; group1 = chunk1
        {
            uint32_t dstoff = O_WB;
            const char* src = (const char*)Wm;
#pragma unroll
            for (int j = 0; j < 4; j++) {
                int idx = tid + j * 512;
                int oc = idx >> 3, seg = idx & 7;
                cp16_s(sb + dstoff + oc * 144 + seg * 16, src + oc * 128 + seg * 16);
            }
            asm volatile("cp.async.commit_group;" ::: "memory");
        }
        stage_w(1);
    }

    // ---- fragment geometry ----
    const int mw = wid & 3;                  // gate block (64 oc)
    const int nw = wid >> 2;                 // px quarter (32 px)
    const uint32_t a_row = mw * 64 + (lane & 15);
    const uint32_t a_kh = ((lane >> 4) << 3);
    const int nfsel = lane >> 4;             // which nf of the pair this lane addresses
    const int khalf = (lane >> 3) & 1;
    int prow[4], pcol[4];
#pragma unroll
    for (int nf = 0; nf < 4; nf++) {
        int p = nw * 32 + nf * 8 + (lane & 7);
        prow[nf] = p >> 6;
        pcol[nf] = p & 63;
    }

    float acc[4][4][4];
#pragma unroll
    for (int i = 0; i < 4; i++)
#pragma unroll
        for (int j = 0; j < 4; j++)
#pragma unroll
            for (int k = 0; k < 4; k++) acc[i][j][k] = 0.f;

    if (has_mma) {
        for (int ci = 0; ci < 18; ci++) {
            if (ci < 17) asm volatile("cp.async.wait_group 1;" ::: "memory");
            else         asm volatile("cp.async.wait_group 0;" ::: "memory");
            __syncthreads();

            // ---- fused CNN head (slab is resident; runs once) ----
            if (ci == 0 && do_head && tid < 128) {
                const int pr = tid >> 6, pc = tid & 63;
                float hacc = __ldg(bc);
#pragma unroll
                for (int ky = 0; ky < 3; ky++)
#pragma unroll
                    for (int kx = 0; kx < 3; kx++) {
                        const uint32_t base = (uint32_t)(((pr + ky) * 66 + pc + kx) * 144);
                        const float* wr = (const float*)(smem + O_HW) + (ky * 3 + kx) * 64;
#pragma unroll 4
                        for (int ch = 0; ch < 64; ch += 4) {
                            uint2 h2 = *(const uint2*)(smem + O_INH + base + ch * 2);
                            uint2 l2 = *(const uint2*)(smem + O_INL + base + ch * 2);
                            __nv_bfloat162 ha = *(__nv_bfloat162*)&h2.x;
                            __nv_bfloat162 hb = *(__nv_bfloat162*)&h2.y;
                            __nv_bfloat162 la = *(__nv_bfloat162*)&l2.x;
                            __nv_bfloat162 lb = *(__nv_bfloat162*)&l2.y;
                            hacc += wr[ch+0] * (__bfloat162float(ha.x) + __bfloat162float(la.x));
                            hacc += wr[ch+1] * (__bfloat162float(ha.y) + __bfloat162float(la.y));
                            hacc += wr[ch+2] * (__bfloat162float(hb.x) + __bfloat162float(lb.x));
                            hacc += wr[ch+3] * (__bfloat162float(hb.y) + __bfloat162float(lb.y));
                        }
                    }
                yout[((size_t)b * TT + tout) * 4096 + (y0 + pr) * 64 + pc] = hacc;
            }

            if (ci + 2 < 18) stage_w(ci + 2);

            const uint32_t wb = sb + O_WB + (uint32_t)(ci % 3) * WBSZ;
            const int tap = ci >> 1, comp = ci & 1;
            const int dy = tap / 3, dx = tap % 3;
            const int npass = comp ? 1 : 2;
            // per-lane B ldsm4 offsets for nf pairs {0,1} and {2,3}
            uint32_t bco[2];
#pragma unroll
            for (int j = 0; j < 2; j++) {
                int nf = j * 2 + nfsel;
                bco[j] = (uint32_t)(((prow[nf] + dy) * 66 + pcol[nf] + dx) * 144 + khalf * 16);
            }

#pragma unroll
            for (int ks = 0; ks < 4; ks++) {
                const int k0 = ks * 16;
                uint32_t af[4][4];
#pragma unroll
                for (int mf = 0; mf < 4; mf++)
                    ldsm4(af[mf], wb + (a_row + mf * 16) * 144 + (k0 + a_kh) * 2);
                for (int pp = 0; pp < npass; pp++) {
                    const uint32_t slab = sb + (pp ? O_INL : O_INH);
                    uint32_t bf4[2][4];
                    ldsm4(bf4[0], slab + bco[0] + k0 * 2);
                    ldsm4(bf4[1], slab + bco[1] + k0 * 2);
#pragma unroll
                    for (int mf = 0; mf < 4; mf++)
#pragma unroll
                        for (int nf = 0; nf < 4; nf++)
                            mma16816(acc[mf][nf], af[mf], &bf4[nf >> 1][(nf & 1) * 2]);
                }
            }
        }
    }
    __syncthreads();

    // ---- store gate fragments to smem overlay [gate][128px][64ch] fp32 ----
    float* sg = (float*)smem;
    if (has_mma) {
        const int g = lane >> 2, tp = lane & 3;
#pragma unroll
        for (int mf = 0; mf < 4; mf++)
#pragma unroll
            for (int nf = 0; nf < 4; nf++) {
                int ch0 = mf * 16 + g;
                int px0 = nw * 32 + nf * 8 + tp * 2;
                float* p = sg + mw * 8192 + px0 * 64 + ch0;
                p[0]      = acc[mf][nf][0];
                p[64]     = acc[mf][nf][1];
                p[8]      = acc[mf][nf][2];
                p[64 + 8] = acc[mf][nf][3];
            }
    }
    __syncthreads();

    // ---- LSTM pointwise epilogue: 128 px x 64 ch over 512 threads ----
    const int ch = tid & 63;
    const int pxb = (tid >> 6) * 16;
    const float bi = __ldg(bias + ch);
    const float bf_ = __ldg(bias + 64 + ch);
    const float bo = __ldg(bias + 128 + ch);
    const float bg = __ldg(bias + 192 + ch);

    float wxr[36];
    if (has_x) {
        const float* sWx = (const float*)(smem + O_WX);
#pragma unroll
        for (int g4 = 0; g4 < 4; g4++)
#pragma unroll
            for (int tp = 0; tp < 9; tp++)
                wxr[g4 * 9 + tp] = sWx[(g4 * 64 + ch) * 9 + tp];
    }
    const float* sx = (const float*)(smem + O_XS);

#pragma unroll 4
    for (int k = 0; k < 16; k++) {
        const int px = pxb + k;
        const int pr = px >> 6, pc = px & 63;
        float vi = bi, vf = bf_, vo = bo, vg = bg;
        if (has_mma) {
            vi += sg[px * 64 + ch];
            vf += sg[8192 + px * 64 + ch];
            vo += sg[16384 + px * 64 + ch];
            vg += sg[24576 + px * 64 + ch];
        }
        if (has_x) {
            float xs[9];
#pragma unroll
            for (int tp = 0; tp < 9; tp++)
                xs[tp] = sx[(pr + tp / 3) * 66 + (tp % 3) + pc];
            float s0 = 0, s1 = 0, s2 = 0, s3 = 0;
#pragma unroll
            for (int tp = 0; tp < 9; tp++) {
                s0 += wxr[tp] * xs[tp];
                s1 += wxr[9 + tp] * xs[tp];
                s2 += wxr[18 + tp] * xs[tp];
                s3 += wxr[27 + tp] * xs[tp];
            }
            vi += s0; vf += s1; vo += s2; vg += s3;
        }
        const int y = y0 + pr;
        const size_t coff = (((size_t)b * 64 + y) * 64 + pc) * 64 + ch;
        float cn = sigmoidf_(vf) * c[coff] + sigmoidf_(vi) * tanhf_(vg);
        c[coff] = cn;
        float hv = sigmoidf_(vo) * tanhf_(cn);
        __nv_bfloat16 hhi = __float2bfloat16(hv);
        __nv_bfloat16 hlo = __float2bfloat16(hv - __bfloat162float(hhi));
        const size_t hoff = ((size_t)b * PPX + (size_t)(y + 1) * PHW + (pc + 1)) * 64 + ch;
        hi_out[hoff] = hhi;
        lo_out[hoff] = hlo;
    }
}

// ---------------- encoder-vector: padded NHWC hi/lo -> NCHW fp32 ----------------
__global__ void ev_out(const __nv_bfloat16* __restrict__ hi, const __nv_bfloat16* __restrict__ lo,
                       float* __restrict__ outv) {
    __shared__ float s[64][65];
    int b = blockIdx.x >> 6, y = blockIdx.x & 63;
    int tid = threadIdx.x;
#pragma unroll
    for (int i = 0; i < 16; i++) {
        int xx = (tid >> 6) + i * 4, ch = tid & 63;
        size_t off = (((size_t)b * PPX) + (size_t)(y + 1) * PHW + (xx + 1)) * 64 + ch;
        s[xx][ch] = __bfloat162float(hi[off]) + __bfloat162float(lo[off]);
    }
    __syncthreads();
#pragma unroll
    for (int i = 0; i < 16; i++) {
        int xx = tid & 63, ch = (tid >> 6) + i * 4;
        outv[((size_t)b * 64 + ch) * 4096 + y * 64 + xx] = s[xx][ch];
    }
}

// ---------------- standalone 3D CNN head (final decoder step only) ----------------
__global__ void cnn_head(const __nv_bfloat16* __restrict__ hi, const __nv_bfloat16* __restrict__ lo,
                         const float* __restrict__ Wc, const float* __restrict__ bc,
                         float* __restrict__ out, int t) {
    __shared__ float s_w[9 * 64];
    int b = blockIdx.x >> 4, yg = blockIdx.x & 15, y0 = yg * 4;
    int tid = threadIdx.x;
    for (int i = tid; i < 576; i += 256) {
        int ch = i / 9, tap = i % 9;
        s_w[tap * 64 + ch] = Wc[i];
    }
    __syncthreads();
    int r = tid >> 6, xx = tid & 63, iy = y0 + r;
    float acc = bc[0];
#pragma unroll
    for (int ky = 0; ky < 3; ky++)
#pragma unroll
        for (int kx = 0; kx < 3; kx++) {
            size_t base = (((size_t)b * PPX) + (size_t)(iy + ky) * PHW + (xx + kx)) * 64;
            const float* wrow = s_w + (ky * 3 + kx) * 64;
            float s = 0.f;
            for (int ch = 0; ch < 64; ch++)
                s += wrow[ch] * (__bfloat162float(hi[base + ch]) + __bfloat162float(lo[base + ch]));
            acc += s;
        }
    out[((size_t)b * TT + t) * 4096 + iy * 64 + xx] = acc;
}

// ---------------- launch ----------------
extern "C" void kernel_launch(void* const* d_in, const int* in_sizes, int n_in,
                              void* d_out, int out_size) {
    const float* x     = (const float*)d_in[0];
    const float* W_enc = (const float*)d_in[2];
    const float* b_enc = (const float*)d_in[3];
    const float* W_dec = (const float*)d_in[4];
    const float* b_dec = (const float*)d_in[5];
    const float* W_cnn = (const float*)d_in[6];
    const float* b_cnn = (const float*)d_in[7];
    float* out = (float*)d_out;

    float *c, *wxf;
    __nv_bfloat16 *ahi, *alo, *bhi, *blo, *whe, *wdx, *wds;
    cudaGetSymbolAddress((void**)&c, g_c);
    cudaGetSymbolAddress((void**)&ahi, g_nhA_hi);
    cudaGetSymbolAddress((void**)&alo, g_nhA_lo);
    cudaGetSymbolAddress((void**)&bhi, g_nhB_hi);
    cudaGetSymbolAddress((void**)&blo, g_nhB_lo);
    cudaGetSymbolAddress((void**)&whe, g_WhE);
    cudaGetSymbolAddress((void**)&wdx, g_WdX);
    cudaGetSymbolAddress((void**)&wds, g_WdS);
    cudaGetSymbolAddress((void**)&wxf, g_Wxf);

    cudaFuncSetAttribute(conv_step, cudaFuncAttributeMaxDynamicSharedMemorySize, SMEM_BYTES);

    zero_buf<<<2048, 256>>>(c, STATE_ELEMS);
    zero_buf<<<2048, 256>>>((float*)ahi, BB * PPX * NF / 2);
    zero_buf<<<2048, 256>>>((float*)alo, BB * PPX * NF / 2);
    zero_buf<<<2048, 256>>>((float*)bhi, BB * PPX * NF / 2);
    zero_buf<<<2048, 256>>>((float*)blo, BB * PPX * NF / 2);

    prep_wh<<<576, 256>>>(W_enc, whe, 65, 1, -1);
    prep_wh<<<576, 256>>>(W_dec, wdx, 128, 0, -1);
    prep_wh<<<576, 256>>>(W_dec, wds, 128, 0, 64);
    prep_wxf<<<9, 256>>>(W_enc, wxf);

    __nv_bfloat16 *curhi = ahi, *curlo = alo, *othhi = bhi, *othlo = blo;

    // ---- encoder ----
    for (int t = 0; t < TT; t++) {
        conv_step<<<1024, 512, SMEM_BYTES>>>(curhi, curlo, othhi, othlo, c,
                                             whe, x, t, b_enc, t > 0, 1,
                                             0, 0, W_cnn, b_cnn, out);
        __nv_bfloat16* tp;
        tp = curhi; curhi = othhi; othhi = tp;
        tp = curlo; curlo = othlo; othlo = tp;
    }

    ev_out<<<BB * 64, 256>>>(curhi, curlo, out + Y_ELEMS);
    zero_buf<<<2048, 256>>>(c, STATE_ELEMS);

    // ---- decoder (head for step t-1 fused into step t's prologue) ----
    for (int t = 0; t < TT; t++) {
        const __nv_bfloat16* W = (t == 0) ? wdx : wds;
        conv_step<<<1024, 512, SMEM_BYTES>>>(curhi, curlo, othhi, othlo, c,
                                             W, x, t, b_dec, 1, 0,
                                             t > 0, t - 1, W_cnn, b_cnn, out);
        __nv_bfloat16* tp;
        tp = curhi; curhi = othhi; othhi = tp;
        tp = curlo; curlo = othlo; othlo = tp;
    }
    // final head for t = 11 from the last h
    cnn_head<<<512, 256>>>(curhi, curlo, W_cnn, b_cnn, out, TT - 1);
}

// round 12
// speedup vs baseline: 8.4429x; 1.3531x over previous
#include <cuda_runtime.h>
#include <cuda_fp16.h>
#include <math.h>
#include <stdint.h>

// ---------------- constants ----------------
#define HW 64
#define NF 64
#define BB 32
#define TT 12
#define PHW 66
#define PPX (PHW*PHW)                 // 4356
#define STATE_ELEMS (BB*NF*HW*HW)     // 8,388,608
#define Y_ELEMS (BB*TT*HW*HW)         // 1,572,864

// ---------------- smem layout (bytes) ----------------
#define O_INH 0                       // input slab hi: 264 px * 144B (4 rows x 66)
#define O_INL 38016                   // input slab lo
#define O_WB  76032                   // 3 weight bufs: 256 oc * 144B each
#define WBSZ  36864
#define O_XS  186624                  // x slab: 264 fp32
#define O_WX  187680                  // Wx: 2304 fp32
#define O_HW  196896                  // head weights: 576 fp32
#define SMEM_BYTES 199232
// epilogue overlays gates fp32 [4][128px][64ch] = 131072B at offset 0

// ---------------- device globals ----------------
__device__ float g_c[STATE_ELEMS];
__device__ __align__(16) __half g_nhA_hi[BB*PPX*NF];
__device__ __align__(16) __half g_nhA_lo[BB*PPX*NF];
__device__ __align__(16) __half g_nhB_hi[BB*PPX*NF];
__device__ __align__(16) __half g_nhB_lo[BB*PPX*NF];
__device__ __align__(16) __half g_WhE[9*256*64];   // [tap][oc][ch] fp16
__device__ __align__(16) __half g_WdX[9*256*64];
__device__ __align__(16) __half g_WdS[9*256*64];
__device__ float g_Wxf[256*9];

// ---------------- PTX helpers ----------------
__device__ __forceinline__ uint32_t smem_u32(const void* p) {
    uint32_t a;
    asm("{ .reg .u64 t; cvta.to.shared.u64 t, %1; cvt.u32.u64 %0, t; }" : "=r"(a) : "l"(p));
    return a;
}
__device__ __forceinline__ void cp16_s(uint32_t sdst, const void* g) {
    asm volatile("cp.async.cg.shared.global [%0], [%1], 16;" :: "r"(sdst), "l"(g));
}
__device__ __forceinline__ void ldsm4(uint32_t* r, uint32_t addr) {
    asm volatile("ldmatrix.sync.aligned.m8n8.x4.shared.b16 {%0,%1,%2,%3}, [%4];"
        : "=r"(r[0]), "=r"(r[1]), "=r"(r[2]), "=r"(r[3]) : "r"(addr));
}
__device__ __forceinline__ void mma16816(float* d, const uint32_t* a, const uint32_t* b) {
    asm volatile("mma.sync.aligned.m16n8k16.row.col.f32.f16.f16.f32 "
        "{%0,%1,%2,%3}, {%4,%5,%6,%7}, {%8,%9}, {%0,%1,%2,%3};"
        : "+f"(d[0]), "+f"(d[1]), "+f"(d[2]), "+f"(d[3])
        : "r"(a[0]), "r"(a[1]), "r"(a[2]), "r"(a[3]), "r"(b[0]), "r"(b[1]));
}
__device__ __forceinline__ float sigmoidf_(float x) { return 1.f / (1.f + __expf(-x)); }
__device__ __forceinline__ float tanhf_(float x) {
    float e = __expf(2.f * x);
    return (e - 1.f) * __frcp_rn(e + 1.f);
}

// ---------------- prep kernels ----------------
__global__ void zero_buf(float* __restrict__ p, int n) {
    for (int i = blockIdx.x * blockDim.x + threadIdx.x; i < n; i += gridDim.x * blockDim.x)
        p[i] = 0.f;
}
// W[oc][CIN][9] -> dst[tap][oc][64ch] fp16, channels off1.., optional fold +off2
__global__ void prep_wh(const float* __restrict__ W, __half* __restrict__ dst,
                        int CIN, int off1, int off2) {
    int idx = blockIdx.x * blockDim.x + threadIdx.x;
    if (idx >= 9 * 256 * 64) return;
    int ch = idx & 63, oc = (idx >> 6) & 255, tap = idx >> 14;
    float w = W[((size_t)oc * CIN + off1 + ch) * 9 + tap];
    if (off2 >= 0) w += W[((size_t)oc * CIN + off2 + ch) * 9 + tap];
    dst[((size_t)tap * 256 + oc) * 64 + ch] = __float2half(w);
}
__global__ void prep_wxf(const float* __restrict__ W, float* __restrict__ dst) {
    int i = blockIdx.x * blockDim.x + threadIdx.x;
    if (i >= 2304) return;
    int oc = i / 9, tap = i % 9;
    dst[i] = W[(size_t)oc * 65 * 9 + tap];
}

// ---------------- ConvLSTM step: fp16 mma.sync implicit GEMM (2-product) ----------------
// grid 1024 = 32 b x 32 y-pairs (2 rows); 512 threads (16 warps: 4 M x 4 N)
__global__ void __launch_bounds__(512, 1)
conv_step(const __half* __restrict__ hi_in, const __half* __restrict__ lo_in,
          __half* __restrict__ hi_out, __half* __restrict__ lo_out,
          float* __restrict__ c,
          const __half* __restrict__ Wm,
          const float* __restrict__ x, int t,
          const float* __restrict__ bias, int has_mma, int has_x,
          int do_head, int tout,
          const float* __restrict__ Wc, const float* __restrict__ bc,
          float* __restrict__ yout) {
    extern __shared__ __align__(16) unsigned char smem[];
    const uint32_t sb = smem_u32(smem);
    const int tid = threadIdx.x, wid = tid >> 5, lane = tid & 31;
    const int b = blockIdx.x >> 5, yg = blockIdx.x & 31, y0 = yg * 2;

    // ---- prologue staging ----
    if (has_x) {
        if (tid < 264) {
            int r = tid / 66, cc = tid % 66;
            int gy = y0 + r - 1, gx = cc - 1;
            float v = 0.f;
            if ((unsigned)gy < 64u && (unsigned)gx < 64u)
                v = x[((size_t)b * TT + t) * 4096 + gy * 64 + gx];
            ((float*)(smem + O_XS))[tid] = v;
        }
#pragma unroll
        for (int j = 0; j < 5; j++) {
            int idx = tid + j * 512;
            if (idx < 2304) ((float*)(smem + O_WX))[idx] = g_Wxf[idx];
        }
    }
    if (do_head) {
        for (int i = tid; i < 576; i += 512) {
            int tap = i >> 6, ch = i & 63;
            ((float*)(smem + O_HW))[i] = Wc[ch * 9 + tap];
        }
    }

    auto stage_w = [&](int ci) {
        uint32_t dstoff = O_WB + (uint32_t)(ci % 3) * WBSZ;
        const char* src = (const char*)(Wm + (size_t)ci * 16384);
#pragma unroll
        for (int j = 0; j < 4; j++) {
            int idx = tid + j * 512;            // 0..2047
            int oc = idx >> 3, seg = idx & 7;
            cp16_s(sb + dstoff + oc * 144 + seg * 16, src + oc * 128 + seg * 16);
        }
        asm volatile("cp.async.commit_group;" ::: "memory");
    };

    if (has_mma) {
        const char* hbase = (const char*)(hi_in + ((size_t)b * PPX + (size_t)y0 * PHW) * 64);
        const char* lbase = (const char*)(lo_in + ((size_t)b * PPX + (size_t)y0 * PHW) * 64);
#pragma unroll
        for (int j = 0; j < 5; j++) {
            int idx = tid + j * 512;
            if (idx < 2112) {                    // 264 px * 8 segs
                int p = idx >> 3, seg = idx & 7;
                cp16_s(sb + O_INH + p * 144 + seg * 16, hbase + p * 128 + seg * 16);
                cp16_s(sb + O_INL + p * 144 + seg * 16, lbase + p * 128 + seg * 16);
            }
        }
        // group0 = slabs + chunk0; group1 = chunk1
        {
            uint32_t dstoff = O_WB;
            const char* src = (const char*)Wm;
#pragma unroll
            for (int j = 0; j < 4; j++) {
                int idx = tid + j * 512;
                int oc = idx >> 3, seg = idx & 7;
                cp16_s(sb + dstoff + oc * 144 + seg * 16, src + oc * 128 + seg * 16);
            }
            asm volatile("cp.async.commit_group;" ::: "memory");
        }
        stage_w(1);
    }

    // ---- fragment geometry ----
    const int mw = wid & 3;                  // gate block (64 oc)
    const int nw = wid >> 2;                 // px quarter (32 px)
    const uint32_t a_row = mw * 64 + (lane & 15);
    const uint32_t a_kh = ((lane >> 4) << 3);
    const int nfsel = lane >> 4;
    const int khalf = (lane >> 3) & 1;
    int prow[4], pcol[4];
#pragma unroll
    for (int nf = 0; nf < 4; nf++) {
        int p = nw * 32 + nf * 8 + (lane & 7);
        prow[nf] = p >> 6;
        pcol[nf] = p & 63;
    }

    float acc[4][4][4];
#pragma unroll
    for (int i = 0; i < 4; i++)
#pragma unroll
        for (int j = 0; j < 4; j++)
#pragma unroll
            for (int k = 0; k < 4; k++) acc[i][j][k] = 0.f;

    if (has_mma) {
        for (int ci = 0; ci < 9; ci++) {
            if (ci < 8) asm volatile("cp.async.wait_group 1;" ::: "memory");
            else        asm volatile("cp.async.wait_group 0;" ::: "memory");
            __syncthreads();

            // ---- fused CNN head (slab is resident; runs once) ----
            if (ci == 0 && do_head && tid < 128) {
                const int pr = tid >> 6, pc = tid & 63;
                float hacc = __ldg(bc);
#pragma unroll
                for (int ky = 0; ky < 3; ky++)
#pragma unroll
                    for (int kx = 0; kx < 3; kx++) {
                        const uint32_t base = (uint32_t)(((pr + ky) * 66 + pc + kx) * 144);
                        const float* wr = (const float*)(smem + O_HW) + (ky * 3 + kx) * 64;
#pragma unroll 4
                        for (int ch = 0; ch < 64; ch += 4) {
                            uint2 h2 = *(const uint2*)(smem + O_INH + base + ch * 2);
                            uint2 l2 = *(const uint2*)(smem + O_INL + base + ch * 2);
                            float2 ha = __half22float2(*(__half2*)&h2.x);
                            float2 hb = __half22float2(*(__half2*)&h2.y);
                            float2 la = __half22float2(*(__half2*)&l2.x);
                            float2 lb = __half22float2(*(__half2*)&l2.y);
                            hacc += wr[ch+0] * (ha.x + la.x);
                            hacc += wr[ch+1] * (ha.y + la.y);
                            hacc += wr[ch+2] * (hb.x + lb.x);
                            hacc += wr[ch+3] * (hb.y + lb.y);
                        }
                    }
                yout[((size_t)b * TT + tout) * 4096 + (y0 + pr) * 64 + pc] = hacc;
            }

            if (ci + 2 < 9) stage_w(ci + 2);

            const uint32_t wb = sb + O_WB + (uint32_t)(ci % 3) * WBSZ;
            const int dy = ci / 3, dx = ci % 3;
            uint32_t bco[2];
#pragma unroll
            for (int j = 0; j < 2; j++) {
                int nf = j * 2 + nfsel;
                bco[j] = (uint32_t)(((prow[nf] + dy) * 66 + pcol[nf] + dx) * 144 + khalf * 16);
            }

#pragma unroll
            for (int ks = 0; ks < 4; ks++) {
                const int k0 = ks * 16;
                uint32_t af[4][4];
#pragma unroll
                for (int mf = 0; mf < 4; mf++)
                    ldsm4(af[mf], wb + (a_row + mf * 16) * 144 + (k0 + a_kh) * 2);
#pragma unroll
                for (int pp = 0; pp < 2; pp++) {
                    const uint32_t slab = sb + (pp ? O_INL : O_INH);
                    uint32_t bf4[2][4];
                    ldsm4(bf4[0], slab + bco[0] + k0 * 2);
                    ldsm4(bf4[1], slab + bco[1] + k0 * 2);
#pragma unroll
                    for (int mf = 0; mf < 4; mf++)
#pragma unroll
                        for (int nf = 0; nf < 4; nf++)
                            mma16816(acc[mf][nf], af[mf], &bf4[nf >> 1][(nf & 1) * 2]);
                }
            }
        }
    }
    __syncthreads();

    // ---- store gate fragments to smem overlay [gate][128px][64ch] fp32 ----
    float* sg = (float*)smem;
    if (has_mma) {
        const int g = lane >> 2, tp = lane & 3;
#pragma unroll
        for (int mf = 0; mf < 4; mf++)
#pragma unroll
            for (int nf = 0; nf < 4; nf++) {
                int ch0 = mf * 16 + g;
                int px0 = nw * 32 + nf * 8 + tp * 2;
                float* p = sg + mw * 8192 + px0 * 64 + ch0;
                p[0]      = acc[mf][nf][0];
                p[64]     = acc[mf][nf][1];
                p[8]      = acc[mf][nf][2];
                p[64 + 8] = acc[mf][nf][3];
            }
    }
    __syncthreads();

    // ---- LSTM pointwise epilogue: 128 px x 64 ch over 512 threads ----
    const int ch = tid & 63;
    const int pxb = (tid >> 6) * 16;
    const float bi = __ldg(bias + ch);
    const float bf_ = __ldg(bias + 64 + ch);
    const float bo = __ldg(bias + 128 + ch);
    const float bg = __ldg(bias + 192 + ch);

    float wxr[36];
    if (has_x) {
        const float* sWx = (const float*)(smem + O_WX);
#pragma unroll
        for (int g4 = 0; g4 < 4; g4++)
#pragma unroll
            for (int tp = 0; tp < 9; tp++)
                wxr[g4 * 9 + tp] = sWx[(g4 * 64 + ch) * 9 + tp];
    }
    const float* sx = (const float*)(smem + O_XS);

#pragma unroll 4
    for (int k = 0; k < 16; k++) {
        const int px = pxb + k;
        const int pr = px >> 6, pc = px & 63;
        float vi = bi, vf = bf_, vo = bo, vg = bg;
        if (has_mma) {
            vi += sg[px * 64 + ch];
            vf += sg[8192 + px * 64 + ch];
            vo += sg[16384 + px * 64 + ch];
            vg += sg[24576 + px * 64 + ch];
        }
        if (has_x) {
            float xs[9];
#pragma unroll
            for (int tp = 0; tp < 9; tp++)
                xs[tp] = sx[(pr + tp / 3) * 66 + (tp % 3) + pc];
            float s0 = 0, s1 = 0, s2 = 0, s3 = 0;
#pragma unroll
            for (int tp = 0; tp < 9; tp++) {
                s0 += wxr[tp] * xs[tp];
                s1 += wxr[9 + tp] * xs[tp];
                s2 += wxr[18 + tp] * xs[tp];
                s3 += wxr[27 + tp] * xs[tp];
            }
            vi += s0; vf += s1; vo += s2; vg += s3;
        }
        const int y = y0 + pr;
        const size_t coff = (((size_t)b * 64 + y) * 64 + pc) * 64 + ch;
        float cn = sigmoidf_(vf) * c[coff] + sigmoidf_(vi) * tanhf_(vg);
        c[coff] = cn;
        float hv = sigmoidf_(vo) * tanhf_(cn);
        __half hhi = __float2half(hv);
        __half hlo = __float2half(hv - __half2float(hhi));
        const size_t hoff = ((size_t)b * PPX + (size_t)(y + 1) * PHW + (pc + 1)) * 64 + ch;
        hi_out[hoff] = hhi;
        lo_out[hoff] = hlo;
    }
}

// ---------------- encoder-vector: padded NHWC hi/lo -> NCHW fp32 ----------------
__global__ void ev_out(const __half* __restrict__ hi, const __half* __restrict__ lo,
                       float* __restrict__ outv) {
    __shared__ float s[64][65];
    int b = blockIdx.x >> 6, y = blockIdx.x & 63;
    int tid = threadIdx.x;
#pragma unroll
    for (int i = 0; i < 16; i++) {
        int xx = (tid >> 6) + i * 4, ch = tid & 63;
        size_t off = (((size_t)b * PPX) + (size_t)(y + 1) * PHW + (xx + 1)) * 64 + ch;
        s[xx][ch] = __half2float(hi[off]) + __half2float(lo[off]);
    }
    __syncthreads();
#pragma unroll
    for (int i = 0; i < 16; i++) {
        int xx = tid & 63, ch = (tid >> 6) + i * 4;
        outv[((size_t)b * 64 + ch) * 4096 + y * 64 + xx] = s[xx][ch];
    }
}

// ---------------- standalone 3D CNN head (final decoder step only) ----------------
__global__ void cnn_head(const __half* __restrict__ hi, const __half* __restrict__ lo,
                         const float* __restrict__ Wc, const float* __restrict__ bc,
                         float* __restrict__ out, int t) {
    __shared__ float s_w[9 * 64];
    int b = blockIdx.x >> 4, yg = blockIdx.x & 15, y0 = yg * 4;
    int tid = threadIdx.x;
    for (int i = tid; i < 576; i += 256) {
        int ch = i / 9, tap = i % 9;
        s_w[tap * 64 + ch] = Wc[i];
    }
    __syncthreads();
    int r = tid >> 6, xx = tid & 63, iy = y0 + r;
    float acc = bc[0];
#pragma unroll
    for (int ky = 0; ky < 3; ky++)
#pragma unroll
        for (int kx = 0; kx < 3; kx++) {
            size_t base = (((size_t)b * PPX) + (size_t)(iy + ky) * PHW + (xx + kx)) * 64;
            const float* wrow = s_w + (ky * 3 + kx) * 64;
            float s = 0.f;
            for (int ch = 0; ch < 64; ch++)
                s += wrow[ch] * (__half2float(hi[base + ch]) + __half2float(lo[base + ch]));
            acc += s;
        }
    out[((size_t)b * TT + t) * 4096 + iy * 64 + xx] = acc;
}

// ---------------- launch ----------------
extern "C" void kernel_launch(void* const* d_in, const int* in_sizes, int n_in,
                              void* d_out, int out_size) {
    const float* x     = (const float*)d_in[0];
    const float* W_enc = (const float*)d_in[2];
    const float* b_enc = (const float*)d_in[3];
    const float* W_dec = (const float*)d_in[4];
    const float* b_dec = (const float*)d_in[5];
    const float* W_cnn = (const float*)d_in[6];
    const float* b_cnn = (const float*)d_in[7];
    float* out = (float*)d_out;

    float *c, *wxf;
    __half *ahi, *alo, *bhi, *blo, *whe, *wdx, *wds;
    cudaGetSymbolAddress((void**)&c, g_c);
    cudaGetSymbolAddress((void**)&ahi, g_nhA_hi);
    cudaGetSymbolAddress((void**)&alo, g_nhA_lo);
    cudaGetSymbolAddress((void**)&bhi, g_nhB_hi);
    cudaGetSymbolAddress((void**)&blo, g_nhB_lo);
    cudaGetSymbolAddress((void**)&whe, g_WhE);
    cudaGetSymbolAddress((void**)&wdx, g_WdX);
    cudaGetSymbolAddress((void**)&wds, g_WdS);
    cudaGetSymbolAddress((void**)&wxf, g_Wxf);

    cudaFuncSetAttribute(conv_step, cudaFuncAttributeMaxDynamicSharedMemorySize, SMEM_BYTES);

    zero_buf<<<2048, 256>>>(c, STATE_ELEMS);
    zero_buf<<<2048, 256>>>((float*)ahi, BB * PPX * NF / 2);
    zero_buf<<<2048, 256>>>((float*)alo, BB * PPX * NF / 2);
    zero_buf<<<2048, 256>>>((float*)bhi, BB * PPX * NF / 2);
    zero_buf<<<2048, 256>>>((float*)blo, BB * PPX * NF / 2);

    prep_wh<<<576, 256>>>(W_enc, whe, 65, 1, -1);
    prep_wh<<<576, 256>>>(W_dec, wdx, 128, 0, -1);
    prep_wh<<<576, 256>>>(W_dec, wds, 128, 0, 64);
    prep_wxf<<<9, 256>>>(W_enc, wxf);

    __half *curhi = ahi, *curlo = alo, *othhi = bhi, *othlo = blo;

    // ---- encoder ----
    for (int t = 0; t < TT; t++) {
        conv_step<<<1024, 512, SMEM_BYTES>>>(curhi, curlo, othhi, othlo, c,
                                             whe, x, t, b_enc, t > 0, 1,
                                             0, 0, W_cnn, b_cnn, out);
        __half* tp;
        tp = curhi; curhi = othhi; othhi = tp;
        tp = curlo; curlo = othlo; othlo = tp;
    }

    ev_out<<<BB * 64, 256>>>(curhi, curlo, out + Y_ELEMS);
    zero_buf<<<2048, 256>>>(c, STATE_ELEMS);

    // ---- decoder (head for step t-1 fused into step t's prologue) ----
    for (int t = 0; t < TT; t++) {
        const __half* W = (t == 0) ? wdx : wds;
        conv_step<<<1024, 512, SMEM_BYTES>>>(curhi, curlo, othhi, othlo, c,
                                             W, x, t, b_dec, 1, 0,
                                             t > 0, t - 1, W_cnn, b_cnn, out);
        __half* tp;
        tp = curhi; curhi = othhi; othhi = tp;
        tp = curlo; curlo = othlo; othlo = tp;
    }
    // final head for t = 11 from the last h
    cnn_head<<<512, 256>>>(curhi, curlo, W_cnn, b_cnn, out, TT - 1);
}

// round 13
// speedup vs baseline: 10.7440x; 1.2726x over previous
#include <cuda_runtime.h>
#include <cuda_fp16.h>
#include <math.h>
#include <stdint.h>

// ---------------- constants ----------------
#define HW 64
#define NF 64
#define BB 32
#define TT 12
#define PHW 66
#define PPX (PHW*PHW)                 // 4356
#define STATE_ELEMS (BB*NF*HW*HW)     // 8,388,608
#define Y_ELEMS (BB*TT*HW*HW)         // 1,572,864

// ---------------- smem layout (bytes) ----------------
#define O_INH 0                       // input slab hi: 264 px * 144B (4 rows x 66)
#define O_INL 38016                   // input slab lo (staged only when do_head)
#define O_WB  76032                   // 3 weight bufs: 256 oc * 144B each
#define WBSZ  36864
#define O_XS  186624                  // x slab: 264 fp32
#define O_WX  187680                  // Wx: 2304 fp32
#define O_HW  196896                  // head weights: 576 fp32
#define SMEM_BYTES 199232
// epilogue overlays gates fp32 [4][128px][64ch] = 131072B at offset 0

// ---------------- device globals ----------------
__device__ float g_c[STATE_ELEMS];
__device__ __align__(16) __half g_nhA_hi[BB*PPX*NF];
__device__ __align__(16) __half g_nhA_lo[BB*PPX*NF];
__device__ __align__(16) __half g_nhB_hi[BB*PPX*NF];
__device__ __align__(16) __half g_nhB_lo[BB*PPX*NF];
__device__ __align__(16) __half g_WhE[9*256*64];   // [tap][oc][ch] fp16
__device__ __align__(16) __half g_WdX[9*256*64];
__device__ __align__(16) __half g_WdS[9*256*64];
__device__ float g_Wxf[256*9];

// ---------------- PTX helpers ----------------
__device__ __forceinline__ uint32_t smem_u32(const void* p) {
    uint32_t a;
    asm("{ .reg .u64 t; cvta.to.shared.u64 t, %1; cvt.u32.u64 %0, t; }" : "=r"(a) : "l"(p));
    return a;
}
__device__ __forceinline__ void cp16_s(uint32_t sdst, const void* g) {
    asm volatile("cp.async.cg.shared.global [%0], [%1], 16;" :: "r"(sdst), "l"(g));
}
__device__ __forceinline__ void ldsm4(uint32_t* r, uint32_t addr) {
    asm volatile("ldmatrix.sync.aligned.m8n8.x4.shared.b16 {%0,%1,%2,%3}, [%4];"
        : "=r"(r[0]), "=r"(r[1]), "=r"(r[2]), "=r"(r[3]) : "r"(addr));
}
__device__ __forceinline__ void mma16816(float* d, const uint32_t* a, const uint32_t* b) {
    asm volatile("mma.sync.aligned.m16n8k16.row.col.f32.f16.f16.f32 "
        "{%0,%1,%2,%3}, {%4,%5,%6,%7}, {%8,%9}, {%0,%1,%2,%3};"
        : "+f"(d[0]), "+f"(d[1]), "+f"(d[2]), "+f"(d[3])
        : "r"(a[0]), "r"(a[1]), "r"(a[2]), "r"(a[3]), "r"(b[0]), "r"(b[1]));
}
__device__ __forceinline__ float sigmoidf_(float x) { return 1.f / (1.f + __expf(-x)); }
__device__ __forceinline__ float tanhf_(float x) {
    float e = __expf(2.f * x);
    return (e - 1.f) * __frcp_rn(e + 1.f);
}

// ---------------- prep kernels ----------------
__global__ void zero_buf(float* __restrict__ p, int n) {
    for (int i = blockIdx.x * blockDim.x + threadIdx.x; i < n; i += gridDim.x * blockDim.x)
        p[i] = 0.f;
}
// W[oc][CIN][9] -> dst[tap][oc][64ch] fp16, channels off1.., optional fold +off2
__global__ void prep_wh(const float* __restrict__ W, __half* __restrict__ dst,
                        int CIN, int off1, int off2) {
    int idx = blockIdx.x * blockDim.x + threadIdx.x;
    if (idx >= 9 * 256 * 64) return;
    int ch = idx & 63, oc = (idx >> 6) & 255, tap = idx >> 14;
    float w = W[((size_t)oc * CIN + off1 + ch) * 9 + tap];
    if (off2 >= 0) w += W[((size_t)oc * CIN + off2 + ch) * 9 + tap];
    dst[((size_t)tap * 256 + oc) * 64 + ch] = __float2half(w);
}
__global__ void prep_wxf(const float* __restrict__ W, float* __restrict__ dst) {
    int i = blockIdx.x * blockDim.x + threadIdx.x;
    if (i >= 2304) return;
    int oc = i / 9, tap = i % 9;
    dst[i] = W[(size_t)oc * 65 * 9 + tap];
}

// ---------------- ConvLSTM step: fp16 mma.sync implicit GEMM (1-product) ----------------
// grid 1024 = 32 b x 32 y-pairs (2 rows); 512 threads (16 warps: 4 M x 4 N)
// Recurrent conv uses h_hi only (fp16); head/ev paths read exact h (hi+lo).
__global__ void __launch_bounds__(512, 1)
conv_step(const __half* __restrict__ hi_in, const __half* __restrict__ lo_in,
          __half* __restrict__ hi_out, __half* __restrict__ lo_out,
          float* __restrict__ c,
          const __half* __restrict__ Wm,
          const float* __restrict__ x, int t,
          const float* __restrict__ bias, int has_mma, int has_x,
          int do_head, int tout,
          const float* __restrict__ Wc, const float* __restrict__ bc,
          float* __restrict__ yout) {
    extern __shared__ __align__(16) unsigned char smem[];
    const uint32_t sb = smem_u32(smem);
    const int tid = threadIdx.x, wid = tid >> 5, lane = tid & 31;
    const int b = blockIdx.x >> 5, yg = blockIdx.x & 31, y0 = yg * 2;

    // ---- prologue staging ----
    if (has_x) {
        if (tid < 264) {
            int r = tid / 66, cc = tid % 66;
            int gy = y0 + r - 1, gx = cc - 1;
            float v = 0.f;
            if ((unsigned)gy < 64u && (unsigned)gx < 64u)
                v = x[((size_t)b * TT + t) * 4096 + gy * 64 + gx];
            ((float*)(smem + O_XS))[tid] = v;
        }
#pragma unroll
        for (int j = 0; j < 5; j++) {
            int idx = tid + j * 512;
            if (idx < 2304) ((float*)(smem + O_WX))[idx] = g_Wxf[idx];
        }
    }
    if (do_head) {
        for (int i = tid; i < 576; i += 512) {
            int tap = i >> 6, ch = i & 63;
            ((float*)(smem + O_HW))[i] = Wc[ch * 9 + tap];
        }
    }

    auto stage_w = [&](int ci) {
        uint32_t dstoff = O_WB + (uint32_t)(ci % 3) * WBSZ;
        const char* src = (const char*)(Wm + (size_t)ci * 16384);
#pragma unroll
        for (int j = 0; j < 4; j++) {
            int idx = tid + j * 512;            // 0..2047
            int oc = idx >> 3, seg = idx & 7;
            cp16_s(sb + dstoff + oc * 144 + seg * 16, src + oc * 128 + seg * 16);
        }
        asm volatile("cp.async.commit_group;" ::: "memory");
    };

    if (has_mma) {
        const char* hbase = (const char*)(hi_in + ((size_t)b * PPX + (size_t)y0 * PHW) * 64);
        const char* lbase = (const char*)(lo_in + ((size_t)b * PPX + (size_t)y0 * PHW) * 64);
#pragma unroll
        for (int j = 0; j < 5; j++) {
            int idx = tid + j * 512;
            if (idx < 2112) {                    // 264 px * 8 segs
                int p = idx >> 3, seg = idx & 7;
                cp16_s(sb + O_INH + p * 144 + seg * 16, hbase + p * 128 + seg * 16);
                if (do_head)
                    cp16_s(sb + O_INL + p * 144 + seg * 16, lbase + p * 128 + seg * 16);
            }
        }
        // group0 = slabs + chunk0; group1 = chunk1
        {
            uint32_t dstoff = O_WB;
            const char* src = (const char*)Wm;
#pragma unroll
            for (int j = 0; j < 4; j++) {
                int idx = tid + j * 512;
                int oc = idx >> 3, seg = idx & 7;
                cp16_s(sb + dstoff + oc * 144 + seg * 16, src + oc * 128 + seg * 16);
            }
            asm volatile("cp.async.commit_group;" ::: "memory");
        }
        stage_w(1);
    }

    // ---- fragment geometry ----
    const int mw = wid & 3;                  // gate block (64 oc)
    const int nw = wid >> 2;                 // px quarter (32 px)
    const uint32_t a_row = mw * 64 + (lane & 15);
    const uint32_t a_kh = ((lane >> 4) << 3);
    const int nfsel = lane >> 4;
    const int khalf = (lane >> 3) & 1;
    int prow[4], pcol[4];
#pragma unroll
    for (int nf = 0; nf < 4; nf++) {
        int p = nw * 32 + nf * 8 + (lane & 7);
        prow[nf] = p >> 6;
        pcol[nf] = p & 63;
    }

    float acc[4][4][4];
#pragma unroll
    for (int i = 0; i < 4; i++)
#pragma unroll
        for (int j = 0; j < 4; j++)
#pragma unroll
            for (int k = 0; k < 4; k++) acc[i][j][k] = 0.f;

    if (has_mma) {
        for (int ci = 0; ci < 9; ci++) {
            if (ci < 8) asm volatile("cp.async.wait_group 1;" ::: "memory");
            else        asm volatile("cp.async.wait_group 0;" ::: "memory");
            __syncthreads();

            // ---- fused CNN head (exact h = hi+lo; slab resident; runs once) ----
            if (ci == 0 && do_head && tid < 128) {
                const int pr = tid >> 6, pc = tid & 63;
                float hacc = __ldg(bc);
#pragma unroll
                for (int ky = 0; ky < 3; ky++)
#pragma unroll
                    for (int kx = 0; kx < 3; kx++) {
                        const uint32_t base = (uint32_t)(((pr + ky) * 66 + pc + kx) * 144);
                        const float* wr = (const float*)(smem + O_HW) + (ky * 3 + kx) * 64;
#pragma unroll 4
                        for (int ch = 0; ch < 64; ch += 4) {
                            uint2 h2 = *(const uint2*)(smem + O_INH + base + ch * 2);
                            uint2 l2 = *(const uint2*)(smem + O_INL + base + ch * 2);
                            float2 ha = __half22float2(*(__half2*)&h2.x);
                            float2 hb = __half22float2(*(__half2*)&h2.y);
                            float2 la = __half22float2(*(__half2*)&l2.x);
                            float2 lb = __half22float2(*(__half2*)&l2.y);
                            hacc += wr[ch+0] * (ha.x + la.x);
                            hacc += wr[ch+1] * (ha.y + la.y);
                            hacc += wr[ch+2] * (hb.x + lb.x);
                            hacc += wr[ch+3] * (hb.y + lb.y);
                        }
                    }
                yout[((size_t)b * TT + tout) * 4096 + (y0 + pr) * 64 + pc] = hacc;
            }

            if (ci + 2 < 9) stage_w(ci + 2);

            const uint32_t wb = sb + O_WB + (uint32_t)(ci % 3) * WBSZ;
            const int dy = ci / 3, dx = ci % 3;
            uint32_t bco[2];
#pragma unroll
            for (int j = 0; j < 2; j++) {
                int nf = j * 2 + nfsel;
                bco[j] = (uint32_t)(((prow[nf] + dy) * 66 + pcol[nf] + dx) * 144 + khalf * 16);
            }

#pragma unroll
            for (int ks = 0; ks < 4; ks++) {
                const int k0 = ks * 16;
                uint32_t af[4][4];
#pragma unroll
                for (int mf = 0; mf < 4; mf++)
                    ldsm4(af[mf], wb + (a_row + mf * 16) * 144 + (k0 + a_kh) * 2);
                uint32_t bf4[2][4];
                ldsm4(bf4[0], sb + O_INH + bco[0] + k0 * 2);
                ldsm4(bf4[1], sb + O_INH + bco[1] + k0 * 2);
#pragma unroll
                for (int mf = 0; mf < 4; mf++)
#pragma unroll
                    for (int nf = 0; nf < 4; nf++)
                        mma16816(acc[mf][nf], af[mf], &bf4[nf >> 1][(nf & 1) * 2]);
            }
        }
    }
    __syncthreads();

    // ---- store gate fragments to smem overlay [gate][128px][64ch] fp32 ----
    float* sg = (float*)smem;
    if (has_mma) {
        const int g = lane >> 2, tp = lane & 3;
#pragma unroll
        for (int mf = 0; mf < 4; mf++)
#pragma unroll
            for (int nf = 0; nf < 4; nf++) {
                int ch0 = mf * 16 + g;
                int px0 = nw * 32 + nf * 8 + tp * 2;
                float* p = sg + mw * 8192 + px0 * 64 + ch0;
                p[0]      = acc[mf][nf][0];
                p[64]     = acc[mf][nf][1];
                p[8]      = acc[mf][nf][2];
                p[64 + 8] = acc[mf][nf][3];
            }
    }
    __syncthreads();

    // ---- LSTM pointwise epilogue: 128 px x 64 ch over 512 threads ----
    const int ch = tid & 63;
    const int pxb = (tid >> 6) * 16;
    const float bi = __ldg(bias + ch);
    const float bf_ = __ldg(bias + 64 + ch);
    const float bo = __ldg(bias + 128 + ch);
    const float bg = __ldg(bias + 192 + ch);

    float wxr[36];
    if (has_x) {
        const float* sWx = (const float*)(smem + O_WX);
#pragma unroll
        for (int g4 = 0; g4 < 4; g4++)
#pragma unroll
            for (int tp = 0; tp < 9; tp++)
                wxr[g4 * 9 + tp] = sWx[(g4 * 64 + ch) * 9 + tp];
    }
    const float* sx = (const float*)(smem + O_XS);

#pragma unroll 4
    for (int k = 0; k < 16; k++) {
        const int px = pxb + k;
        const int pr = px >> 6, pc = px & 63;
        float vi = bi, vf = bf_, vo = bo, vg = bg;
        if (has_mma) {
            vi += sg[px * 64 + ch];
            vf += sg[8192 + px * 64 + ch];
            vo += sg[16384 + px * 64 + ch];
            vg += sg[24576 + px * 64 + ch];
        }
        if (has_x) {
            float xs[9];
#pragma unroll
            for (int tp = 0; tp < 9; tp++)
                xs[tp] = sx[(pr + tp / 3) * 66 + (tp % 3) + pc];
            float s0 = 0, s1 = 0, s2 = 0, s3 = 0;
#pragma unroll
            for (int tp = 0; tp < 9; tp++) {
                s0 += wxr[tp] * xs[tp];
                s1 += wxr[9 + tp] * xs[tp];
                s2 += wxr[18 + tp] * xs[tp];
                s3 += wxr[27 + tp] * xs[tp];
            }
            vi += s0; vf += s1; vo += s2; vg += s3;
        }
        const int y = y0 + pr;
        const size_t coff = (((size_t)b * 64 + y) * 64 + pc) * 64 + ch;
        float cn = sigmoidf_(vf) * c[coff] + sigmoidf_(vi) * tanhf_(vg);
        c[coff] = cn;
        float hv = sigmoidf_(vo) * tanhf_(cn);
        __half hhi = __float2half(hv);
        __half hlo = __float2half(hv - __half2float(hhi));
        const size_t hoff = ((size_t)b * PPX + (size_t)(y + 1) * PHW + (pc + 1)) * 64 + ch;
        hi_out[hoff] = hhi;
        lo_out[hoff] = hlo;
    }
}

// ---------------- encoder-vector: padded NHWC hi/lo -> NCHW fp32 ----------------
__global__ void ev_out(const __half* __restrict__ hi, const __half* __restrict__ lo,
                       float* __restrict__ outv) {
    __shared__ float s[64][65];
    int b = blockIdx.x >> 6, y = blockIdx.x & 63;
    int tid = threadIdx.x;
#pragma unroll
    for (int i = 0; i < 16; i++) {
        int xx = (tid >> 6) + i * 4, ch = tid & 63;
        size_t off = (((size_t)b * PPX) + (size_t)(y + 1) * PHW + (xx + 1)) * 64 + ch;
        s[xx][ch] = __half2float(hi[off]) + __half2float(lo[off]);
    }
    __syncthreads();
#pragma unroll
    for (int i = 0; i < 16; i++) {
        int xx = tid & 63, ch = (tid >> 6) + i * 4;
        outv[((size_t)b * 64 + ch) * 4096 + y * 64 + xx] = s[xx][ch];
    }
}

// ---------------- standalone 3D CNN head (final decoder step only) ----------------
__global__ void cnn_head(const __half* __restrict__ hi, const __half* __restrict__ lo,
                         const float* __restrict__ Wc, const float* __restrict__ bc,
                         float* __restrict__ out, int t) {
    __shared__ float s_w[9 * 64];
    int b = blockIdx.x >> 4, yg = blockIdx.x & 15, y0 = yg * 4;
    int tid = threadIdx.x;
    for (int i = tid; i < 576; i += 256) {
        int ch = i / 9, tap = i % 9;
        s_w[tap * 64 + ch] = Wc[i];
    }
    __syncthreads();
    int r = tid >> 6, xx = tid & 63, iy = y0 + r;
    float acc = bc[0];
#pragma unroll
    for (int ky = 0; ky < 3; ky++)
#pragma unroll
        for (int kx = 0; kx < 3; kx++) {
            size_t base = (((size_t)b * PPX) + (size_t)(iy + ky) * PHW + (xx + kx)) * 64;
            const float* wrow = s_w + (ky * 3 + kx) * 64;
            float s = 0.f;
            for (int ch = 0; ch < 64; ch++)
                s += wrow[ch] * (__half2float(hi[base + ch]) + __half2float(lo[base + ch]));
            acc += s;
        }
    out[((size_t)b * TT + t) * 4096 + iy * 64 + xx] = acc;
}

// ---------------- launch ----------------
extern "C" void kernel_launch(void* const* d_in, const int* in_sizes, int n_in,
                              void* d_out, int out_size) {
    const float* x     = (const float*)d_in[0];
    const float* W_enc = (const float*)d_in[2];
    const float* b_enc = (const float*)d_in[3];
    const float* W_dec = (const float*)d_in[4];
    const float* b_dec = (const float*)d_in[5];
    const float* W_cnn = (const float*)d_in[6];
    const float* b_cnn = (const float*)d_in[7];
    float* out = (float*)d_out;

    float *c, *wxf;
    __half *ahi, *alo, *bhi, *blo, *whe, *wdx, *wds;
    cudaGetSymbolAddress((void**)&c, g_c);
    cudaGetSymbolAddress((void**)&ahi, g_nhA_hi);
    cudaGetSymbolAddress((void**)&alo, g_nhA_lo);
    cudaGetSymbolAddress((void**)&bhi, g_nhB_hi);
    cudaGetSymbolAddress((void**)&blo, g_nhB_lo);
    cudaGetSymbolAddress((void**)&whe, g_WhE);
    cudaGetSymbolAddress((void**)&wdx, g_WdX);
    cudaGetSymbolAddress((void**)&wds, g_WdS);
    cudaGetSymbolAddress((void**)&wxf, g_Wxf);

    cudaFuncSetAttribute(conv_step, cudaFuncAttributeMaxDynamicSharedMemorySize, SMEM_BYTES);

    zero_buf<<<2048, 256>>>(c, STATE_ELEMS);
    zero_buf<<<2048, 256>>>((float*)ahi, BB * PPX * NF / 2);
    zero_buf<<<2048, 256>>>((float*)alo, BB * PPX * NF / 2);
    zero_buf<<<2048, 256>>>((float*)bhi, BB * PPX * NF / 2);
    zero_buf<<<2048, 256>>>((float*)blo, BB * PPX * NF / 2);

    prep_wh<<<576, 256>>>(W_enc, whe, 65, 1, -1);
    prep_wh<<<576, 256>>>(W_dec, wdx, 128, 0, -1);
    prep_wh<<<576, 256>>>(W_dec, wds, 128, 0, 64);
    prep_wxf<<<9, 256>>>(W_enc, wxf);

    __half *curhi = ahi, *curlo = alo, *othhi = bhi, *othlo = blo;

    // ---- encoder ----
    for (int t = 0; t < TT; t++) {
        conv_step<<<1024, 512, SMEM_BYTES>>>(curhi, curlo, othhi, othlo, c,
                                             whe, x, t, b_enc, t > 0, 1,
                                             0, 0, W_cnn, b_cnn, out);
        __half* tp;
        tp = curhi; curhi = othhi; othhi = tp;
        tp = curlo; curlo = othlo; othlo = tp;
    }

    ev_out<<<BB * 64, 256>>>(curhi, curlo, out + Y_ELEMS);
    zero_buf<<<2048, 256>>>(c, STATE_ELEMS);

    // ---- decoder (head for step t-1 fused into step t's prologue) ----
    for (int t = 0; t < TT; t++) {
        const __half* W = (t == 0) ? wdx : wds;
        conv_step<<<1024, 512, SMEM_BYTES>>>(curhi, curlo, othhi, othlo, c,
                                             W, x, t, b_dec, 1, 0,
                                             t > 0, t - 1, W_cnn, b_cnn, out);
        __half* tp;
        tp = curhi; curhi = othhi; othhi = tp;
        tp = curlo; curlo = othlo; othlo = tp;
    }
    // final head for t = 11 from the last h
    cnn_head<<<512, 256>>>(curhi, curlo, W_cnn, b_cnn, out, TT - 1);
}

// round 14
// speedup vs baseline: 12.9964x; 1.2096x over previous
#include <cuda_runtime.h>
#include <cuda_fp16.h>
#include <math.h>
#include <stdint.h>

// ---------------- constants ----------------
#define HW 64
#define NF 64
#define BB 32
#define TT 12
#define PHW 66
#define PPX (PHW*PHW)                 // 4356
#define STATE_ELEMS (BB*NF*HW*HW)     // 8,388,608
#define Y_ELEMS (BB*TT*HW*HW)         // 1,572,864

// ---------------- smem layout (bytes) ----------------
#define O_INH 0                       // input slab hi: 264 px * 144B (4 rows x 66)
#define O_WB  38016                   // 3 weight bufs: 256 oc * 144B each
#define WBSZ  36864
#define O_XS  148608                  // x slab: 264 fp32
#define O_WX  149664                  // Wx: 2304 fp32
#define O_HW  158880                  // head weights: 576 fp32
#define SMEM_BYTES 161216
// epilogue overlays gates fp32 [4][128px][64ch] = 131072B at offset 0

// ---------------- device globals ----------------
__device__ float g_c[STATE_ELEMS];
__device__ __align__(16) __half g_nhA_hi[BB*PPX*NF];
__device__ __align__(16) __half g_nhB_hi[BB*PPX*NF];
__device__ __align__(16) __half g_WhE[9*256*64];   // [tap][oc][ch] fp16
__device__ __align__(16) __half g_WdX[9*256*64];
__device__ __align__(16) __half g_WdS[9*256*64];
__device__ float g_Wxf[256*9];

// ---------------- PTX helpers ----------------
__device__ __forceinline__ uint32_t smem_u32(const void* p) {
    uint32_t a;
    asm("{ .reg .u64 t; cvta.to.shared.u64 t, %1; cvt.u32.u64 %0, t; }" : "=r"(a) : "l"(p));
    return a;
}
__device__ __forceinline__ void cp16_s(uint32_t sdst, const void* g) {
    asm volatile("cp.async.cg.shared.global [%0], [%1], 16;" :: "r"(sdst), "l"(g));
}
__device__ __forceinline__ void ldsm4(uint32_t* r, uint32_t addr) {
    asm volatile("ldmatrix.sync.aligned.m8n8.x4.shared.b16 {%0,%1,%2,%3}, [%4];"
        : "=r"(r[0]), "=r"(r[1]), "=r"(r[2]), "=r"(r[3]) : "r"(addr));
}
__device__ __forceinline__ void mma16816(float* d, const uint32_t* a, const uint32_t* b) {
    asm volatile("mma.sync.aligned.m16n8k16.row.col.f32.f16.f16.f32 "
        "{%0,%1,%2,%3}, {%4,%5,%6,%7}, {%8,%9}, {%0,%1,%2,%3};"
        : "+f"(d[0]), "+f"(d[1]), "+f"(d[2]), "+f"(d[3])
        : "r"(a[0]), "r"(a[1]), "r"(a[2]), "r"(a[3]), "r"(b[0]), "r"(b[1]));
}
__device__ __forceinline__ float sigmoidf_(float x) { return 1.f / (1.f + __expf(-x)); }
__device__ __forceinline__ float tanhf_(float x) {
    float e = __expf(2.f * x);
    return (e - 1.f) * __frcp_rn(e + 1.f);
}

// ---------------- prep kernels ----------------
__global__ void zero_buf(float* __restrict__ p, int n) {
    for (int i = blockIdx.x * blockDim.x + threadIdx.x; i < n; i += gridDim.x * blockDim.x)
        p[i] = 0.f;
}
// W[oc][CIN][9] -> dst[tap][oc][64ch] fp16, channels off1.., optional fold +off2
__global__ void prep_wh(const float* __restrict__ W, __half* __restrict__ dst,
                        int CIN, int off1, int off2) {
    int idx = blockIdx.x * blockDim.x + threadIdx.x;
    if (idx >= 9 * 256 * 64) return;
    int ch = idx & 63, oc = (idx >> 6) & 255, tap = idx >> 14;
    float w = W[((size_t)oc * CIN + off1 + ch) * 9 + tap];
    if (off2 >= 0) w += W[((size_t)oc * CIN + off2 + ch) * 9 + tap];
    dst[((size_t)tap * 256 + oc) * 64 + ch] = __float2half(w);
}
__global__ void prep_wxf(const float* __restrict__ W, float* __restrict__ dst) {
    int i = blockIdx.x * blockDim.x + threadIdx.x;
    if (i >= 2304) return;
    int oc = i / 9, tap = i % 9;
    dst[i] = W[(size_t)oc * 65 * 9 + tap];
}

// ---------------- ConvLSTM step: fp16 mma.sync implicit GEMM ----------------
// grid 1024 = 32 b x 32 y-pairs (2 rows); 512 threads (16 warps: 4 M x 4 N)
// h stored as single fp16. do_head: fused 3D-CNN head for step tout.
// do_ev: fused encoder-vector transpose (decoder t=0 reads encoder-final h slab).
__global__ void __launch_bounds__(512, 1)
conv_step(const __half* __restrict__ hi_in,
          __half* __restrict__ hi_out,
          float* __restrict__ c,
          const __half* __restrict__ Wm,
          const float* __restrict__ x, int t,
          const float* __restrict__ bias, int has_mma, int has_x,
          int do_head, int tout,
          const float* __restrict__ Wc, const float* __restrict__ bc,
          float* __restrict__ yout,
          int do_ev, float* __restrict__ evout) {
    extern __shared__ __align__(16) unsigned char smem[];
    const uint32_t sb = smem_u32(smem);
    const int tid = threadIdx.x, wid = tid >> 5, lane = tid & 31;
    const int b = blockIdx.x >> 5, yg = blockIdx.x & 31, y0 = yg * 2;

    // ---- prologue staging ----
    if (has_x) {
        if (tid < 264) {
            int r = tid / 66, cc = tid % 66;
            int gy = y0 + r - 1, gx = cc - 1;
            float v = 0.f;
            if ((unsigned)gy < 64u && (unsigned)gx < 64u)
                v = x[((size_t)b * TT + t) * 4096 + gy * 64 + gx];
            ((float*)(smem + O_XS))[tid] = v;
        }
#pragma unroll
        for (int j = 0; j < 5; j++) {
            int idx = tid + j * 512;
            if (idx < 2304) ((float*)(smem + O_WX))[idx] = g_Wxf[idx];
        }
    }
    if (do_head) {
        for (int i = tid; i < 576; i += 512) {
            int tap = i >> 6, ch = i & 63;
            ((float*)(smem + O_HW))[i] = Wc[ch * 9 + tap];
        }
    }

    auto stage_w = [&](int ci) {
        uint32_t dstoff = O_WB + (uint32_t)(ci % 3) * WBSZ;
        const char* src = (const char*)(Wm + (size_t)ci * 16384);
#pragma unroll
        for (int j = 0; j < 4; j++) {
            int idx = tid + j * 512;            // 0..2047
            int oc = idx >> 3, seg = idx & 7;
            cp16_s(sb + dstoff + oc * 144 + seg * 16, src + oc * 128 + seg * 16);
        }
        asm volatile("cp.async.commit_group;" ::: "memory");
    };

    if (has_mma) {
        const char* hbase = (const char*)(hi_in + ((size_t)b * PPX + (size_t)y0 * PHW) * 64);
#pragma unroll
        for (int j = 0; j < 5; j++) {
            int idx = tid + j * 512;
            if (idx < 2112) {                    // 264 px * 8 segs
                int p = idx >> 3, seg = idx & 7;
                cp16_s(sb + O_INH + p * 144 + seg * 16, hbase + p * 128 + seg * 16);
            }
        }
        // group0 = slab + chunk0; group1 = chunk1
        {
            uint32_t dstoff = O_WB;
            const char* src = (const char*)Wm;
#pragma unroll
            for (int j = 0; j < 4; j++) {
                int idx = tid + j * 512;
                int oc = idx >> 3, seg = idx & 7;
                cp16_s(sb + dstoff + oc * 144 + seg * 16, src + oc * 128 + seg * 16);
            }
            asm volatile("cp.async.commit_group;" ::: "memory");
        }
        stage_w(1);
    }

    // ---- fragment geometry ----
    const int mw = wid & 3;                  // gate block (64 oc)
    const int nw = wid >> 2;                 // px quarter (32 px)
    const uint32_t a_row = mw * 64 + (lane & 15);
    const uint32_t a_kh = ((lane >> 4) << 3);
    const int nfsel = lane >> 4;
    const int khalf = (lane >> 3) & 1;
    int prow[4], pcol[4];
#pragma unroll
    for (int nf = 0; nf < 4; nf++) {
        int p = nw * 32 + nf * 8 + (lane & 7);
        prow[nf] = p >> 6;
        pcol[nf] = p & 63;
    }

    float acc[4][4][4];
#pragma unroll
    for (int i = 0; i < 4; i++)
#pragma unroll
        for (int j = 0; j < 4; j++)
#pragma unroll
            for (int k = 0; k < 4; k++) acc[i][j][k] = 0.f;

    if (has_mma) {
        for (int ci = 0; ci < 9; ci++) {
            if (ci < 8) asm volatile("cp.async.wait_group 1;" ::: "memory");
            else        asm volatile("cp.async.wait_group 0;" ::: "memory");
            __syncthreads();

            // ---- fused CNN head (fp16 h; slab resident; runs once) ----
            if (ci == 0 && do_head && tid < 128) {
                const int pr = tid >> 6, pc = tid & 63;
                float hacc = __ldg(bc);
#pragma unroll
                for (int ky = 0; ky < 3; ky++)
#pragma unroll
                    for (int kx = 0; kx < 3; kx++) {
                        const uint32_t base = (uint32_t)(((pr + ky) * 66 + pc + kx) * 144);
                        const float* wr = (const float*)(smem + O_HW) + (ky * 3 + kx) * 64;
#pragma unroll 4
                        for (int ch = 0; ch < 64; ch += 4) {
                            uint2 h2 = *(const uint2*)(smem + O_INH + base + ch * 2);
                            float2 ha = __half22float2(*(__half2*)&h2.x);
                            float2 hb = __half22float2(*(__half2*)&h2.y);
                            hacc += wr[ch + 0] * ha.x;
                            hacc += wr[ch + 1] * ha.y;
                            hacc += wr[ch + 2] * hb.x;
                            hacc += wr[ch + 3] * hb.y;
                        }
                    }
                yout[((size_t)b * TT + tout) * 4096 + (y0 + pr) * 64 + pc] = hacc;
            }
            // ---- fused encoder-vector output (decoder t=0; slab = enc-final h) ----
            if (ci == 0 && do_ev) {
                const int xx = tid & 63;
                const int pr = (tid >> 6) & 1;
                const int chb = (tid >> 7) * 16;
                const uint32_t base = (uint32_t)(((pr + 1) * 66 + xx + 1) * 144);
#pragma unroll
                for (int j = 0; j < 16; j++) {
                    int ch = chb + j;
                    __half hv = *(const __half*)(smem + O_INH + base + ch * 2);
                    evout[((size_t)b * 64 + ch) * 4096 + (y0 + pr) * 64 + xx] =
                        __half2float(hv);
                }
            }

            if (ci + 2 < 9) stage_w(ci + 2);

            const uint32_t wb = sb + O_WB + (uint32_t)(ci % 3) * WBSZ;
            const int dy = ci / 3, dx = ci % 3;
            uint32_t bco[2];
#pragma unroll
            for (int j = 0; j < 2; j++) {
                int nf = j * 2 + nfsel;
                bco[j] = (uint32_t)(((prow[nf] + dy) * 66 + pcol[nf] + dx) * 144 + khalf * 16);
            }

#pragma unroll
            for (int ks = 0; ks < 4; ks++) {
                const int k0 = ks * 16;
                uint32_t af[4][4];
#pragma unroll
                for (int mf = 0; mf < 4; mf++)
                    ldsm4(af[mf], wb + (a_row + mf * 16) * 144 + (k0 + a_kh) * 2);
                uint32_t bf4[2][4];
                ldsm4(bf4[0], sb + O_INH + bco[0] + k0 * 2);
                ldsm4(bf4[1], sb + O_INH + bco[1] + k0 * 2);
#pragma unroll
                for (int mf = 0; mf < 4; mf++)
#pragma unroll
                    for (int nf = 0; nf < 4; nf++)
                        mma16816(acc[mf][nf], af[mf], &bf4[nf >> 1][(nf & 1) * 2]);
            }
        }
    }
    __syncthreads();

    // ---- store gate fragments to smem overlay [gate][128px][64ch] fp32 ----
    float* sg = (float*)smem;
    if (has_mma) {
        const int g = lane >> 2, tp = lane & 3;
#pragma unroll
        for (int mf = 0; mf < 4; mf++)
#pragma unroll
            for (int nf = 0; nf < 4; nf++) {
                int ch0 = mf * 16 + g;
                int px0 = nw * 32 + nf * 8 + tp * 2;
                float* p = sg + mw * 8192 + px0 * 64 + ch0;
                p[0]      = acc[mf][nf][0];
                p[64]     = acc[mf][nf][1];
                p[8]      = acc[mf][nf][2];
                p[64 + 8] = acc[mf][nf][3];
            }
    }
    __syncthreads();

    // ---- LSTM pointwise epilogue: 128 px x 64 ch over 512 threads ----
    const int ch = tid & 63;
    const int pxb = (tid >> 6) * 16;
    const float bi = __ldg(bias + ch);
    const float bf_ = __ldg(bias + 64 + ch);
    const float bo = __ldg(bias + 128 + ch);
    const float bg = __ldg(bias + 192 + ch);

    float wxr[36];
    if (has_x) {
        const float* sWx = (const float*)(smem + O_WX);
#pragma unroll
        for (int g4 = 0; g4 < 4; g4++)
#pragma unroll
            for (int tp = 0; tp < 9; tp++)
                wxr[g4 * 9 + tp] = sWx[(g4 * 64 + ch) * 9 + tp];
    }
    const float* sx = (const float*)(smem + O_XS);

    // batch-prefetch c_old (MLP 16)
    float cold[16];
    {
        const size_t cbase = (((size_t)b * 64 + y0) * 64) * 64 + ch;  // px=0
#pragma unroll
        for (int k = 0; k < 16; k++)
            cold[k] = c[cbase + (size_t)(pxb + k) * 64];
    }

#pragma unroll 4
    for (int k = 0; k < 16; k++) {
        const int px = pxb + k;
        const int pr = px >> 6, pc = px & 63;
        float vi = bi, vf = bf_, vo = bo, vg = bg;
        if (has_mma) {
            vi += sg[px * 64 + ch];
            vf += sg[8192 + px * 64 + ch];
            vo += sg[16384 + px * 64 + ch];
            vg += sg[24576 + px * 64 + ch];
        }
        if (has_x) {
            float xs[9];
#pragma unroll
            for (int tp = 0; tp < 9; tp++)
                xs[tp] = sx[(pr + tp / 3) * 66 + (tp % 3) + pc];
            float s0 = 0, s1 = 0, s2 = 0, s3 = 0;
#pragma unroll
            for (int tp = 0; tp < 9; tp++) {
                s0 += wxr[tp] * xs[tp];
                s1 += wxr[9 + tp] * xs[tp];
                s2 += wxr[18 + tp] * xs[tp];
                s3 += wxr[27 + tp] * xs[tp];
            }
            vi += s0; vf += s1; vo += s2; vg += s3;
        }
        const int y = y0 + pr;
        const size_t coff = (((size_t)b * 64 + y) * 64 + pc) * 64 + ch;
        float cn = sigmoidf_(vf) * cold[k] + sigmoidf_(vi) * tanhf_(vg);
        c[coff] = cn;
        float hv = sigmoidf_(vo) * tanhf_(cn);
        const size_t hoff = ((size_t)b * PPX + (size_t)(y + 1) * PHW + (pc + 1)) * 64 + ch;
        hi_out[hoff] = __float2half(hv);
    }
}

// ---------------- standalone 3D CNN head (final decoder step only) ----------------
__global__ void cnn_head(const __half* __restrict__ hi,
                         const float* __restrict__ Wc, const float* __restrict__ bc,
                         float* __restrict__ out, int t) {
    __shared__ float s_w[9 * 64];
    int b = blockIdx.x >> 4, yg = blockIdx.x & 15, y0 = yg * 4;
    int tid = threadIdx.x;
    for (int i = tid; i < 576; i += 256) {
        int ch = i / 9, tap = i % 9;
        s_w[tap * 64 + ch] = Wc[i];
    }
    __syncthreads();
    int r = tid >> 6, xx = tid & 63, iy = y0 + r;
    float acc = bc[0];
#pragma unroll
    for (int ky = 0; ky < 3; ky++)
#pragma unroll
        for (int kx = 0; kx < 3; kx++) {
            size_t base = (((size_t)b * PPX) + (size_t)(iy + ky) * PHW + (xx + kx)) * 64;
            const float* wrow = s_w + (ky * 3 + kx) * 64;
            float s = 0.f;
            for (int ch = 0; ch < 64; ch++)
                s += wrow[ch] * __half2float(hi[base + ch]);
            acc += s;
        }
    out[((size_t)b * TT + t) * 4096 + iy * 64 + xx] = acc;
}

// ---------------- launch ----------------
extern "C" void kernel_launch(void* const* d_in, const int* in_sizes, int n_in,
                              void* d_out, int out_size) {
    const float* x     = (const float*)d_in[0];
    const float* W_enc = (const float*)d_in[2];
    const float* b_enc = (const float*)d_in[3];
    const float* W_dec = (const float*)d_in[4];
    const float* b_dec = (const float*)d_in[5];
    const float* W_cnn = (const float*)d_in[6];
    const float* b_cnn = (const float*)d_in[7];
    float* out = (float*)d_out;

    float *c, *wxf;
    __half *ahi, *bhi, *whe, *wdx, *wds;
    cudaGetSymbolAddress((void**)&c, g_c);
    cudaGetSymbolAddress((void**)&ahi, g_nhA_hi);
    cudaGetSymbolAddress((void**)&bhi, g_nhB_hi);
    cudaGetSymbolAddress((void**)&whe, g_WhE);
    cudaGetSymbolAddress((void**)&wdx, g_WdX);
    cudaGetSymbolAddress((void**)&wds, g_WdS);
    cudaGetSymbolAddress((void**)&wxf, g_Wxf);

    cudaFuncSetAttribute(conv_step, cudaFuncAttributeMaxDynamicSharedMemorySize, SMEM_BYTES);

    zero_buf<<<2048, 256>>>(c, STATE_ELEMS);
    zero_buf<<<2048, 256>>>((float*)ahi, BB * PPX * NF / 2);
    zero_buf<<<2048, 256>>>((float*)bhi, BB * PPX * NF / 2);

    prep_wh<<<576, 256>>>(W_enc, whe, 65, 1, -1);
    prep_wh<<<576, 256>>>(W_dec, wdx, 128, 0, -1);
    prep_wh<<<576, 256>>>(W_dec, wds, 128, 0, 64);
    prep_wxf<<<9, 256>>>(W_enc, wxf);

    __half *curhi = ahi, *othhi = bhi;

    // ---- encoder ----
    for (int t = 0; t < TT; t++) {
        conv_step<<<1024, 512, SMEM_BYTES>>>(curhi, othhi, c,
                                             whe, x, t, b_enc, t > 0, 1,
                                             0, 0, W_cnn, b_cnn, out, 0, out);
        __half* tp = curhi; curhi = othhi; othhi = tp;
    }

    // decoder state restarts at zero (c only)
    zero_buf<<<2048, 256>>>(c, STATE_ELEMS);

    // ---- decoder (head for t-1 and ev output fused into prologues) ----
    for (int t = 0; t < TT; t++) {
        const __half* W = (t == 0) ? wdx : wds;
        conv_step<<<1024, 512, SMEM_BYTES>>>(curhi, othhi, c,
                                             W, x, t, b_dec, 1, 0,
                                             t > 0, t - 1, W_cnn, b_cnn, out,
                                             t == 0, out + Y_ELEMS);
        __half* tp = curhi; curhi = othhi; othhi = tp;
    }
    // final head for t = 11 from the last h
    cnn_head<<<512, 256>>>(curhi, W_cnn, b_cnn, out, TT - 1);
}

// round 15
// speedup vs baseline: 13.6064x; 1.0469x over previous
#include <cuda_runtime.h>
#include <cuda_fp16.h>
#include <math.h>
#include <stdint.h>

// ---------------- constants ----------------
#define HW 64
#define NF 64
#define BB 32
#define TT 12
#define PHW 66
#define PPX (PHW*PHW)                 // 4356
#define STATE_ELEMS (BB*NF*HW*HW)     // 8,388,608
#define Y_ELEMS (BB*TT*HW*HW)         // 1,572,864

// ---------------- smem layout (bytes) ----------------
#define O_INH 0                       // input slab: 264 px * 144B (4 rows x 66)
#define O_WB  38016                   // 3 weight bufs: 256 oc * 144B each
#define WBSZ  36864
#define O_XS  148608                  // x slab: 264 fp32
#define O_WX  149664                  // Wx: 2304 fp32
#define O_HW  158880                  // head weights: 576 fp32
#define SMEM_BYTES 161216

// ---------------- device globals ----------------
__device__ float g_c[STATE_ELEMS];
__device__ __align__(16) __half g_nhA_hi[BB*PPX*NF];
__device__ __align__(16) __half g_nhB_hi[BB*PPX*NF];
__device__ __align__(16) __half g_WhE[9*256*64];   // [tap][oc][ch] fp16
__device__ __align__(16) __half g_WdX[9*256*64];
__device__ __align__(16) __half g_WdS[9*256*64];
__device__ float g_Wxf[256*9];

// ---------------- PTX helpers ----------------
__device__ __forceinline__ uint32_t smem_u32(const void* p) {
    uint32_t a;
    asm("{ .reg .u64 t; cvta.to.shared.u64 t, %1; cvt.u32.u64 %0, t; }" : "=r"(a) : "l"(p));
    return a;
}
__device__ __forceinline__ void cp16_s(uint32_t sdst, const void* g) {
    asm volatile("cp.async.cg.shared.global [%0], [%1], 16;" :: "r"(sdst), "l"(g));
}
__device__ __forceinline__ void ldsm4(uint32_t* r, uint32_t addr) {
    asm volatile("ldmatrix.sync.aligned.m8n8.x4.shared.b16 {%0,%1,%2,%3}, [%4];"
        : "=r"(r[0]), "=r"(r[1]), "=r"(r[2]), "=r"(r[3]) : "r"(addr));
}
__device__ __forceinline__ void mma16816(float* d, const uint32_t* a, const uint32_t* b) {
    asm volatile("mma.sync.aligned.m16n8k16.row.col.f32.f16.f16.f32 "
        "{%0,%1,%2,%3}, {%4,%5,%6,%7}, {%8,%9}, {%0,%1,%2,%3};"
        : "+f"(d[0]), "+f"(d[1]), "+f"(d[2]), "+f"(d[3])
        : "r"(a[0]), "r"(a[1]), "r"(a[2]), "r"(a[3]), "r"(b[0]), "r"(b[1]));
}
__device__ __forceinline__ float sigmoidf_(float x) { return 1.f / (1.f + __expf(-x)); }
__device__ __forceinline__ float tanhf_(float x) {
    float e = __expf(2.f * x);
    return (e - 1.f) * __frcp_rn(e + 1.f);
}

// ---------------- prep kernels ----------------
__global__ void zero_buf(float* __restrict__ p, int n) {
    for (int i = blockIdx.x * blockDim.x + threadIdx.x; i < n; i += gridDim.x * blockDim.x)
        p[i] = 0.f;
}
// W[oc][CIN][9] -> dst[tap][oc][64ch] fp16, channels off1.., optional fold +off2
__global__ void prep_wh(const float* __restrict__ W, __half* __restrict__ dst,
                        int CIN, int off1, int off2) {
    int idx = blockIdx.x * blockDim.x + threadIdx.x;
    if (idx >= 9 * 256 * 64) return;
    int ch = idx & 63, oc = (idx >> 6) & 255, tap = idx >> 14;
    float w = W[((size_t)oc * CIN + off1 + ch) * 9 + tap];
    if (off2 >= 0) w += W[((size_t)oc * CIN + off2 + ch) * 9 + tap];
    dst[((size_t)tap * 256 + oc) * 64 + ch] = __float2half(w);
}
__global__ void prep_wxf(const float* __restrict__ W, float* __restrict__ dst) {
    int i = blockIdx.x * blockDim.x + threadIdx.x;
    if (i >= 2304) return;
    int oc = i / 9, tap = i % 9;
    dst[i] = W[(size_t)oc * 65 * 9 + tap];
}

// ---------------- ConvLSTM step: fp16 mma.sync implicit GEMM ----------------
// grid 1024 = 32 b x 32 y-pairs (2 rows); 512 threads (16 warps: 4 "M" x 4 N)
// A-fragment rows: gate = mf (64-row blocks), ch-block = mw (16-row blocks), so
// each thread holds i/f/o/g for the same (ch,px) -> fully in-register epilogue.
__global__ void __launch_bounds__(512, 1)
conv_step(const __half* __restrict__ hi_in,
          __half* __restrict__ hi_out,
          float* __restrict__ c,
          const __half* __restrict__ Wm,
          const float* __restrict__ x, int t,
          const float* __restrict__ bias, int has_mma, int has_x,
          int do_head, int tout,
          const float* __restrict__ Wc, const float* __restrict__ bc,
          float* __restrict__ yout,
          int do_ev, float* __restrict__ evout) {
    extern __shared__ __align__(16) unsigned char smem[];
    const uint32_t sb = smem_u32(smem);
    const int tid = threadIdx.x, wid = tid >> 5, lane = tid & 31;
    const int b = blockIdx.x >> 5, yg = blockIdx.x & 31, y0 = yg * 2;

    // ---- prologue staging ----
    if (has_x) {
        if (tid < 264) {
            int r = tid / 66, cc = tid % 66;
            int gy = y0 + r - 1, gx = cc - 1;
            float v = 0.f;
            if ((unsigned)gy < 64u && (unsigned)gx < 64u)
                v = x[((size_t)b * TT + t) * 4096 + gy * 64 + gx];
            ((float*)(smem + O_XS))[tid] = v;
        }
#pragma unroll
        for (int j = 0; j < 5; j++) {
            int idx = tid + j * 512;
            if (idx < 2304) ((float*)(smem + O_WX))[idx] = g_Wxf[idx];
        }
    }
    if (do_head) {
        for (int i = tid; i < 576; i += 512) {
            int tap = i >> 6, ch = i & 63;
            ((float*)(smem + O_HW))[i] = Wc[ch * 9 + tap];
        }
    }

    auto stage_w = [&](int ci) {
        uint32_t dstoff = O_WB + (uint32_t)(ci % 3) * WBSZ;
        const char* src = (const char*)(Wm + (size_t)ci * 16384);
#pragma unroll
        for (int j = 0; j < 4; j++) {
            int idx = tid + j * 512;            // 0..2047
            int oc = idx >> 3, seg = idx & 7;
            cp16_s(sb + dstoff + oc * 144 + seg * 16, src + oc * 128 + seg * 16);
        }
        asm volatile("cp.async.commit_group;" ::: "memory");
    };

    if (has_mma) {
        const char* hbase = (const char*)(hi_in + ((size_t)b * PPX + (size_t)y0 * PHW) * 64);
#pragma unroll
        for (int j = 0; j < 5; j++) {
            int idx = tid + j * 512;
            if (idx < 2112) {                    // 264 px * 8 segs
                int p = idx >> 3, seg = idx & 7;
                cp16_s(sb + O_INH + p * 144 + seg * 16, hbase + p * 128 + seg * 16);
            }
        }
        // group0 = slab + chunk0; group1 = chunk1
        {
            uint32_t dstoff = O_WB;
            const char* src = (const char*)Wm;
#pragma unroll
            for (int j = 0; j < 4; j++) {
                int idx = tid + j * 512;
                int oc = idx >> 3, seg = idx & 7;
                cp16_s(sb + dstoff + oc * 144 + seg * 16, src + oc * 128 + seg * 16);
            }
            asm volatile("cp.async.commit_group;" ::: "memory");
        }
        stage_w(1);
    }

    // ---- fragment geometry ----
    const int mw = wid & 3;                  // 16-ch block within each gate
    const int nw = wid >> 2;                 // px quarter (32 px)
    const uint32_t a_kh = ((lane >> 4) << 3);
    const int nfsel = lane >> 4;
    const int khalf = (lane >> 3) & 1;
    int prow[4], pcol[4];
#pragma unroll
    for (int nf = 0; nf < 4; nf++) {
        int p = nw * 32 + nf * 8 + (lane & 7);
        prow[nf] = p >> 6;
        pcol[nf] = p & 63;
    }

    float acc[4][4][4];                      // [gate][nf][dreg]
#pragma unroll
    for (int i = 0; i < 4; i++)
#pragma unroll
        for (int j = 0; j < 4; j++)
#pragma unroll
            for (int k = 0; k < 4; k++) acc[i][j][k] = 0.f;

    if (has_mma) {
        for (int ci = 0; ci < 9; ci++) {
            if (ci < 8) asm volatile("cp.async.wait_group 1;" ::: "memory");
            else        asm volatile("cp.async.wait_group 0;" ::: "memory");
            __syncthreads();

            // ---- fused CNN head (fp16 h; slab resident; runs once) ----
            if (ci == 0 && do_head && tid < 128) {
                const int pr = tid >> 6, pc = tid & 63;
                float hacc = __ldg(bc);
#pragma unroll
                for (int ky = 0; ky < 3; ky++)
#pragma unroll
                    for (int kx = 0; kx < 3; kx++) {
                        const uint32_t base = (uint32_t)(((pr + ky) * 66 + pc + kx) * 144);
                        const float* wr = (const float*)(smem + O_HW) + (ky * 3 + kx) * 64;
#pragma unroll 4
                        for (int ch = 0; ch < 64; ch += 4) {
                            uint2 h2 = *(const uint2*)(smem + O_INH + base + ch * 2);
                            float2 ha = __half22float2(*(__half2*)&h2.x);
                            float2 hb = __half22float2(*(__half2*)&h2.y);
                            hacc += wr[ch + 0] * ha.x;
                            hacc += wr[ch + 1] * ha.y;
                            hacc += wr[ch + 2] * hb.x;
                            hacc += wr[ch + 3] * hb.y;
                        }
                    }
                yout[((size_t)b * TT + tout) * 4096 + (y0 + pr) * 64 + pc] = hacc;
            }
            // ---- fused encoder-vector output (decoder t=0; slab = enc-final h) ----
            if (ci == 0 && do_ev) {
                const int xx = tid & 63;
                const int pr = (tid >> 6) & 1;
                const int chb = (tid >> 7) * 16;
                const uint32_t base = (uint32_t)(((pr + 1) * 66 + xx + 1) * 144);
#pragma unroll
                for (int j = 0; j < 16; j++) {
                    int ch = chb + j;
                    __half hv = *(const __half*)(smem + O_INH + base + ch * 2);
                    evout[((size_t)b * 64 + ch) * 4096 + (y0 + pr) * 64 + xx] =
                        __half2float(hv);
                }
            }

            if (ci + 2 < 9) stage_w(ci + 2);

            const uint32_t wb = sb + O_WB + (uint32_t)(ci % 3) * WBSZ;
            const int dy = ci / 3, dx = ci % 3;
            uint32_t bco[2];
#pragma unroll
            for (int j = 0; j < 2; j++) {
                int nf = j * 2 + nfsel;
                bco[j] = (uint32_t)(((prow[nf] + dy) * 66 + pcol[nf] + dx) * 144 + khalf * 16);
            }

#pragma unroll
            for (int ks = 0; ks < 4; ks++) {
                const int k0 = ks * 16;
                uint32_t af[4][4];
#pragma unroll
                for (int mf = 0; mf < 4; mf++) {
                    // A row = gate(mf)*64 + chblock(mw)*16 + (lane&15)
                    uint32_t arow = (uint32_t)(mf * 64 + mw * 16 + (lane & 15));
                    ldsm4(af[mf], wb + arow * 144 + (k0 + a_kh) * 2);
                }
                uint32_t bf4[2][4];
                ldsm4(bf4[0], sb + O_INH + bco[0] + k0 * 2);
                ldsm4(bf4[1], sb + O_INH + bco[1] + k0 * 2);
#pragma unroll
                for (int mf = 0; mf < 4; mf++)
#pragma unroll
                    for (int nf = 0; nf < 4; nf++)
                        mma16816(acc[mf][nf], af[mf], &bf4[nf >> 1][(nf & 1) * 2]);
            }
        }
    }
    __syncthreads();   // also orders prologue smem writes for has_mma=0 path

    // ---- in-register LSTM pointwise epilogue ----
    // thread owns ch = mw*16 + (lane>>2) + half*8, px = nw*32 + nf*8 + (lane&3)*2 + kk
    const int grp = lane >> 2, tig = lane & 3;
    const float* sx  = (const float*)(smem + O_XS);
    const float* sWx = (const float*)(smem + O_WX);

#pragma unroll
    for (int half = 0; half < 2; half++) {
        const int ch = mw * 16 + grp + half * 8;
        const float bi  = __ldg(bias + ch);
        const float bf_ = __ldg(bias + 64 + ch);
        const float bo  = __ldg(bias + 128 + ch);
        const float bg  = __ldg(bias + 192 + ch);

        float wxr[36];
        if (has_x) {
#pragma unroll
            for (int g4 = 0; g4 < 4; g4++)
#pragma unroll
                for (int tp = 0; tp < 9; tp++)
                    wxr[g4 * 9 + tp] = sWx[(g4 * 64 + ch) * 9 + tp];
        }

        // batch c_old prefetch (MLP 8)
        float cold[8];
#pragma unroll
        for (int nf = 0; nf < 4; nf++)
#pragma unroll
            for (int kk = 0; kk < 2; kk++) {
                int px = nw * 32 + nf * 8 + tig * 2 + kk;
                cold[nf * 2 + kk] =
                    c[(((size_t)b * 64 + y0 + (px >> 6)) * 64 + (px & 63)) * 64 + ch];
            }

#pragma unroll
        for (int nf = 0; nf < 4; nf++)
#pragma unroll
            for (int kk = 0; kk < 2; kk++) {
                const int k = half * 2 + kk;
                const int px = nw * 32 + nf * 8 + tig * 2 + kk;
                const int pr = px >> 6, pc = px & 63;
                float vi = acc[0][nf][k] + bi;
                float vf = acc[1][nf][k] + bf_;
                float vo = acc[2][nf][k] + bo;
                float vg = acc[3][nf][k] + bg;
                if (has_x) {
                    float s0 = 0, s1 = 0, s2 = 0, s3 = 0;
#pragma unroll
                    for (int tp = 0; tp < 9; tp++) {
                        float xv = sx[(pr + tp / 3) * 66 + (tp % 3) + pc];
                        s0 += wxr[tp] * xv;
                        s1 += wxr[9 + tp] * xv;
                        s2 += wxr[18 + tp] * xv;
                        s3 += wxr[27 + tp] * xv;
                    }
                    vi += s0; vf += s1; vo += s2; vg += s3;
                }
                const int y = y0 + pr;
                const size_t coff = (((size_t)b * 64 + y) * 64 + pc) * 64 + ch;
                float cn = sigmoidf_(vf) * cold[nf * 2 + kk] + sigmoidf_(vi) * tanhf_(vg);
                c[coff] = cn;
                float hv = sigmoidf_(vo) * tanhf_(cn);
                const size_t hoff =
                    ((size_t)b * PPX + (size_t)(y + 1) * PHW + (pc + 1)) * 64 + ch;
                hi_out[hoff] = __float2half(hv);
            }
    }
}

// ---------------- standalone 3D CNN head (final decoder step only) ----------------
__global__ void cnn_head(const __half* __restrict__ hi,
                         const float* __restrict__ Wc, const float* __restrict__ bc,
                         float* __restrict__ out, int t) {
    __shared__ float s_w[9 * 64];
    int b = blockIdx.x >> 4, yg = blockIdx.x & 15, y0 = yg * 4;
    int tid = threadIdx.x;
    for (int i = tid; i < 576; i += 256) {
        int ch = i / 9, tap = i % 9;
        s_w[tap * 64 + ch] = Wc[i];
    }
    __syncthreads();
    int r = tid >> 6, xx = tid & 63, iy = y0 + r;
    float acc = bc[0];
#pragma unroll
    for (int ky = 0; ky < 3; ky++)
#pragma unroll
        for (int kx = 0; kx < 3; kx++) {
            size_t base = (((size_t)b * PPX) + (size_t)(iy + ky) * PHW + (xx + kx)) * 64;
            const float* wrow = s_w + (ky * 3 + kx) * 64;
            float s = 0.f;
            for (int ch = 0; ch < 64; ch++)
                s += wrow[ch] * __half2float(hi[base + ch]);
            acc += s;
        }
    out[((size_t)b * TT + t) * 4096 + iy * 64 + xx] = acc;
}

// ---------------- launch ----------------
extern "C" void kernel_launch(void* const* d_in, const int* in_sizes, int n_in,
                              void* d_out, int out_size) {
    const float* x     = (const float*)d_in[0];
    const float* W_enc = (const float*)d_in[2];
    const float* b_enc = (const float*)d_in[3];
    const float* W_dec = (const float*)d_in[4];
    const float* b_dec = (const float*)d_in[5];
    const float* W_cnn = (const float*)d_in[6];
    const float* b_cnn = (const float*)d_in[7];
    float* out = (float*)d_out;

    float *c, *wxf;
    __half *ahi, *bhi, *whe, *wdx, *wds;
    cudaGetSymbolAddress((void**)&c, g_c);
    cudaGetSymbolAddress((void**)&ahi, g_nhA_hi);
    cudaGetSymbolAddress((void**)&bhi, g_nhB_hi);
    cudaGetSymbolAddress((void**)&whe, g_WhE);
    cudaGetSymbolAddress((void**)&wdx, g_WdX);
    cudaGetSymbolAddress((void**)&wds, g_WdS);
    cudaGetSymbolAddress((void**)&wxf, g_Wxf);

    cudaFuncSetAttribute(conv_step, cudaFuncAttributeMaxDynamicSharedMemorySize, SMEM_BYTES);

    zero_buf<<<2048, 256>>>(c, STATE_ELEMS);
    zero_buf<<<2048, 256>>>((float*)ahi, BB * PPX * NF / 2);
    zero_buf<<<2048, 256>>>((float*)bhi, BB * PPX * NF / 2);

    prep_wh<<<576, 256>>>(W_enc, whe, 65, 1, -1);
    prep_wh<<<576, 256>>>(W_dec, wdx, 128, 0, -1);
    prep_wh<<<576, 256>>>(W_dec, wds, 128, 0, 64);
    prep_wxf<<<9, 256>>>(W_enc, wxf);

    __half *curhi = ahi, *othhi = bhi;

    // ---- encoder ----
    for (int t = 0; t < TT; t++) {
        conv_step<<<1024, 512, SMEM_BYTES>>>(curhi, othhi, c,
                                             whe, x, t, b_enc, t > 0, 1,
                                             0, 0, W_cnn, b_cnn, out, 0, out);
        __half* tp = curhi; curhi = othhi; othhi = tp;
    }

    // decoder state restarts at zero (c only)
    zero_buf<<<2048, 256>>>(c, STATE_ELEMS);

    // ---- decoder (head for t-1 and ev output fused into prologues) ----
    for (int t = 0; t < TT; t++) {
        const __half* W = (t == 0) ? wdx : wds;
        conv_step<<<1024, 512, SMEM_BYTES>>>(curhi, othhi, c,
                                             W, x, t, b_dec, 1, 0,
                                             t > 0, t - 1, W_cnn, b_cnn, out,
                                             t == 0, out + Y_ELEMS);
        __half* tp = curhi; curhi = othhi; othhi = tp;
    }
    // final head for t = 11 from the last h
    cnn_head<<<512, 256>>>(curhi, W_cnn, b_cnn, out, TT - 1);
}

// round 16
// speedup vs baseline: 14.5384x; 1.0685x over previous
#include <cuda_runtime.h>
#include <cuda_fp16.h>
#include <math.h>
#include <stdint.h>

// ---------------- constants ----------------
#define HW 64
#define NF 64
#define BB 32
#define TT 12
#define PHW 66
#define PPX (PHW*PHW)                 // 4356
#define STATE_ELEMS (BB*NF*HW*HW)     // 8,388,608
#define Y_ELEMS (BB*TT*HW*HW)         // 1,572,864

// ---------------- smem layout (bytes) ----------------
#define O_INH 0                       // input slab: 264 px * 144B (4 rows x 66)
#define O_WB  38016                   // 4 weight bufs: 256 oc * 144B each
#define WBSZ  36864
#define O_XI  185472                  // x im2col: 128 px * 48B
#define O_WXH 191616                  // Wx fp16: 256 oc * 48B
#define O_XS  203904                  // x halo slab: 264 fp32
#define O_HW  204960                  // head weights: 576 fp32
#define SMEM_BYTES 207360

// ---------------- device globals ----------------
__device__ float g_c[STATE_ELEMS];
__device__ __align__(16) __half g_nhA_hi[BB*PPX*NF];
__device__ __align__(16) __half g_nhB_hi[BB*PPX*NF];
__device__ __align__(16) __half g_WhE[9*256*64];   // [tap][oc][ch] fp16
__device__ __align__(16) __half g_WdX[9*256*64];
__device__ __align__(16) __half g_WdS[9*256*64];
__device__ __align__(16) __half g_Wx16[256*16];    // [oc][16] (9 taps + pad)

// ---------------- PTX helpers ----------------
__device__ __forceinline__ uint32_t smem_u32(const void* p) {
    uint32_t a;
    asm("{ .reg .u64 t; cvta.to.shared.u64 t, %1; cvt.u32.u64 %0, t; }" : "=r"(a) : "l"(p));
    return a;
}
__device__ __forceinline__ void cp16_s(uint32_t sdst, const void* g) {
    asm volatile("cp.async.cg.shared.global [%0], [%1], 16;" :: "r"(sdst), "l"(g));
}
__device__ __forceinline__ void ldsm4(uint32_t* r, uint32_t addr) {
    asm volatile("ldmatrix.sync.aligned.m8n8.x4.shared.b16 {%0,%1,%2,%3}, [%4];"
        : "=r"(r[0]), "=r"(r[1]), "=r"(r[2]), "=r"(r[3]) : "r"(addr));
}
__device__ __forceinline__ void mma16816(float* d, const uint32_t* a, const uint32_t* b) {
    asm volatile("mma.sync.aligned.m16n8k16.row.col.f32.f16.f16.f32 "
        "{%0,%1,%2,%3}, {%4,%5,%6,%7}, {%8,%9}, {%0,%1,%2,%3};"
        : "+f"(d[0]), "+f"(d[1]), "+f"(d[2]), "+f"(d[3])
        : "r"(a[0]), "r"(a[1]), "r"(a[2]), "r"(a[3]), "r"(b[0]), "r"(b[1]));
}
__device__ __forceinline__ float sigmoidf_(float x) { return 1.f / (1.f + __expf(-x)); }
__device__ __forceinline__ float tanhf_(float x) {
    float e = __expf(2.f * x);
    return (e - 1.f) * __frcp_rn(e + 1.f);
}

// ---------------- prep kernels ----------------
__global__ void zero_buf(float* __restrict__ p, int n) {
    for (int i = blockIdx.x * blockDim.x + threadIdx.x; i < n; i += gridDim.x * blockDim.x)
        p[i] = 0.f;
}
// W[oc][CIN][9] -> dst[tap][oc][64ch] fp16, channels off1.., optional fold +off2
__global__ void prep_wh(const float* __restrict__ W, __half* __restrict__ dst,
                        int CIN, int off1, int off2) {
    int idx = blockIdx.x * blockDim.x + threadIdx.x;
    if (idx >= 9 * 256 * 64) return;
    int ch = idx & 63, oc = (idx >> 6) & 255, tap = idx >> 14;
    float w = W[((size_t)oc * CIN + off1 + ch) * 9 + tap];
    if (off2 >= 0) w += W[((size_t)oc * CIN + off2 + ch) * 9 + tap];
    dst[((size_t)tap * 256 + oc) * 64 + ch] = __float2half(w);
}
__global__ void prep_wx16(const float* __restrict__ W, __half* __restrict__ dst) {
    int idx = blockIdx.x * blockDim.x + threadIdx.x;
    if (idx >= 4096) return;
    int oc = idx >> 4, k = idx & 15;
    float v = (k < 9) ? W[((size_t)oc * 65) * 9 + k] : 0.f;   // cin 0 = x
    dst[idx] = __float2half(v);
}

// ---------------- ConvLSTM step: fp16 mma.sync implicit GEMM ----------------
// grid 1024 = 32 b x 32 y-pairs (2 rows); 512 threads (16 warps: 4 chblk x 4 N)
// A rows: gate = mf*64, ch-block = mw*16 -> in-register i/f/o/g epilogue.
// x path folded into one K=16 MMA pass (im2col B + fp16 Wx A).
__global__ void __launch_bounds__(512, 1)
conv_step(const __half* __restrict__ hi_in,
          __half* __restrict__ hi_out,
          float* __restrict__ c,
          const __half* __restrict__ Wm,
          const float* __restrict__ x, int t,
          const float* __restrict__ bias, int has_mma, int has_x,
          int do_head, int tout,
          const float* __restrict__ Wc, const float* __restrict__ bc,
          float* __restrict__ yout,
          int do_ev, float* __restrict__ evout) {
    extern __shared__ __align__(16) unsigned char smem[];
    const uint32_t sb = smem_u32(smem);
    const int tid = threadIdx.x, wid = tid >> 5, lane = tid & 31;
    const int b = blockIdx.x >> 5, yg = blockIdx.x & 31, y0 = yg * 2;

    auto stage_w = [&](int ci) {
        uint32_t dstoff = O_WB + (uint32_t)(ci & 3) * WBSZ;
        const char* src = (const char*)(Wm + (size_t)ci * 16384);
#pragma unroll
        for (int j = 0; j < 4; j++) {
            int idx = tid + j * 512;            // 0..2047
            int oc = idx >> 3, seg = idx & 7;
            cp16_s(sb + dstoff + oc * 144 + seg * 16, src + oc * 128 + seg * 16);
        }
        asm volatile("cp.async.commit_group;" ::: "memory");
    };

    // ---- async staging: slab + 4 weight chunks ----
    if (has_mma) {
        const char* hbase = (const char*)(hi_in + ((size_t)b * PPX + (size_t)y0 * PHW) * 64);
#pragma unroll
        for (int j = 0; j < 5; j++) {
            int idx = tid + j * 512;
            if (idx < 2112) {                    // 264 px * 8 segs
                int p = idx >> 3, seg = idx & 7;
                cp16_s(sb + O_INH + p * 144 + seg * 16, hbase + p * 128 + seg * 16);
            }
        }
        // group0 = slab + chunk0
        {
            const char* src = (const char*)Wm;
#pragma unroll
            for (int j = 0; j < 4; j++) {
                int idx = tid + j * 512;
                int oc = idx >> 3, seg = idx & 7;
                cp16_s(sb + O_WB + oc * 144 + seg * 16, src + oc * 128 + seg * 16);
            }
            asm volatile("cp.async.commit_group;" ::: "memory");
        }
        stage_w(1);
        stage_w(2);
        stage_w(3);
    }

    // ---- plain-load staging (overlaps with cp.async latency) ----
    if (has_x) {
        if (tid < 264) {
            int r = tid / 66, cc = tid % 66;
            int gy = y0 + r - 1, gx = cc - 1;
            float v = 0.f;
            if ((unsigned)gy < 64u && (unsigned)gx < 64u)
                v = x[((size_t)b * TT + t) * 4096 + gy * 64 + gx];
            ((float*)(smem + O_XS))[tid] = v;
        }
#pragma unroll
        for (int j = 0; j < 8; j++) {
            int idx = tid + j * 512;            // 0..4095
            int oc = idx >> 4, k = idx & 15;
            *(__half*)(smem + O_WXH + oc * 48 + k * 2) = g_Wx16[idx];
        }
    }
    if (do_head) {
        for (int i = tid; i < 576; i += 512) {
            int tap = i >> 6, ch = i & 63;
            ((float*)(smem + O_HW))[i] = Wc[ch * 9 + tap];
        }
    }

    // ---- fragment geometry ----
    const int mw = wid & 3;                  // 16-ch block within each gate
    const int nw = wid >> 2;                 // px quarter (32 px)
    const uint32_t a_kh = ((lane >> 4) << 3);
    const int nfsel = lane >> 4;
    const int khalf = (lane >> 3) & 1;
    int prow[4], pcol[4];
#pragma unroll
    for (int nf = 0; nf < 4; nf++) {
        int p = nw * 32 + nf * 8 + (lane & 7);
        prow[nf] = p >> 6;
        pcol[nf] = p & 63;
    }

    float acc[4][4][4];                      // [gate][nf][dreg]
#pragma unroll
    for (int i = 0; i < 4; i++)
#pragma unroll
        for (int j = 0; j < 4; j++)
#pragma unroll
            for (int k = 0; k < 4; k++) acc[i][j][k] = 0.f;

    // ---- x path: build im2col, run one K=16 MMA pass ----
    if (has_x) {
        __syncthreads();                      // sx + Wx16 visible
#pragma unroll
        for (int j = 0; j < 4; j++) {
            int idx = tid + j * 512;          // 0..2047
            int px = idx >> 4, k = idx & 15;
            float v = 0.f;
            if (k < 9) {
                int pr = px >> 6, pc = px & 63;
                v = ((const float*)(smem + O_XS))[(pr + k / 3) * 66 + (k % 3) + pc];
            }
            *(__half*)(smem + O_XI + px * 48 + k * 2) = __float2half(v);
        }
        __syncthreads();                      // im2col ready
        uint32_t afx[4][4];
#pragma unroll
        for (int mf = 0; mf < 4; mf++) {
            uint32_t arow = (uint32_t)(mf * 64 + mw * 16 + (lane & 15));
            ldsm4(afx[mf], sb + O_WXH + arow * 48 + a_kh * 2);
        }
        uint32_t bfx[2][4];
#pragma unroll
        for (int j = 0; j < 2; j++) {
            uint32_t px = (uint32_t)(nw * 32 + (j * 2 + nfsel) * 8 + (lane & 7));
            ldsm4(bfx[j], sb + O_XI + px * 48 + khalf * 16);
        }
#pragma unroll
        for (int mf = 0; mf < 4; mf++)
#pragma unroll
            for (int nf = 0; nf < 4; nf++)
                mma16816(acc[mf][nf], afx[mf], &bfx[nf >> 1][(nf & 1) * 2]);
    }

    // ---- h-chunk loop (9 taps), 4-deep weight pipeline ----
    if (has_mma) {
        for (int ci = 0; ci < 9; ci++) {
            int wg = 8 - ci; if (wg > 3) wg = 3;
            switch (wg) {
                case 3: asm volatile("cp.async.wait_group 3;" ::: "memory"); break;
                case 2: asm volatile("cp.async.wait_group 2;" ::: "memory"); break;
                case 1: asm volatile("cp.async.wait_group 1;" ::: "memory"); break;
                default: asm volatile("cp.async.wait_group 0;" ::: "memory"); break;
            }
            __syncthreads();

            // ---- fused CNN head (slab resident; runs once) ----
            if (ci == 0 && do_head && tid < 128) {
                const int pr = tid >> 6, pc = tid & 63;
                float hacc = __ldg(bc);
#pragma unroll
                for (int ky = 0; ky < 3; ky++)
#pragma unroll
                    for (int kx = 0; kx < 3; kx++) {
                        const uint32_t base = (uint32_t)(((pr + ky) * 66 + pc + kx) * 144);
                        const float* wr = (const float*)(smem + O_HW) + (ky * 3 + kx) * 64;
#pragma unroll 4
                        for (int ch = 0; ch < 64; ch += 4) {
                            uint2 h2 = *(const uint2*)(smem + O_INH + base + ch * 2);
                            float2 ha = __half22float2(*(__half2*)&h2.x);
                            float2 hb = __half22float2(*(__half2*)&h2.y);
                            hacc += wr[ch + 0] * ha.x;
                            hacc += wr[ch + 1] * ha.y;
                            hacc += wr[ch + 2] * hb.x;
                            hacc += wr[ch + 3] * hb.y;
                        }
                    }
                yout[((size_t)b * TT + tout) * 4096 + (y0 + pr) * 64 + pc] = hacc;
            }
            // ---- fused encoder-vector output (decoder t=0) ----
            if (ci == 0 && do_ev) {
                const int xx = tid & 63;
                const int pr = (tid >> 6) & 1;
                const int chb = (tid >> 7) * 16;
                const uint32_t base = (uint32_t)(((pr + 1) * 66 + xx + 1) * 144);
#pragma unroll
                for (int j = 0; j < 16; j++) {
                    int ch = chb + j;
                    __half hv = *(const __half*)(smem + O_INH + base + ch * 2);
                    evout[((size_t)b * 64 + ch) * 4096 + (y0 + pr) * 64 + xx] =
                        __half2float(hv);
                }
            }

            if (ci + 3 < 9) stage_w(ci + 3);

            const uint32_t wb = sb + O_WB + (uint32_t)(ci & 3) * WBSZ;
            const int dy = ci / 3, dx = ci % 3;
            uint32_t bco[2];
#pragma unroll
            for (int j = 0; j < 2; j++) {
                int nf = j * 2 + nfsel;
                bco[j] = (uint32_t)(((prow[nf] + dy) * 66 + pcol[nf] + dx) * 144 + khalf * 16);
            }

#pragma unroll
            for (int ks = 0; ks < 4; ks++) {
                const int k0 = ks * 16;
                uint32_t af[4][4];
#pragma unroll
                for (int mf = 0; mf < 4; mf++) {
                    uint32_t arow = (uint32_t)(mf * 64 + mw * 16 + (lane & 15));
                    ldsm4(af[mf], wb + arow * 144 + (k0 + a_kh) * 2);
                }
                uint32_t bf4[2][4];
                ldsm4(bf4[0], sb + O_INH + bco[0] + k0 * 2);
                ldsm4(bf4[1], sb + O_INH + bco[1] + k0 * 2);
#pragma unroll
                for (int mf = 0; mf < 4; mf++)
#pragma unroll
                    for (int nf = 0; nf < 4; nf++)
                        mma16816(acc[mf][nf], af[mf], &bf4[nf >> 1][(nf & 1) * 2]);
            }
        }
    }

    // ---- in-register LSTM pointwise epilogue ----
    const int grp = lane >> 2, tig = lane & 3;
#pragma unroll
    for (int half = 0; half < 2; half++) {
        const int ch = mw * 16 + grp + half * 8;
        const float bi  = __ldg(bias + ch);
        const float bf_ = __ldg(bias + 64 + ch);
        const float bo  = __ldg(bias + 128 + ch);
        const float bg  = __ldg(bias + 192 + ch);

        float cold[8];
#pragma unroll
        for (int nf = 0; nf < 4; nf++)
#pragma unroll
            for (int kk = 0; kk < 2; kk++) {
                int px = nw * 32 + nf * 8 + tig * 2 + kk;
                cold[nf * 2 + kk] =
                    c[(((size_t)b * 64 + y0 + (px >> 6)) * 64 + (px & 63)) * 64 + ch];
            }

#pragma unroll
        for (int nf = 0; nf < 4; nf++)
#pragma unroll
            for (int kk = 0; kk < 2; kk++) {
                const int k = half * 2 + kk;
                const int px = nw * 32 + nf * 8 + tig * 2 + kk;
                const int pr = px >> 6, pc = px & 63;
                float vi = acc[0][nf][k] + bi;
                float vf = acc[1][nf][k] + bf_;
                float vo = acc[2][nf][k] + bo;
                float vg = acc[3][nf][k] + bg;
                const int y = y0 + pr;
                const size_t coff = (((size_t)b * 64 + y) * 64 + pc) * 64 + ch;
                float cn = sigmoidf_(vf) * cold[nf * 2 + kk] + sigmoidf_(vi) * tanhf_(vg);
                c[coff] = cn;
                float hv = sigmoidf_(vo) * tanhf_(cn);
                const size_t hoff =
                    ((size_t)b * PPX + (size_t)(y + 1) * PHW + (pc + 1)) * 64 + ch;
                hi_out[hoff] = __float2half(hv);
            }
    }
}

// ---------------- standalone 3D CNN head (final decoder step only) ----------------
__global__ void cnn_head(const __half* __restrict__ hi,
                         const float* __restrict__ Wc, const float* __restrict__ bc,
                         float* __restrict__ out, int t) {
    __shared__ float s_w[9 * 64];
    int b = blockIdx.x >> 4, yg = blockIdx.x & 15, y0 = yg * 4;
    int tid = threadIdx.x;
    for (int i = tid; i < 576; i += 256) {
        int ch = i / 9, tap = i % 9;
        s_w[tap * 64 + ch] = Wc[i];
    }
    __syncthreads();
    int r = tid >> 6, xx = tid & 63, iy = y0 + r;
    float acc = bc[0];
#pragma unroll
    for (int ky = 0; ky < 3; ky++)
#pragma unroll
        for (int kx = 0; kx < 3; kx++) {
            size_t base = (((size_t)b * PPX) + (size_t)(iy + ky) * PHW + (xx + kx)) * 64;
            const float* wrow = s_w + (ky * 3 + kx) * 64;
            float s = 0.f;
            for (int ch = 0; ch < 64; ch++)
                s += wrow[ch] * __half2float(hi[base + ch]);
            acc += s;
        }
    out[((size_t)b * TT + t) * 4096 + iy * 64 + xx] = acc;
}

// ---------------- launch ----------------
extern "C" void kernel_launch(void* const* d_in, const int* in_sizes, int n_in,
                              void* d_out, int out_size) {
    const float* x     = (const float*)d_in[0];
    const float* W_enc = (const float*)d_in[2];
    const float* b_enc = (const float*)d_in[3];
    const float* W_dec = (const float*)d_in[4];
    const float* b_dec = (const float*)d_in[5];
    const float* W_cnn = (const float*)d_in[6];
    const float* b_cnn = (const float*)d_in[7];
    float* out = (float*)d_out;

    float* c;
    __half *ahi, *bhi, *whe, *wdx, *wds, *wx16;
    cudaGetSymbolAddress((void**)&c, g_c);
    cudaGetSymbolAddress((void**)&ahi, g_nhA_hi);
    cudaGetSymbolAddress((void**)&bhi, g_nhB_hi);
    cudaGetSymbolAddress((void**)&whe, g_WhE);
    cudaGetSymbolAddress((void**)&wdx, g_WdX);
    cudaGetSymbolAddress((void**)&wds, g_WdS);
    cudaGetSymbolAddress((void**)&wx16, g_Wx16);

    cudaFuncSetAttribute(conv_step, cudaFuncAttributeMaxDynamicSharedMemorySize, SMEM_BYTES);

    zero_buf<<<2048, 256>>>(c, STATE_ELEMS);
    zero_buf<<<2048, 256>>>((float*)ahi, BB * PPX * NF / 2);
    zero_buf<<<2048, 256>>>((float*)bhi, BB * PPX * NF / 2);

    prep_wh<<<576, 256>>>(W_enc, whe, 65, 1, -1);
    prep_wh<<<576, 256>>>(W_dec, wdx, 128, 0, -1);
    prep_wh<<<576, 256>>>(W_dec, wds, 128, 0, 64);
    prep_wx16<<<16, 256>>>(W_enc, wx16);

    __half *curhi = ahi, *othhi = bhi;

    // ---- encoder ----
    for (int t = 0; t < TT; t++) {
        conv_step<<<1024, 512, SMEM_BYTES>>>(curhi, othhi, c,
                                             whe, x, t, b_enc, t > 0, 1,
                                             0, 0, W_cnn, b_cnn, out, 0, out);
        __half* tp = curhi; curhi = othhi; othhi = tp;
    }

    // decoder state restarts at zero (c only)
    zero_buf<<<2048, 256>>>(c, STATE_ELEMS);

    // ---- decoder (head for t-1 and ev output fused into prologues) ----
    for (int t = 0; t < TT; t++) {
        const __half* W = (t == 0) ? wdx : wds;
        conv_step<<<1024, 512, SMEM_BYTES>>>(curhi, othhi, c,
                                             W, x, t, b_dec, 1, 0,
                                             t > 0, t - 1, W_cnn, b_cnn, out,
                                             t == 0, out + Y_ELEMS);
        __half* tp = curhi; curhi = othhi; othhi = tp;
    }
    // final head for t = 11 from the last h
    cnn_head<<<512, 256>>>(curhi, W_cnn, b_cnn, out, TT - 1);
}